// round 1
// baseline (speedup 1.0000x reference)
#include <cuda_runtime.h>
#include <math.h>

#define BB 2
#define SS 2048
#define DD 512
#define HH 8
#define DK 64
#define FFD 2048
#define MM (BB*SS)          // 4096 rows
#define L2E 1.4426950408889634f

// ---------------- scratch (static device arrays; no runtime alloc) -------------
__device__ float g_xm[MM*DD];
__device__ float g_q [MM*DD];
__device__ float g_k [MM*DD];
__device__ float g_v [MM*DD];
__device__ float g_wv[MM*DD];
__device__ float g_ao[MM*DD];
__device__ float g_y1[MM*DD];
__device__ float g_h1[MM*FFD];
__device__ float g_f2[MM*DD];
__device__ float g_diag[BB*HH*SS];

// ---------------- pad-mask: xm = x * (s < len[b]) ------------------------------
__global__ void mask_kernel(const float* __restrict__ x, const int* __restrict__ lengths,
                            float* __restrict__ xm)
{
    int i = blockIdx.x * blockDim.x + threadIdx.x;       // float4 index
    if (i >= (MM*DD)/4) return;
    int row = (i * 4) / DD;                              // b*S + s
    int s = row & (SS - 1);
    int b = row >> 11;
    float4 val = ((const float4*)x)[i];
    if (s >= lengths[b]) val = make_float4(0.f, 0.f, 0.f, 0.f);
    ((float4*)xm)[i] = val;
}

// ---------------- SGEMM: C[M,N] = A[M,K] @ W[K,N] + bias, optional relu --------
// BM=128, BN=64, BK=16, 256 threads, per-thread 8x4
template<bool RELU>
__global__ __launch_bounds__(256)
void sgemm_kernel(const float* __restrict__ A, const float* __restrict__ W,
                  const float* __restrict__ bias, float* __restrict__ C,
                  int M, int N, int K)
{
    __shared__ float As[16][128];
    __shared__ float Bs[16][64];
    int tid = threadIdx.x;
    int bm = blockIdx.y * 128;
    int bn = blockIdx.x * 64;
    int ty = tid >> 4;          // 0..15  -> rows ty*8..ty*8+7
    int tx = tid & 15;          // 0..15  -> cols tx*4..tx*4+3

    float acc[8][4];
#pragma unroll
    for (int i = 0; i < 8; i++)
#pragma unroll
        for (int j = 0; j < 4; j++) acc[i][j] = 0.f;

    for (int k0 = 0; k0 < K; k0 += 16) {
        // load A tile: 128x16 = 512 float4, 2 per thread, store transposed
#pragma unroll
        for (int it = 0; it < 2; it++) {
            int aidx = tid + it * 256;
            int ar = aidx >> 2;
            int ac = (aidx & 3) * 4;
            float4 av = *(const float4*)&A[(size_t)(bm + ar) * K + k0 + ac];
            As[ac + 0][ar] = av.x;
            As[ac + 1][ar] = av.y;
            As[ac + 2][ar] = av.z;
            As[ac + 3][ar] = av.w;
        }
        // load B tile: 16x64 = 256 float4, 1 per thread
        {
            int br = tid >> 4;
            int bc = (tid & 15) * 4;
            float4 bv = *(const float4*)&W[(size_t)(k0 + br) * N + bn + bc];
            *(float4*)&Bs[br][bc] = bv;
        }
        __syncthreads();
#pragma unroll
        for (int kk = 0; kk < 16; kk++) {
            float a[8];
#pragma unroll
            for (int i = 0; i < 8; i++) a[i] = As[kk][ty * 8 + i];
            float4 bb = *(float4*)&Bs[kk][tx * 4];
#pragma unroll
            for (int i = 0; i < 8; i++) {
                acc[i][0] = fmaf(a[i], bb.x, acc[i][0]);
                acc[i][1] = fmaf(a[i], bb.y, acc[i][1]);
                acc[i][2] = fmaf(a[i], bb.z, acc[i][2]);
                acc[i][3] = fmaf(a[i], bb.w, acc[i][3]);
            }
        }
        __syncthreads();
    }

    float4 b4 = *(const float4*)&bias[bn + tx * 4];
#pragma unroll
    for (int i = 0; i < 8; i++) {
        float4 o;
        o.x = acc[i][0] + b4.x;
        o.y = acc[i][1] + b4.y;
        o.z = acc[i][2] + b4.z;
        o.w = acc[i][3] + b4.w;
        if (RELU) {
            o.x = fmaxf(o.x, 0.f); o.y = fmaxf(o.y, 0.f);
            o.z = fmaxf(o.z, 0.f); o.w = fmaxf(o.w, 0.f);
        }
        *(float4*)&C[(size_t)(bm + ty * 8 + i) * N + bn + tx * 4] = o;
    }
}

// ---------------- attention diagonal (flash-style, diag only) ------------------
// grid (S/64, H, B), block 128 (4 warps x 16 queries)
__global__ __launch_bounds__(128)
void attn_diag_kernel(const float* __restrict__ Q, const float* __restrict__ K,
                      const int* __restrict__ lengths, float* __restrict__ diag)
{
    __shared__ float qs[64][64];
    __shared__ float ks[64][65];

    int bx = blockIdx.x;          // query tile
    int h  = blockIdx.y;
    int b  = blockIdx.z;
    int tid = threadIdx.x;
    int w = tid >> 5;
    int lane = tid & 31;
    int i0 = bx * 64;
    int len = lengths[b];

    // load Q tile
    for (int idx = tid; idx < 64 * 16; idx += 128) {
        int row = idx >> 4;
        int c4 = (idx & 15) * 4;
        float4 qv = *(const float4*)&Q[(size_t)((b * SS + i0 + row) * DD) + h * DK + c4];
        *(float4*)&qs[row][c4] = qv;
    }
    __syncthreads();

    float m[16], l[16], sd[16];
#pragma unroll
    for (int ii = 0; ii < 16; ii++) { m[ii] = -1e30f; l[ii] = 0.f; sd[ii] = -1e30f; }

    int qbase = w * 16;

    for (int t = 0; t <= bx; t++) {
        int j0 = t * 64;
        // load K tile, transposed into ks[d][j]
        for (int idx = tid; idx < 64 * 16; idx += 128) {
            int row = idx >> 4;
            int c4 = (idx & 15) * 4;
            float4 kv = *(const float4*)&K[(size_t)((b * SS + j0 + row) * DD) + h * DK + c4];
            ks[c4 + 0][row] = kv.x;
            ks[c4 + 1][row] = kv.y;
            ks[c4 + 2][row] = kv.z;
            ks[c4 + 3][row] = kv.w;
        }
        __syncthreads();

        float s0[16], s1[16];
#pragma unroll
        for (int ii = 0; ii < 16; ii++) { s0[ii] = 0.f; s1[ii] = 0.f; }

#pragma unroll 4
        for (int d = 0; d < 64; d++) {
            float k0v = ks[d][lane];
            float k1v = ks[d][lane + 32];
#pragma unroll
            for (int ii = 0; ii < 16; ii++) {
                float qd = qs[qbase + ii][d];
                s0[ii] = fmaf(qd, k0v, s0[ii]);
                s1[ii] = fmaf(qd, k1v, s1[ii]);
            }
        }

        int jg0 = j0 + lane;
        int jg1 = jg0 + 32;
#pragma unroll
        for (int ii = 0; ii < 16; ii++) {
            int ig = i0 + qbase + ii;
            if (jg0 <= ig) {
                float s = s0[ii];
                if (jg0 == ig) sd[ii] = s;
                float nm = fmaxf(m[ii], s);
                l[ii] = l[ii] * exp2f((m[ii] - nm) * L2E) + exp2f((s - nm) * L2E);
                m[ii] = nm;
            }
            if (jg1 <= ig) {
                float s = s1[ii];
                if (jg1 == ig) sd[ii] = s;
                float nm = fmaxf(m[ii], s);
                l[ii] = l[ii] * exp2f((m[ii] - nm) * L2E) + exp2f((s - nm) * L2E);
                m[ii] = nm;
            }
        }
        __syncthreads();
    }

    // cross-lane reduce + write
#pragma unroll
    for (int ii = 0; ii < 16; ii++) {
        float mt = m[ii];
#pragma unroll
        for (int o = 16; o > 0; o >>= 1) mt = fmaxf(mt, __shfl_xor_sync(0xffffffffu, mt, o));
        float lp = l[ii] * exp2f((m[ii] - mt) * L2E);
#pragma unroll
        for (int o = 16; o > 0; o >>= 1) lp += __shfl_xor_sync(0xffffffffu, lp, o);
        float sdt = sd[ii];
#pragma unroll
        for (int o = 16; o > 0; o >>= 1) sdt = fmaxf(sdt, __shfl_xor_sync(0xffffffffu, sdt, o));
        if (lane == 0) {
            int ig = i0 + qbase + ii;
            float dv = (ig < len) ? exp2f((sdt - mt) * L2E) / lp : 0.f;
            diag[(size_t)(b * HH + h) * SS + ig] = dv;
        }
    }
}

// ---------------- wv = diag * v ------------------------------------------------
__global__ void wv_kernel(const float* __restrict__ V, const float* __restrict__ diag,
                          float* __restrict__ wv)
{
    int i = blockIdx.x * blockDim.x + threadIdx.x;       // float4 index
    if (i >= (MM*DD)/4) return;
    int e = i * 4;
    int row = e / DD;                                     // b*S + s
    int c = e & (DD - 1);
    int b = row >> 11;
    int s = row & (SS - 1);
    int h = c >> 6;
    float dv = diag[(size_t)(b * HH + h) * SS + s];
    float4 v4 = ((const float4*)V)[i];
    v4.x *= dv; v4.y *= dv; v4.z *= dv; v4.w *= dv;
    ((float4*)wv)[i] = v4;
}

// ---------------- LayerNorm(a + r) ---------------------------------------------
// one block per row of 512, 256 threads, 2 elems/thread
__global__ __launch_bounds__(256)
void ln_kernel(const float* __restrict__ a, const float* __restrict__ r,
               const float* __restrict__ gamma, const float* __restrict__ beta,
               float* __restrict__ out)
{
    int row = blockIdx.x;
    int tid = threadIdx.x;
    const float* pa = a + (size_t)row * DD;
    const float* pr = r + (size_t)row * DD;

    float v0 = pa[tid] + pr[tid];
    float v1 = pa[tid + 256] + pr[tid + 256];

    __shared__ float sred[8];
    __shared__ float smean, srstd;

    float s = v0 + v1;
#pragma unroll
    for (int o = 16; o > 0; o >>= 1) s += __shfl_xor_sync(0xffffffffu, s, o);
    if ((tid & 31) == 0) sred[tid >> 5] = s;
    __syncthreads();
    if (tid == 0) {
        float t = 0.f;
#pragma unroll
        for (int i = 0; i < 8; i++) t += sred[i];
        smean = t * (1.0f / DD);
    }
    __syncthreads();
    float mean = smean;
    float d0 = v0 - mean, d1 = v1 - mean;
    float vs = d0 * d0 + d1 * d1;
#pragma unroll
    for (int o = 16; o > 0; o >>= 1) vs += __shfl_xor_sync(0xffffffffu, vs, o);
    if ((tid & 31) == 0) sred[tid >> 5] = vs;
    __syncthreads();
    if (tid == 0) {
        float t = 0.f;
#pragma unroll
        for (int i = 0; i < 8; i++) t += sred[i];
        srstd = rsqrtf(t * (1.0f / DD) + 1e-3f);
    }
    __syncthreads();
    float rstd = srstd;
    out[(size_t)row * DD + tid]       = gamma[tid]       * (d0 * rstd) + beta[tid];
    out[(size_t)row * DD + tid + 256] = gamma[tid + 256] * (d1 * rstd) + beta[tid + 256];
}

// ---------------- launch --------------------------------------------------------
extern "C" void kernel_launch(void* const* d_in, const int* in_sizes, int n_in,
                              void* d_out, int out_size)
{
    const float* x       = (const float*)d_in[0];
    const int*   lengths = (const int*)d_in[1];
    const float* Wq = (const float*)d_in[2];
    const float* bq = (const float*)d_in[3];
    const float* Wk = (const float*)d_in[4];
    const float* bk = (const float*)d_in[5];
    const float* Wv = (const float*)d_in[6];
    const float* bv = (const float*)d_in[7];
    const float* Wo = (const float*)d_in[8];
    const float* bo = (const float*)d_in[9];
    const float* W1 = (const float*)d_in[10];
    const float* b1 = (const float*)d_in[11];
    const float* W2 = (const float*)d_in[12];
    const float* b2 = (const float*)d_in[13];
    const float* gamma1 = (const float*)d_in[14];
    const float* beta1  = (const float*)d_in[15];
    const float* gamma2 = (const float*)d_in[16];
    const float* beta2  = (const float*)d_in[17];

    float *xm, *q, *k, *v, *wv, *ao, *y1, *h1, *f2, *diag;
    cudaGetSymbolAddress((void**)&xm,   g_xm);
    cudaGetSymbolAddress((void**)&q,    g_q);
    cudaGetSymbolAddress((void**)&k,    g_k);
    cudaGetSymbolAddress((void**)&v,    g_v);
    cudaGetSymbolAddress((void**)&wv,   g_wv);
    cudaGetSymbolAddress((void**)&ao,   g_ao);
    cudaGetSymbolAddress((void**)&y1,   g_y1);
    cudaGetSymbolAddress((void**)&h1,   g_h1);
    cudaGetSymbolAddress((void**)&f2,   g_f2);
    cudaGetSymbolAddress((void**)&diag, g_diag);

    int n4 = (MM * DD) / 4;
    mask_kernel<<<(n4 + 255) / 256, 256>>>(x, lengths, xm);

    dim3 g512(DD / 64, MM / 128);        // (8, 32)
    dim3 gFF (FFD / 64, MM / 128);       // (32, 32)

    sgemm_kernel<false><<<g512, 256>>>(xm, Wq, bq, q, MM, DD, DD);
    sgemm_kernel<false><<<g512, 256>>>(xm, Wk, bk, k, MM, DD, DD);
    sgemm_kernel<false><<<g512, 256>>>(xm, Wv, bv, v, MM, DD, DD);

    attn_diag_kernel<<<dim3(SS / 64, HH, BB), 128>>>(q, k, lengths, diag);

    wv_kernel<<<(n4 + 255) / 256, 256>>>(v, diag, wv);

    sgemm_kernel<false><<<g512, 256>>>(wv, Wo, bo, ao, MM, DD, DD);

    ln_kernel<<<MM, 256>>>(xm, ao, gamma1, beta1, y1);

    sgemm_kernel<true ><<<gFF, 256>>>(y1, W1, b1, h1, MM, FFD, DD);
    sgemm_kernel<false><<<g512, 256>>>(h1, W2, b2, f2, MM, DD, FFD);

    ln_kernel<<<MM, 256>>>(y1, f2, gamma2, beta2, (float*)d_out);
}

// round 8
// speedup vs baseline: 1.7922x; 1.7922x over previous
#include <cuda_runtime.h>
#include <cuda_bf16.h>
#include <math.h>
#include <stdint.h>

#define BB 2
#define SS 2048
#define DD 512
#define HH 8
#define DK 64
#define FFD 2048
#define MM (BB*SS)          // 4096 rows
#define L2E 1.4426950408889634f

// ---------------- scratch (static device arrays; no runtime alloc) -------------
__device__ float g_xm[MM*DD];
__device__ float g_q [MM*DD];
__device__ float g_k [MM*DD];
__device__ float g_v [MM*DD];
__device__ float g_ao[MM*DD];
__device__ float g_y1[MM*DD];
__device__ float g_f2[MM*DD];
__device__ float g_diag[BB*HH*SS];
// bf16 hi/lo planes
__device__ __nv_bfloat16 g_xh [MM*DD],  g_xl [MM*DD];
__device__ __nv_bfloat16 g_wvh[MM*DD],  g_wvl[MM*DD];
__device__ __nv_bfloat16 g_y1h[MM*DD],  g_y1l[MM*DD];
__device__ __nv_bfloat16 g_h1h[MM*FFD], g_h1l[MM*FFD];
// transposed weights [N, K] bf16 hi/lo
__device__ __nv_bfloat16 g_wqth[DD*DD], g_wqtl[DD*DD];
__device__ __nv_bfloat16 g_wkth[DD*DD], g_wktl[DD*DD];
__device__ __nv_bfloat16 g_wvth[DD*DD], g_wvtl[DD*DD];
__device__ __nv_bfloat16 g_woth[DD*DD], g_wotl[DD*DD];
__device__ __nv_bfloat16 g_w1th[FFD*DD], g_w1tl[FFD*DD];
__device__ __nv_bfloat16 g_w2th[DD*FFD], g_w2tl[DD*FFD];

// ---------------- PTX helpers ---------------------------------------------------
__device__ __forceinline__ uint32_t smem_u32(const void* p) {
    uint32_t a;
    asm("{ .reg .u64 t; cvta.to.shared.u64 t, %1; cvt.u32.u64 %0, t; }" : "=r"(a) : "l"(p));
    return a;
}
__device__ __forceinline__ void mma_bf16(float* c, const uint32_t* a, const uint32_t* b) {
    asm volatile(
        "mma.sync.aligned.m16n8k16.row.col.f32.bf16.bf16.f32 "
        "{%0,%1,%2,%3},{%4,%5,%6,%7},{%8,%9},{%0,%1,%2,%3};"
        : "+f"(c[0]), "+f"(c[1]), "+f"(c[2]), "+f"(c[3])
        : "r"(a[0]), "r"(a[1]), "r"(a[2]), "r"(a[3]), "r"(b[0]), "r"(b[1]));
}
__device__ __forceinline__ void ldsm4(uint32_t* r, uint32_t addr) {
    asm volatile("ldmatrix.sync.aligned.m8n8.x4.shared.b16 {%0,%1,%2,%3},[%4];"
                 : "=r"(r[0]), "=r"(r[1]), "=r"(r[2]), "=r"(r[3]) : "r"(addr));
}
__device__ __forceinline__ void cpa16(uint32_t dst, const void* src) {
    asm volatile("cp.async.cg.shared.global [%0],[%1],16;" :: "r"(dst), "l"(src));
}
__device__ __forceinline__ void split1(float a, __nv_bfloat16& h, __nv_bfloat16& l) {
    h = __float2bfloat16(a);
    l = __float2bfloat16(a - __bfloat162float(h));
}

// ---------------- weight transpose+split: oh/ol[C][R] = split(in[R][C]) --------
__global__ __launch_bounds__(256)
void transpose_split_kernel(const float* __restrict__ in,
                            __nv_bfloat16* __restrict__ oh, __nv_bfloat16* __restrict__ ol,
                            int R, int C)
{
    __shared__ float t[32][33];
    int bx = blockIdx.x * 32, by = blockIdx.y * 32;
    int tx = threadIdx.x, ty = threadIdx.y;   // (32, 8)
#pragma unroll
    for (int i = 0; i < 32; i += 8)
        t[ty + i][tx] = in[(size_t)(by + ty + i) * C + bx + tx];
    __syncthreads();
#pragma unroll
    for (int i = 0; i < 32; i += 8) {
        float v = t[tx][ty + i];
        __nv_bfloat16 h, l;
        split1(v, h, l);
        size_t o = (size_t)(bx + ty + i) * R + by + tx;
        oh[o] = h; ol[o] = l;
    }
}

// ---------------- HMMA bf16 3-pass GEMM ------------------------------------------
// C[M,N] = (Ah+Al)[M,K] @ (Bh+Bl)[N,K]^T + bias   (drops Al*Bl term)
// tile 128x128, BK=32 (hi+lo packed per 128B row), 3-stage cp.async, 8 warps 64x32
#define STAGE_BYTES 32768
#define SMEM_HGEMM (3 * STAGE_BYTES)

template<int MODE>  // 0: fp32 out   1: relu + bf16 hi/lo split out
__global__ __launch_bounds__(256, 1)
void hgemm(const __nv_bfloat16* __restrict__ Ah, const __nv_bfloat16* __restrict__ Al,
           const __nv_bfloat16* __restrict__ Bh, const __nv_bfloat16* __restrict__ Bl,
           const float* __restrict__ bias,
           float* __restrict__ C, __nv_bfloat16* __restrict__ Ch, __nv_bfloat16* __restrict__ Cl,
           int M, int N, int K)
{
    extern __shared__ char smem[];
    uint32_t sb = smem_u32(smem);
    int tid = threadIdx.x, lane = tid & 31, wid = tid >> 5;
    int bm = blockIdx.y * 128, bn = blockIdx.x * 128;
    int wm = wid & 1, wn = wid >> 1;
    int NK = K >> 5;

    auto issue = [&](int kt) {
        uint32_t base = sb + (kt % 3) * STAGE_BYTES;
        int k0 = kt << 5;
#pragma unroll
        for (int i = 0; i < 4; i++) {
            int ch = i * 256 + tid;
            int row = ch >> 3, col = ch & 7;
            const __nv_bfloat16* src =
                (col < 4 ? Ah : Al) + (size_t)(bm + row) * K + k0 + (col & 3) * 8;
            cpa16(base + row * 128 + ((col ^ (row & 7)) << 4), src);
        }
#pragma unroll
        for (int i = 0; i < 4; i++) {
            int ch = i * 256 + tid;
            int row = ch >> 3, col = ch & 7;
            const __nv_bfloat16* src =
                (col < 4 ? Bh : Bl) + (size_t)(bn + row) * K + k0 + (col & 3) * 8;
            cpa16(base + 16384 + row * 128 + ((col ^ (row & 7)) << 4), src);
        }
        asm volatile("cp.async.commit_group;");
    };

    issue(0); issue(1); issue(2);

    float acc[4][4][4];
#pragma unroll
    for (int i = 0; i < 4; i++)
#pragma unroll
        for (int j = 0; j < 4; j++)
#pragma unroll
            for (int r = 0; r < 4; r++) acc[i][j][r] = 0.f;

    int arow = (lane & 7) + ((lane >> 3) & 1) * 8;
    int asel = lane >> 4;
    int brow = (lane & 7) + (lane >> 4) * 8;
    int bsel = (lane >> 3) & 1;
    int rx = lane & 7;

    for (int kt = 0; kt < NK; kt++) {
        asm volatile("cp.async.wait_group %0;" :: "n"(2));
        __syncthreads();
        uint32_t base = sb + (kt % 3) * STAGE_BYTES;
#pragma unroll
        for (int s = 0; s < 2; s++) {
            uint32_t Ahf[16], Alf[16], Bhf[8], Blf[8];
#pragma unroll
            for (int mt = 0; mt < 4; mt++) {
                uint32_t ro = base + (wm * 64 + mt * 16 + arow) * 128;
                ldsm4(&Ahf[mt * 4], ro + (((2 * s + asel) ^ rx) << 4));
                ldsm4(&Alf[mt * 4], ro + (((4 + 2 * s + asel) ^ rx) << 4));
            }
#pragma unroll
            for (int nt2 = 0; nt2 < 2; nt2++) {
                uint32_t ro = base + 16384 + (wn * 32 + nt2 * 16 + brow) * 128;
                ldsm4(&Bhf[nt2 * 4], ro + (((2 * s + bsel) ^ rx) << 4));
                ldsm4(&Blf[nt2 * 4], ro + (((4 + 2 * s + bsel) ^ rx) << 4));
            }
#pragma unroll
            for (int mt = 0; mt < 4; mt++)
#pragma unroll
                for (int nt = 0; nt < 4; nt++)
                    mma_bf16(acc[mt][nt], &Ahf[mt * 4], &Bhf[nt * 2]);
#pragma unroll
            for (int mt = 0; mt < 4; mt++)
#pragma unroll
                for (int nt = 0; nt < 4; nt++)
                    mma_bf16(acc[mt][nt], &Ahf[mt * 4], &Blf[nt * 2]);
#pragma unroll
            for (int mt = 0; mt < 4; mt++)
#pragma unroll
                for (int nt = 0; nt < 4; nt++)
                    mma_bf16(acc[mt][nt], &Alf[mt * 4], &Bhf[nt * 2]);
        }
        __syncthreads();
        if (kt + 3 < NK) issue(kt + 3);
    }

    // epilogue: bias (+relu/split) straight to global
    int g = lane >> 2, tig = lane & 3;
#pragma unroll
    for (int mt = 0; mt < 4; mt++) {
#pragma unroll
        for (int nt = 0; nt < 4; nt++) {
            int col = bn + wn * 32 + nt * 8 + tig * 2;
            float2 bv = *(const float2*)&bias[col];
            int r0 = bm + wm * 64 + mt * 16 + g;
            float x0 = acc[mt][nt][0] + bv.x, x1 = acc[mt][nt][1] + bv.y;
            float x2 = acc[mt][nt][2] + bv.x, x3 = acc[mt][nt][3] + bv.y;
            if (MODE == 0) {
                float2 o0 = {x0, x1}, o1 = {x2, x3};
                *(float2*)&C[(size_t)r0 * N + col] = o0;
                *(float2*)&C[(size_t)(r0 + 8) * N + col] = o1;
            } else {
                x0 = fmaxf(x0, 0.f); x1 = fmaxf(x1, 0.f);
                x2 = fmaxf(x2, 0.f); x3 = fmaxf(x3, 0.f);
                __nv_bfloat16 h0, l0, h1, l1, h2, l2, h3, l3;
                split1(x0, h0, l0); split1(x1, h1, l1);
                split1(x2, h2, l2); split1(x3, h3, l3);
                __nv_bfloat162 hh0 = {h0, h1}, ll0 = {l0, l1};
                __nv_bfloat162 hh1 = {h2, h3}, ll1 = {l2, l3};
                *(__nv_bfloat162*)&Ch[(size_t)r0 * N + col] = hh0;
                *(__nv_bfloat162*)&Cl[(size_t)r0 * N + col] = ll0;
                *(__nv_bfloat162*)&Ch[(size_t)(r0 + 8) * N + col] = hh1;
                *(__nv_bfloat162*)&Cl[(size_t)(r0 + 8) * N + col] = ll1;
            }
        }
    }
}

// ---------------- pad-mask + split ----------------------------------------------
__global__ void mask_split_kernel(const float* __restrict__ x, const int* __restrict__ lengths,
                                  float* __restrict__ xm,
                                  __nv_bfloat16* __restrict__ xh, __nv_bfloat16* __restrict__ xl)
{
    int i = blockIdx.x * blockDim.x + threadIdx.x;       // float4 index
    if (i >= (MM*DD)/4) return;
    int row = (i * 4) / DD;
    int s = row & (SS - 1);
    int b = row >> 11;
    float4 val = ((const float4*)x)[i];
    if (s >= lengths[b]) val = make_float4(0.f, 0.f, 0.f, 0.f);
    ((float4*)xm)[i] = val;
    __nv_bfloat16 h0, l0, h1, l1, h2, l2, h3, l3;
    split1(val.x, h0, l0); split1(val.y, h1, l1);
    split1(val.z, h2, l2); split1(val.w, h3, l3);
    __nv_bfloat162* ph = (__nv_bfloat162*)&xh[i * 4];
    __nv_bfloat162* pl = (__nv_bfloat162*)&xl[i * 4];
    ph[0] = {h0, h1}; ph[1] = {h2, h3};
    pl[0] = {l0, l1}; pl[1] = {l2, l3};
}

// ---------------- attention diagonal (flash-style, diag only) ------------------
__global__ __launch_bounds__(128)
void attn_diag_kernel(const float* __restrict__ Q, const float* __restrict__ K,
                      const int* __restrict__ lengths, float* __restrict__ diag)
{
    __shared__ float qs[64][64];
    __shared__ float ks[64][65];

    int bx = blockIdx.x;
    int h  = blockIdx.y;
    int b  = blockIdx.z;
    int tid = threadIdx.x;
    int w = tid >> 5;
    int lane = tid & 31;
    int i0 = bx * 64;
    int len = lengths[b];

    for (int idx = tid; idx < 64 * 16; idx += 128) {
        int row = idx >> 4;
        int c4 = (idx & 15) * 4;
        float4 qv = *(const float4*)&Q[(size_t)((b * SS + i0 + row) * DD) + h * DK + c4];
        *(float4*)&qs[row][c4] = qv;
    }
    __syncthreads();

    float m[16], l[16], sd[16];
#pragma unroll
    for (int ii = 0; ii < 16; ii++) { m[ii] = -1e30f; l[ii] = 0.f; sd[ii] = -1e30f; }

    int qbase = w * 16;

    for (int t = 0; t <= bx; t++) {
        int j0 = t * 64;
        for (int idx = tid; idx < 64 * 16; idx += 128) {
            int row = idx >> 4;
            int c4 = (idx & 15) * 4;
            float4 kv = *(const float4*)&K[(size_t)((b * SS + j0 + row) * DD) + h * DK + c4];
            ks[c4 + 0][row] = kv.x;
            ks[c4 + 1][row] = kv.y;
            ks[c4 + 2][row] = kv.z;
            ks[c4 + 3][row] = kv.w;
        }
        __syncthreads();

        float s0[16], s1[16];
#pragma unroll
        for (int ii = 0; ii < 16; ii++) { s0[ii] = 0.f; s1[ii] = 0.f; }

#pragma unroll 4
        for (int d = 0; d < 64; d++) {
            float k0v = ks[d][lane];
            float k1v = ks[d][lane + 32];
#pragma unroll
            for (int ii = 0; ii < 16; ii++) {
                float qd = qs[qbase + ii][d];
                s0[ii] = fmaf(qd, k0v, s0[ii]);
                s1[ii] = fmaf(qd, k1v, s1[ii]);
            }
        }

        int jg0 = j0 + lane;
        int jg1 = jg0 + 32;
#pragma unroll
        for (int ii = 0; ii < 16; ii++) {
            int ig = i0 + qbase + ii;
            if (jg0 <= ig) {
                float s = s0[ii];
                if (jg0 == ig) sd[ii] = s;
                float nm = fmaxf(m[ii], s);
                l[ii] = l[ii] * exp2f((m[ii] - nm) * L2E) + exp2f((s - nm) * L2E);
                m[ii] = nm;
            }
            if (jg1 <= ig) {
                float s = s1[ii];
                if (jg1 == ig) sd[ii] = s;
                float nm = fmaxf(m[ii], s);
                l[ii] = l[ii] * exp2f((m[ii] - nm) * L2E) + exp2f((s - nm) * L2E);
                m[ii] = nm;
            }
        }
        __syncthreads();
    }

#pragma unroll
    for (int ii = 0; ii < 16; ii++) {
        float mt = m[ii];
#pragma unroll
        for (int o = 16; o > 0; o >>= 1) mt = fmaxf(mt, __shfl_xor_sync(0xffffffffu, mt, o));
        float lp = l[ii] * exp2f((m[ii] - mt) * L2E);
#pragma unroll
        for (int o = 16; o > 0; o >>= 1) lp += __shfl_xor_sync(0xffffffffu, lp, o);
        float sdt = sd[ii];
#pragma unroll
        for (int o = 16; o > 0; o >>= 1) sdt = fmaxf(sdt, __shfl_xor_sync(0xffffffffu, sdt, o));
        if (lane == 0) {
            int ig = i0 + qbase + ii;
            float dv = (ig < len) ? exp2f((sdt - mt) * L2E) / lp : 0.f;
            diag[(size_t)(b * HH + h) * SS + ig] = dv;
        }
    }
}

// ---------------- wv = diag * v  (-> bf16 hi/lo planes) -------------------------
__global__ void wv_split_kernel(const float* __restrict__ V, const float* __restrict__ diag,
                                __nv_bfloat16* __restrict__ wh, __nv_bfloat16* __restrict__ wl)
{
    int i = blockIdx.x * blockDim.x + threadIdx.x;
    if (i >= (MM*DD)/4) return;
    int e = i * 4;
    int row = e / DD;
    int c = e & (DD - 1);
    int b = row >> 11;
    int s = row & (SS - 1);
    int h = c >> 6;
    float dv = diag[(size_t)(b * HH + h) * SS + s];
    float4 v4 = ((const float4*)V)[i];
    v4.x *= dv; v4.y *= dv; v4.z *= dv; v4.w *= dv;
    __nv_bfloat16 h0, l0, h1, l1, h2, l2, h3, l3;
    split1(v4.x, h0, l0); split1(v4.y, h1, l1);
    split1(v4.z, h2, l2); split1(v4.w, h3, l3);
    __nv_bfloat162* ph = (__nv_bfloat162*)&wh[e];
    __nv_bfloat162* pl = (__nv_bfloat162*)&wl[e];
    ph[0] = {h0, h1}; ph[1] = {h2, h3};
    pl[0] = {l0, l1}; pl[1] = {l2, l3};
}

// ---------------- LayerNorm(a + r)  (optionally also bf16 split out) ------------
template<bool SPLIT>
__global__ __launch_bounds__(256)
void ln_kernel(const float* __restrict__ a, const float* __restrict__ r,
               const float* __restrict__ gamma, const float* __restrict__ beta,
               float* __restrict__ out,
               __nv_bfloat16* __restrict__ oh, __nv_bfloat16* __restrict__ ol)
{
    int row = blockIdx.x;
    int tid = threadIdx.x;
    const float* pa = a + (size_t)row * DD;
    const float* pr = r + (size_t)row * DD;

    float v0 = pa[tid] + pr[tid];
    float v1 = pa[tid + 256] + pr[tid + 256];

    __shared__ float sred[8];
    __shared__ float smean, srstd;

    float s = v0 + v1;
#pragma unroll
    for (int o = 16; o > 0; o >>= 1) s += __shfl_xor_sync(0xffffffffu, s, o);
    if ((tid & 31) == 0) sred[tid >> 5] = s;
    __syncthreads();
    if (tid == 0) {
        float t = 0.f;
#pragma unroll
        for (int i = 0; i < 8; i++) t += sred[i];
        smean = t * (1.0f / DD);
    }
    __syncthreads();
    float mean = smean;
    float d0 = v0 - mean, d1 = v1 - mean;
    float vs = d0 * d0 + d1 * d1;
#pragma unroll
    for (int o = 16; o > 0; o >>= 1) vs += __shfl_xor_sync(0xffffffffu, vs, o);
    if ((tid & 31) == 0) sred[tid >> 5] = vs;
    __syncthreads();
    if (tid == 0) {
        float t = 0.f;
#pragma unroll
        for (int i = 0; i < 8; i++) t += sred[i];
        srstd = rsqrtf(t * (1.0f / DD) + 1e-3f);
    }
    __syncthreads();
    float rstd = srstd;
    float o0 = gamma[tid]       * (d0 * rstd) + beta[tid];
    float o1 = gamma[tid + 256] * (d1 * rstd) + beta[tid + 256];
    out[(size_t)row * DD + tid]       = o0;
    out[(size_t)row * DD + tid + 256] = o1;
    if (SPLIT) {
        __nv_bfloat16 h0, l0, h1, l1;
        split1(o0, h0, l0);
        split1(o1, h1, l1);
        oh[(size_t)row * DD + tid]       = h0;
        ol[(size_t)row * DD + tid]       = l0;
        oh[(size_t)row * DD + tid + 256] = h1;
        ol[(size_t)row * DD + tid + 256] = l1;
    }
}

// ---------------- launch --------------------------------------------------------
extern "C" void kernel_launch(void* const* d_in, const int* in_sizes, int n_in,
                              void* d_out, int out_size)
{
    const float* x       = (const float*)d_in[0];
    const int*   lengths = (const int*)d_in[1];
    const float* Wq = (const float*)d_in[2];
    const float* bq = (const float*)d_in[3];
    const float* Wk = (const float*)d_in[4];
    const float* bk = (const float*)d_in[5];
    const float* Wv = (const float*)d_in[6];
    const float* bv = (const float*)d_in[7];
    const float* Wo = (const float*)d_in[8];
    const float* bo = (const float*)d_in[9];
    const float* W1 = (const float*)d_in[10];
    const float* b1 = (const float*)d_in[11];
    const float* W2 = (const float*)d_in[12];
    const float* b2 = (const float*)d_in[13];
    const float* gamma1 = (const float*)d_in[14];
    const float* beta1  = (const float*)d_in[15];
    const float* gamma2 = (const float*)d_in[16];
    const float* beta2  = (const float*)d_in[17];

    float *xm, *q, *k, *v, *ao, *y1, *f2, *diag;
    __nv_bfloat16 *xh, *xl, *wvh, *wvl, *y1h, *y1l, *h1h, *h1l;
    __nv_bfloat16 *wqth, *wqtl, *wkth, *wktl, *wvth, *wvtl, *woth, *wotl;
    __nv_bfloat16 *w1th, *w1tl, *w2th, *w2tl;
    cudaGetSymbolAddress((void**)&xm,   g_xm);
    cudaGetSymbolAddress((void**)&q,    g_q);
    cudaGetSymbolAddress((void**)&k,    g_k);
    cudaGetSymbolAddress((void**)&v,    g_v);
    cudaGetSymbolAddress((void**)&ao,   g_ao);
    cudaGetSymbolAddress((void**)&y1,   g_y1);
    cudaGetSymbolAddress((void**)&f2,   g_f2);
    cudaGetSymbolAddress((void**)&diag, g_diag);
    cudaGetSymbolAddress((void**)&xh,   g_xh);
    cudaGetSymbolAddress((void**)&xl,   g_xl);
    cudaGetSymbolAddress((void**)&wvh,  g_wvh);
    cudaGetSymbolAddress((void**)&wvl,  g_wvl);
    cudaGetSymbolAddress((void**)&y1h,  g_y1h);
    cudaGetSymbolAddress((void**)&y1l,  g_y1l);
    cudaGetSymbolAddress((void**)&h1h,  g_h1h);
    cudaGetSymbolAddress((void**)&h1l,  g_h1l);
    cudaGetSymbolAddress((void**)&wqth, g_wqth);
    cudaGetSymbolAddress((void**)&wqtl, g_wqtl);
    cudaGetSymbolAddress((void**)&wkth, g_wkth);
    cudaGetSymbolAddress((void**)&wktl, g_wktl);
    cudaGetSymbolAddress((void**)&wvth, g_wvth);
    cudaGetSymbolAddress((void**)&wvtl, g_wvtl);
    cudaGetSymbolAddress((void**)&woth, g_woth);
    cudaGetSymbolAddress((void**)&wotl, g_wotl);
    cudaGetSymbolAddress((void**)&w1th, g_w1th);
    cudaGetSymbolAddress((void**)&w1tl, g_w1tl);
    cudaGetSymbolAddress((void**)&w2th, g_w2th);
    cudaGetSymbolAddress((void**)&w2tl, g_w2tl);

    cudaFuncSetAttribute(hgemm<0>, cudaFuncAttributeMaxDynamicSharedMemorySize, SMEM_HGEMM);
    cudaFuncSetAttribute(hgemm<1>, cudaFuncAttributeMaxDynamicSharedMemorySize, SMEM_HGEMM);

    int n4 = (MM * DD) / 4;
    mask_split_kernel<<<(n4 + 255) / 256, 256>>>(x, lengths, xm, xh, xl);

    dim3 tb(32, 8);
    transpose_split_kernel<<<dim3(DD/32, DD/32), tb>>>(Wq, wqth, wqtl, DD, DD);
    transpose_split_kernel<<<dim3(DD/32, DD/32), tb>>>(Wk, wkth, wktl, DD, DD);
    transpose_split_kernel<<<dim3(DD/32, DD/32), tb>>>(Wv, wvth, wvtl, DD, DD);
    transpose_split_kernel<<<dim3(DD/32, DD/32), tb>>>(Wo, woth, wotl, DD, DD);
    transpose_split_kernel<<<dim3(FFD/32, DD/32), tb>>>(W1, w1th, w1tl, DD, FFD);
    transpose_split_kernel<<<dim3(DD/32, FFD/32), tb>>>(W2, w2th, w2tl, FFD, DD);

    dim3 g512(DD / 128, MM / 128);       // (4, 32)
    dim3 gFF (FFD / 128, MM / 128);      // (16, 32)

    hgemm<0><<<g512, 256, SMEM_HGEMM>>>(xh, xl, wqth, wqtl, bq, q, nullptr, nullptr, MM, DD, DD);
    hgemm<0><<<g512, 256, SMEM_HGEMM>>>(xh, xl, wkth, wktl, bk, k, nullptr, nullptr, MM, DD, DD);
    hgemm<0><<<g512, 256, SMEM_HGEMM>>>(xh, xl, wvth, wvtl, bv, v, nullptr, nullptr, MM, DD, DD);

    attn_diag_kernel<<<dim3(SS / 64, HH, BB), 128>>>(q, k, lengths, diag);

    wv_split_kernel<<<(n4 + 255) / 256, 256>>>(v, diag, wvh, wvl);

    hgemm<0><<<g512, 256, SMEM_HGEMM>>>(wvh, wvl, woth, wotl, bo, ao, nullptr, nullptr, MM, DD, DD);

    ln_kernel<true><<<MM, 256>>>(xm, ao, gamma1, beta1, y1, y1h, y1l);

    hgemm<1><<<gFF, 256, SMEM_HGEMM>>>(y1h, y1l, w1th, w1tl, b1, nullptr, h1h, h1l, MM, FFD, DD);
    hgemm<0><<<g512, 256, SMEM_HGEMM>>>(h1h, h1l, w2th, w2tl, b2, f2, nullptr, nullptr, MM, DD, FFD);

    ln_kernel<false><<<MM, 256>>>(y1, f2, gamma2, beta2, (float*)d_out, nullptr, nullptr);
}

// round 9
// speedup vs baseline: 2.7610x; 1.5406x over previous
#include <cuda_runtime.h>
#include <cuda_bf16.h>
#include <math.h>
#include <stdint.h>

#define BB 2
#define SS 2048
#define DD 512
#define HH 8
#define DK 64
#define FFD 2048
#define MM (BB*SS)          // 4096 rows
#define L2E 1.4426950408889634f

// ---------------- scratch (static device arrays; no runtime alloc) -------------
__device__ float g_xm[MM*DD];
__device__ float g_v [MM*DD];
__device__ float g_ao[MM*DD];
__device__ float g_y1[MM*DD];
__device__ float g_f2[MM*DD];
__device__ float g_diag[BB*HH*SS];
__device__ float g_bqkv[3*DD];
// bf16 hi/lo planes
__device__ __nv_bfloat16 g_xh [MM*DD],  g_xl [MM*DD];
__device__ __nv_bfloat16 g_qh [MM*DD],  g_ql [MM*DD];
__device__ __nv_bfloat16 g_kh [MM*DD],  g_kl [MM*DD];
__device__ __nv_bfloat16 g_wvh[MM*DD],  g_wvl[MM*DD];
__device__ __nv_bfloat16 g_y1h[MM*DD],  g_y1l[MM*DD];
__device__ __nv_bfloat16 g_h1h[MM*FFD], g_h1l[MM*FFD];
// transposed weights [N, K] bf16 hi/lo
__device__ __nv_bfloat16 g_wqkvth[3*DD*DD], g_wqkvtl[3*DD*DD];
__device__ __nv_bfloat16 g_woth[DD*DD], g_wotl[DD*DD];
__device__ __nv_bfloat16 g_w1th[FFD*DD], g_w1tl[FFD*DD];
__device__ __nv_bfloat16 g_w2th[DD*FFD], g_w2tl[DD*FFD];

// ---------------- PTX helpers ---------------------------------------------------
__device__ __forceinline__ uint32_t smem_u32(const void* p) {
    uint32_t a;
    asm("{ .reg .u64 t; cvta.to.shared.u64 t, %1; cvt.u32.u64 %0, t; }" : "=r"(a) : "l"(p));
    return a;
}
__device__ __forceinline__ void mma_bf16(float* c, const uint32_t* a, const uint32_t* b) {
    asm volatile(
        "mma.sync.aligned.m16n8k16.row.col.f32.bf16.bf16.f32 "
        "{%0,%1,%2,%3},{%4,%5,%6,%7},{%8,%9},{%0,%1,%2,%3};"
        : "+f"(c[0]), "+f"(c[1]), "+f"(c[2]), "+f"(c[3])
        : "r"(a[0]), "r"(a[1]), "r"(a[2]), "r"(a[3]), "r"(b[0]), "r"(b[1]));
}
__device__ __forceinline__ void ldsm4(uint32_t* r, uint32_t addr) {
    asm volatile("ldmatrix.sync.aligned.m8n8.x4.shared.b16 {%0,%1,%2,%3},[%4];"
                 : "=r"(r[0]), "=r"(r[1]), "=r"(r[2]), "=r"(r[3]) : "r"(addr));
}
__device__ __forceinline__ void cpa16(uint32_t dst, const void* src) {
    asm volatile("cp.async.cg.shared.global [%0],[%1],16;" :: "r"(dst), "l"(src));
}
__device__ __forceinline__ void split1(float a, __nv_bfloat16& h, __nv_bfloat16& l) {
    h = __float2bfloat16(a);
    l = __float2bfloat16(a - __bfloat162float(h));
}

// ---------------- weight transpose+split: oh/ol[C][R] = split(in[R][C]) --------
__global__ __launch_bounds__(256)
void transpose_split_kernel(const float* __restrict__ in,
                            __nv_bfloat16* __restrict__ oh, __nv_bfloat16* __restrict__ ol,
                            int R, int C)
{
    __shared__ float t[32][33];
    int bx = blockIdx.x * 32, by = blockIdx.y * 32;
    int tx = threadIdx.x, ty = threadIdx.y;   // (32, 8)
#pragma unroll
    for (int i = 0; i < 32; i += 8)
        t[ty + i][tx] = in[(size_t)(by + ty + i) * C + bx + tx];
    __syncthreads();
#pragma unroll
    for (int i = 0; i < 32; i += 8) {
        float v = t[tx][ty + i];
        __nv_bfloat16 h, l;
        split1(v, h, l);
        size_t o = (size_t)(bx + ty + i) * R + by + tx;
        oh[o] = h; ol[o] = l;
    }
}

__global__ void concat_bias_kernel(const float* __restrict__ a, const float* __restrict__ b,
                                   const float* __restrict__ c, float* __restrict__ o)
{
    int i = blockIdx.x * blockDim.x + threadIdx.x;
    if (i >= 3 * DD) return;
    o[i] = (i < DD) ? a[i] : (i < 2 * DD) ? b[i - DD] : c[i - 2 * DD];
}

// ---------------- HMMA bf16 3-pass GEMM ------------------------------------------
// C[M,N] = (Ah+Al)[M,K] @ (Bh+Bl)[N,K]^T + bias   (drops Al*Bl term)
// MODE 0: fp32 out  MODE 1: relu + bf16 split out  MODE 3: qkv combined out
#define STAGE_BYTES 32768
#define SMEM_HGEMM (3 * STAGE_BYTES)

template<int MODE>
__global__ __launch_bounds__(256, 1)
void hgemm(const __nv_bfloat16* __restrict__ Ah, const __nv_bfloat16* __restrict__ Al,
           const __nv_bfloat16* __restrict__ Bh, const __nv_bfloat16* __restrict__ Bl,
           const float* __restrict__ bias,
           float* __restrict__ C, __nv_bfloat16* __restrict__ Ch, __nv_bfloat16* __restrict__ Cl,
           __nv_bfloat16* __restrict__ Dh, __nv_bfloat16* __restrict__ Dl,
           int M, int N, int K, int OD)
{
    extern __shared__ char smem[];
    uint32_t sb = smem_u32(smem);
    int tid = threadIdx.x, lane = tid & 31, wid = tid >> 5;
    int bm = blockIdx.y * 128, bn = blockIdx.x * 128;
    int wm = wid & 1, wn = wid >> 1;
    int NK = K >> 5;

    auto issue = [&](int kt) {
        uint32_t base = sb + (kt % 3) * STAGE_BYTES;
        int k0 = kt << 5;
#pragma unroll
        for (int i = 0; i < 4; i++) {
            int ch = i * 256 + tid;
            int row = ch >> 3, col = ch & 7;
            const __nv_bfloat16* src =
                (col < 4 ? Ah : Al) + (size_t)(bm + row) * K + k0 + (col & 3) * 8;
            cpa16(base + row * 128 + ((col ^ (row & 7)) << 4), src);
        }
#pragma unroll
        for (int i = 0; i < 4; i++) {
            int ch = i * 256 + tid;
            int row = ch >> 3, col = ch & 7;
            const __nv_bfloat16* src =
                (col < 4 ? Bh : Bl) + (size_t)(bn + row) * K + k0 + (col & 3) * 8;
            cpa16(base + 16384 + row * 128 + ((col ^ (row & 7)) << 4), src);
        }
        asm volatile("cp.async.commit_group;");
    };

    issue(0); issue(1); issue(2);

    float acc[4][4][4];
#pragma unroll
    for (int i = 0; i < 4; i++)
#pragma unroll
        for (int j = 0; j < 4; j++)
#pragma unroll
            for (int r = 0; r < 4; r++) acc[i][j][r] = 0.f;

    int arow = (lane & 7) + ((lane >> 3) & 1) * 8;
    int asel = lane >> 4;
    int brow = (lane & 7) + (lane >> 4) * 8;
    int bsel = (lane >> 3) & 1;
    int rx = lane & 7;

    for (int kt = 0; kt < NK; kt++) {
        asm volatile("cp.async.wait_group %0;" :: "n"(2));
        __syncthreads();
        uint32_t base = sb + (kt % 3) * STAGE_BYTES;
#pragma unroll
        for (int s = 0; s < 2; s++) {
            uint32_t Ahf[16], Alf[16], Bhf[8], Blf[8];
#pragma unroll
            for (int mt = 0; mt < 4; mt++) {
                uint32_t ro = base + (wm * 64 + mt * 16 + arow) * 128;
                ldsm4(&Ahf[mt * 4], ro + (((2 * s + asel) ^ rx) << 4));
                ldsm4(&Alf[mt * 4], ro + (((4 + 2 * s + asel) ^ rx) << 4));
            }
#pragma unroll
            for (int nt2 = 0; nt2 < 2; nt2++) {
                uint32_t ro = base + 16384 + (wn * 32 + nt2 * 16 + brow) * 128;
                ldsm4(&Bhf[nt2 * 4], ro + (((2 * s + bsel) ^ rx) << 4));
                ldsm4(&Blf[nt2 * 4], ro + (((4 + 2 * s + bsel) ^ rx) << 4));
            }
#pragma unroll
            for (int mt = 0; mt < 4; mt++)
#pragma unroll
                for (int nt = 0; nt < 4; nt++)
                    mma_bf16(acc[mt][nt], &Ahf[mt * 4], &Bhf[nt * 2]);
#pragma unroll
            for (int mt = 0; mt < 4; mt++)
#pragma unroll
                for (int nt = 0; nt < 4; nt++)
                    mma_bf16(acc[mt][nt], &Ahf[mt * 4], &Blf[nt * 2]);
#pragma unroll
            for (int mt = 0; mt < 4; mt++)
#pragma unroll
                for (int nt = 0; nt < 4; nt++)
                    mma_bf16(acc[mt][nt], &Alf[mt * 4], &Bhf[nt * 2]);
        }
        __syncthreads();
        if (kt + 3 < NK) issue(kt + 3);
    }

    // epilogue
    int g = lane >> 2, tig = lane & 3;
    __nv_bfloat16 *oh = Ch, *ol = Cl;
    int seg = 0;
    if (MODE == 3) {
        seg = bn >> 9;              // 0: q, 1: k, 2: v
        if (seg == 1) { oh = Dh; ol = Dl; }
    }
#pragma unroll
    for (int mt = 0; mt < 4; mt++) {
#pragma unroll
        for (int nt = 0; nt < 4; nt++) {
            int colg = bn + wn * 32 + nt * 8 + tig * 2;
            float2 bv = *(const float2*)&bias[colg];
            int r0 = bm + wm * 64 + mt * 16 + g;
            float x0 = acc[mt][nt][0] + bv.x, x1 = acc[mt][nt][1] + bv.y;
            float x2 = acc[mt][nt][2] + bv.x, x3 = acc[mt][nt][3] + bv.y;
            if (MODE == 0) {
                float2 o0 = {x0, x1}, o1 = {x2, x3};
                *(float2*)&C[(size_t)r0 * OD + colg] = o0;
                *(float2*)&C[(size_t)(r0 + 8) * OD + colg] = o1;
            } else if (MODE == 1) {
                x0 = fmaxf(x0, 0.f); x1 = fmaxf(x1, 0.f);
                x2 = fmaxf(x2, 0.f); x3 = fmaxf(x3, 0.f);
                __nv_bfloat16 h0, l0, h1, l1, h2, l2, h3, l3;
                split1(x0, h0, l0); split1(x1, h1, l1);
                split1(x2, h2, l2); split1(x3, h3, l3);
                __nv_bfloat162 hh0 = {h0, h1}, ll0 = {l0, l1};
                __nv_bfloat162 hh1 = {h2, h3}, ll1 = {l2, l3};
                *(__nv_bfloat162*)&oh[(size_t)r0 * OD + colg] = hh0;
                *(__nv_bfloat162*)&ol[(size_t)r0 * OD + colg] = ll0;
                *(__nv_bfloat162*)&oh[(size_t)(r0 + 8) * OD + colg] = hh1;
                *(__nv_bfloat162*)&ol[(size_t)(r0 + 8) * OD + colg] = ll1;
            } else {  // MODE 3
                int col = colg & 511;
                if (seg == 2) {
                    float2 o0 = {x0, x1}, o1 = {x2, x3};
                    *(float2*)&C[(size_t)r0 * DD + col] = o0;
                    *(float2*)&C[(size_t)(r0 + 8) * DD + col] = o1;
                } else {
                    __nv_bfloat16 h0, l0, h1, l1, h2, l2, h3, l3;
                    split1(x0, h0, l0); split1(x1, h1, l1);
                    split1(x2, h2, l2); split1(x3, h3, l3);
                    __nv_bfloat162 hh0 = {h0, h1}, ll0 = {l0, l1};
                    __nv_bfloat162 hh1 = {h2, h3}, ll1 = {l2, l3};
                    *(__nv_bfloat162*)&oh[(size_t)r0 * DD + col] = hh0;
                    *(__nv_bfloat162*)&ol[(size_t)r0 * DD + col] = ll0;
                    *(__nv_bfloat162*)&oh[(size_t)(r0 + 8) * DD + col] = hh1;
                    *(__nv_bfloat162*)&ol[(size_t)(r0 + 8) * DD + col] = ll1;
                }
            }
        }
    }
}

// ---------------- pad-mask + split ----------------------------------------------
__global__ void mask_split_kernel(const float* __restrict__ x, const int* __restrict__ lengths,
                                  float* __restrict__ xm,
                                  __nv_bfloat16* __restrict__ xh, __nv_bfloat16* __restrict__ xl)
{
    int i = blockIdx.x * blockDim.x + threadIdx.x;
    if (i >= (MM*DD)/4) return;
    int row = (i * 4) / DD;
    int s = row & (SS - 1);
    int b = row >> 11;
    float4 val = ((const float4*)x)[i];
    if (s >= lengths[b]) val = make_float4(0.f, 0.f, 0.f, 0.f);
    ((float4*)xm)[i] = val;
    __nv_bfloat16 h0, l0, h1, l1, h2, l2, h3, l3;
    split1(val.x, h0, l0); split1(val.y, h1, l1);
    split1(val.z, h2, l2); split1(val.w, h3, l3);
    __nv_bfloat162* ph = (__nv_bfloat162*)&xh[i * 4];
    __nv_bfloat162* pl = (__nv_bfloat162*)&xl[i * 4];
    ph[0] = {h0, h1}; ph[1] = {h2, h3};
    pl[0] = {l0, l1}; pl[1] = {l2, l3};
}

// ---------------- attention diagonal via HMMA (flash-style, diag only) ----------
// grid (S/64, H, B) reversed-x, 128 threads (4 warps x 16 query rows)
// smem: q planes [0,16384), K double-buffer at 16384 + buf*16384
#define SMEM_ATTN 49152
__global__ __launch_bounds__(128, 1)
void attn_diag_hmma(const __nv_bfloat16* __restrict__ qh, const __nv_bfloat16* __restrict__ ql,
                    const __nv_bfloat16* __restrict__ kh, const __nv_bfloat16* __restrict__ kl,
                    const int* __restrict__ lengths, float* __restrict__ diag)
{
    extern __shared__ char sm[];
    uint32_t sb = smem_u32(sm);
    int bx = (int)gridDim.x - 1 - (int)blockIdx.x;
    int h = blockIdx.y, b = blockIdx.z;
    int tid = threadIdx.x, lane = tid & 31, w = tid >> 5;
    int i0 = bx * 64;
    int len = lengths[b];

    const size_t qg = ((size_t)(b * SS + i0)) * DD + h * DK;
    // issue Q planes (part of group 0)
#pragma unroll
    for (int i = 0; i < 4; i++) {
        int idx = i * 128 + tid;
        int row = idx >> 3, c = idx & 7;
        cpa16(sb + row * 128 + ((c ^ (row & 7)) << 4), qh + qg + (size_t)row * DD + c * 8);
    }
#pragma unroll
    for (int i = 0; i < 4; i++) {
        int idx = i * 128 + tid;
        int row = idx >> 3, c = idx & 7;
        cpa16(sb + 8192 + row * 128 + ((c ^ (row & 7)) << 4), ql + qg + (size_t)row * DD + c * 8);
    }
    auto issueK = [&](int t, int buf) {
        uint32_t kb = sb + 16384 + buf * 16384;
        size_t g = ((size_t)(b * SS + t * 64)) * DD + h * DK;
#pragma unroll
        for (int i = 0; i < 4; i++) {
            int idx = i * 128 + tid;
            int row = idx >> 3, c = idx & 7;
            cpa16(kb + row * 128 + ((c ^ (row & 7)) << 4), kh + g + (size_t)row * DD + c * 8);
        }
#pragma unroll
        for (int i = 0; i < 4; i++) {
            int idx = i * 128 + tid;
            int row = idx >> 3, c = idx & 7;
            cpa16(kb + 8192 + row * 128 + ((c ^ (row & 7)) << 4), kl + g + (size_t)row * DD + c * 8);
        }
    };
    issueK(0, 0);
    asm volatile("cp.async.commit_group;");
    if (bx >= 1) { issueK(1, 1); asm volatile("cp.async.commit_group;"); }

    int arow = (lane & 7) + ((lane >> 3) & 1) * 8;
    int asel = lane >> 4;
    int brow = (lane & 7) + (lane >> 4) * 8;
    int bsel = (lane >> 3) & 1;
    int g_ = lane >> 2, tig = lane & 3;

    uint32_t Qh[16], Ql[16];
    float m[2] = {-1e30f, -1e30f}, l[2] = {0.f, 0.f}, sd[2] = {-1e30f, -1e30f};

    for (int t = 0; t <= bx; t++) {
        if (t < bx) asm volatile("cp.async.wait_group 1;");
        else        asm volatile("cp.async.wait_group 0;");
        __syncthreads();
        if (t == 0) {
            int r = w * 16 + arow;
#pragma unroll
            for (int kc = 0; kc < 4; kc++) {
                ldsm4(&Qh[kc * 4], sb + r * 128 + (((2 * kc + asel) ^ (r & 7)) << 4));
                ldsm4(&Ql[kc * 4], sb + 8192 + r * 128 + (((2 * kc + asel) ^ (r & 7)) << 4));
            }
        }
        uint32_t kb = sb + 16384 + (t & 1) * 16384;
        float acc[8][4];
#pragma unroll
        for (int nt = 0; nt < 8; nt++)
#pragma unroll
            for (int r = 0; r < 4; r++) acc[nt][r] = 0.f;

#pragma unroll
        for (int kc = 0; kc < 4; kc++) {
            uint32_t Bh[16], Bl[16];
#pragma unroll
            for (int nt2 = 0; nt2 < 4; nt2++) {
                int rr = nt2 * 16 + brow;
                ldsm4(&Bh[nt2 * 4], kb + rr * 128 + (((2 * kc + bsel) ^ (rr & 7)) << 4));
                ldsm4(&Bl[nt2 * 4], kb + 8192 + rr * 128 + (((2 * kc + bsel) ^ (rr & 7)) << 4));
            }
#pragma unroll
            for (int nt = 0; nt < 8; nt++)
                mma_bf16(acc[nt], &Qh[kc * 4], &Bh[(nt >> 1) * 4 + (nt & 1) * 2]);
#pragma unroll
            for (int nt = 0; nt < 8; nt++)
                mma_bf16(acc[nt], &Qh[kc * 4], &Bl[(nt >> 1) * 4 + (nt & 1) * 2]);
#pragma unroll
            for (int nt = 0; nt < 8; nt++)
                mma_bf16(acc[nt], &Ql[kc * 4], &Bh[(nt >> 1) * 4 + (nt & 1) * 2]);
        }

        bool dtile = (t == bx);
#pragma unroll
        for (int r = 0; r < 2; r++) {
            int il = w * 16 + g_ + r * 8;
            float tm = -1e30f;
            float vals[16];
#pragma unroll
            for (int nt = 0; nt < 8; nt++)
#pragma unroll
                for (int c = 0; c < 2; c++) {
                    float v = acc[nt][r * 2 + c];
                    if (dtile) {
                        int jl = nt * 8 + tig * 2 + c;
                        if (jl == il) sd[r] = v;
                        if (jl > il) v = -1e30f;
                    }
                    vals[nt * 2 + c] = v;
                    tm = fmaxf(tm, v);
                }
            float mn = fmaxf(m[r], tm);
            float sc = exp2f((m[r] - mn) * L2E);
            float ls = 0.f;
#pragma unroll
            for (int i = 0; i < 16; i++) ls += exp2f((vals[i] - mn) * L2E);
            l[r] = l[r] * sc + ls;
            m[r] = mn;
        }
        __syncthreads();
        if (t + 2 <= bx) { issueK(t + 2, t & 1); asm volatile("cp.async.commit_group;"); }
    }

    // cross-lane combine within the 4 lanes sharing each row (lane&3 varies)
#pragma unroll
    for (int r = 0; r < 2; r++) {
        float mm = m[r], ll = l[r], ss = sd[r];
#pragma unroll
        for (int o = 1; o <= 2; o <<= 1) {
            float mo = __shfl_xor_sync(0xffffffffu, mm, o);
            float lo = __shfl_xor_sync(0xffffffffu, ll, o);
            float so = __shfl_xor_sync(0xffffffffu, ss, o);
            float mn = fmaxf(mm, mo);
            ll = ll * exp2f((mm - mn) * L2E) + lo * exp2f((mo - mn) * L2E);
            mm = mn;
            ss = fmaxf(ss, so);
        }
        if (tig == 0) {
            int ig = i0 + w * 16 + g_ + r * 8;
            float dv = (ig < len) ? exp2f((ss - mm) * L2E) / ll : 0.f;
            diag[(size_t)(b * HH + h) * SS + ig] = dv;
        }
    }
}

// ---------------- wv = diag * v  (-> bf16 hi/lo planes) -------------------------
__global__ void wv_split_kernel(const float* __restrict__ V, const float* __restrict__ diag,
                                __nv_bfloat16* __restrict__ wh, __nv_bfloat16* __restrict__ wl)
{
    int i = blockIdx.x * blockDim.x + threadIdx.x;
    if (i >= (MM*DD)/4) return;
    int e = i * 4;
    int row = e / DD;
    int c = e & (DD - 1);
    int b = row >> 11;
    int s = row & (SS - 1);
    int h = c >> 6;
    float dv = diag[(size_t)(b * HH + h) * SS + s];
    float4 v4 = ((const float4*)V)[i];
    v4.x *= dv; v4.y *= dv; v4.z *= dv; v4.w *= dv;
    __nv_bfloat16 h0, l0, h1, l1, h2, l2, h3, l3;
    split1(v4.x, h0, l0); split1(v4.y, h1, l1);
    split1(v4.z, h2, l2); split1(v4.w, h3, l3);
    __nv_bfloat162* ph = (__nv_bfloat162*)&wh[e];
    __nv_bfloat162* pl = (__nv_bfloat162*)&wl[e];
    ph[0] = {h0, h1}; ph[1] = {h2, h3};
    pl[0] = {l0, l1}; pl[1] = {l2, l3};
}

// ---------------- LayerNorm(a + r)  (optionally also bf16 split out) ------------
template<bool SPLIT>
__global__ __launch_bounds__(256)
void ln_kernel(const float* __restrict__ a, const float* __restrict__ r,
               const float* __restrict__ gamma, const float* __restrict__ beta,
               float* __restrict__ out,
               __nv_bfloat16* __restrict__ oh, __nv_bfloat16* __restrict__ ol)
{
    int row = blockIdx.x;
    int tid = threadIdx.x;
    const float* pa = a + (size_t)row * DD;
    const float* pr = r + (size_t)row * DD;

    float v0 = pa[tid] + pr[tid];
    float v1 = pa[tid + 256] + pr[tid + 256];

    __shared__ float sred[8];
    __shared__ float smean, srstd;

    float s = v0 + v1;
#pragma unroll
    for (int o = 16; o > 0; o >>= 1) s += __shfl_xor_sync(0xffffffffu, s, o);
    if ((tid & 31) == 0) sred[tid >> 5] = s;
    __syncthreads();
    if (tid == 0) {
        float t = 0.f;
#pragma unroll
        for (int i = 0; i < 8; i++) t += sred[i];
        smean = t * (1.0f / DD);
    }
    __syncthreads();
    float mean = smean;
    float d0 = v0 - mean, d1 = v1 - mean;
    float vs = d0 * d0 + d1 * d1;
#pragma unroll
    for (int o = 16; o > 0; o >>= 1) vs += __shfl_xor_sync(0xffffffffu, vs, o);
    if ((tid & 31) == 0) sred[tid >> 5] = vs;
    __syncthreads();
    if (tid == 0) {
        float t = 0.f;
#pragma unroll
        for (int i = 0; i < 8; i++) t += sred[i];
        srstd = rsqrtf(t * (1.0f / DD) + 1e-3f);
    }
    __syncthreads();
    float rstd = srstd;
    float o0 = gamma[tid]       * (d0 * rstd) + beta[tid];
    float o1 = gamma[tid + 256] * (d1 * rstd) + beta[tid + 256];
    out[(size_t)row * DD + tid]       = o0;
    out[(size_t)row * DD + tid + 256] = o1;
    if (SPLIT) {
        __nv_bfloat16 h0, l0, h1, l1;
        split1(o0, h0, l0);
        split1(o1, h1, l1);
        oh[(size_t)row * DD + tid]       = h0;
        ol[(size_t)row * DD + tid]       = l0;
        oh[(size_t)row * DD + tid + 256] = h1;
        ol[(size_t)row * DD + tid + 256] = l1;
    }
}

// ---------------- launch --------------------------------------------------------
extern "C" void kernel_launch(void* const* d_in, const int* in_sizes, int n_in,
                              void* d_out, int out_size)
{
    const float* x       = (const float*)d_in[0];
    const int*   lengths = (const int*)d_in[1];
    const float* Wq = (const float*)d_in[2];
    const float* bq = (const float*)d_in[3];
    const float* Wk = (const float*)d_in[4];
    const float* bk = (const float*)d_in[5];
    const float* Wv = (const float*)d_in[6];
    const float* bv = (const float*)d_in[7];
    const float* Wo = (const float*)d_in[8];
    const float* bo = (const float*)d_in[9];
    const float* W1 = (const float*)d_in[10];
    const float* b1 = (const float*)d_in[11];
    const float* W2 = (const float*)d_in[12];
    const float* b2 = (const float*)d_in[13];
    const float* gamma1 = (const float*)d_in[14];
    const float* beta1  = (const float*)d_in[15];
    const float* gamma2 = (const float*)d_in[16];
    const float* beta2  = (const float*)d_in[17];

    float *xm, *v, *ao, *y1, *f2, *diag, *bqkv;
    __nv_bfloat16 *xh, *xl, *qh, *ql, *kh, *kl, *wvh, *wvl, *y1h, *y1l, *h1h, *h1l;
    __nv_bfloat16 *wqkvth, *wqkvtl, *woth, *wotl, *w1th, *w1tl, *w2th, *w2tl;
    cudaGetSymbolAddress((void**)&xm,   g_xm);
    cudaGetSymbolAddress((void**)&v,    g_v);
    cudaGetSymbolAddress((void**)&ao,   g_ao);
    cudaGetSymbolAddress((void**)&y1,   g_y1);
    cudaGetSymbolAddress((void**)&f2,   g_f2);
    cudaGetSymbolAddress((void**)&diag, g_diag);
    cudaGetSymbolAddress((void**)&bqkv, g_bqkv);
    cudaGetSymbolAddress((void**)&xh,   g_xh);
    cudaGetSymbolAddress((void**)&xl,   g_xl);
    cudaGetSymbolAddress((void**)&qh,   g_qh);
    cudaGetSymbolAddress((void**)&ql,   g_ql);
    cudaGetSymbolAddress((void**)&kh,   g_kh);
    cudaGetSymbolAddress((void**)&kl,   g_kl);
    cudaGetSymbolAddress((void**)&wvh,  g_wvh);
    cudaGetSymbolAddress((void**)&wvl,  g_wvl);
    cudaGetSymbolAddress((void**)&y1h,  g_y1h);
    cudaGetSymbolAddress((void**)&y1l,  g_y1l);
    cudaGetSymbolAddress((void**)&h1h,  g_h1h);
    cudaGetSymbolAddress((void**)&h1l,  g_h1l);
    cudaGetSymbolAddress((void**)&wqkvth, g_wqkvth);
    cudaGetSymbolAddress((void**)&wqkvtl, g_wqkvtl);
    cudaGetSymbolAddress((void**)&woth, g_woth);
    cudaGetSymbolAddress((void**)&wotl, g_wotl);
    cudaGetSymbolAddress((void**)&w1th, g_w1th);
    cudaGetSymbolAddress((void**)&w1tl, g_w1tl);
    cudaGetSymbolAddress((void**)&w2th, g_w2th);
    cudaGetSymbolAddress((void**)&w2tl, g_w2tl);

    cudaFuncSetAttribute(hgemm<0>, cudaFuncAttributeMaxDynamicSharedMemorySize, SMEM_HGEMM);
    cudaFuncSetAttribute(hgemm<1>, cudaFuncAttributeMaxDynamicSharedMemorySize, SMEM_HGEMM);
    cudaFuncSetAttribute(hgemm<3>, cudaFuncAttributeMaxDynamicSharedMemorySize, SMEM_HGEMM);
    cudaFuncSetAttribute(attn_diag_hmma, cudaFuncAttributeMaxDynamicSharedMemorySize, SMEM_ATTN);

    int n4 = (MM * DD) / 4;
    mask_split_kernel<<<(n4 + 255) / 256, 256>>>(x, lengths, xm, xh, xl);

    dim3 tb(32, 8);
    transpose_split_kernel<<<dim3(DD/32, DD/32), tb>>>(Wq, wqkvth, wqkvtl, DD, DD);
    transpose_split_kernel<<<dim3(DD/32, DD/32), tb>>>(Wk, wqkvth + DD*DD, wqkvtl + DD*DD, DD, DD);
    transpose_split_kernel<<<dim3(DD/32, DD/32), tb>>>(Wv, wqkvth + 2*DD*DD, wqkvtl + 2*DD*DD, DD, DD);
    transpose_split_kernel<<<dim3(DD/32, DD/32), tb>>>(Wo, woth, wotl, DD, DD);
    transpose_split_kernel<<<dim3(FFD/32, DD/32), tb>>>(W1, w1th, w1tl, DD, FFD);
    transpose_split_kernel<<<dim3(DD/32, FFD/32), tb>>>(W2, w2th, w2tl, FFD, DD);
    concat_bias_kernel<<<6, 256>>>(bq, bk, bv, bqkv);

    dim3 g512(DD / 128, MM / 128);       // (4, 32)
    dim3 gQKV(3 * DD / 128, MM / 128);   // (12, 32)
    dim3 gFF (FFD / 128, MM / 128);      // (16, 32)

    // fused QKV: q,k -> bf16 planes; v -> fp32
    hgemm<3><<<gQKV, 256, SMEM_HGEMM>>>(xh, xl, wqkvth, wqkvtl, bqkv,
                                        v, qh, ql, kh, kl, MM, 3 * DD, DD, DD);

    attn_diag_hmma<<<dim3(SS / 64, HH, BB), 128, SMEM_ATTN>>>(qh, ql, kh, kl, lengths, diag);

    wv_split_kernel<<<(n4 + 255) / 256, 256>>>(v, diag, wvh, wvl);

    hgemm<0><<<g512, 256, SMEM_HGEMM>>>(wvh, wvl, woth, wotl, bo,
                                        ao, nullptr, nullptr, nullptr, nullptr, MM, DD, DD, DD);

    ln_kernel<true><<<MM, 256>>>(xm, ao, gamma1, beta1, y1, y1h, y1l);

    hgemm<1><<<gFF, 256, SMEM_HGEMM>>>(y1h, y1l, w1th, w1tl, b1,
                                       nullptr, h1h, h1l, nullptr, nullptr, MM, FFD, DD, FFD);
    hgemm<0><<<g512, 256, SMEM_HGEMM>>>(h1h, h1l, w2th, w2tl, b2,
                                        f2, nullptr, nullptr, nullptr, nullptr, MM, DD, FFD, DD);

    ln_kernel<false><<<MM, 256>>>(y1, f2, gamma2, beta2, (float*)d_out, nullptr, nullptr);
}

// round 10
// speedup vs baseline: 3.2652x; 1.1826x over previous
#include <cuda_runtime.h>
#include <cuda_bf16.h>
#include <math.h>
#include <stdint.h>

#define BB 2
#define SS 2048
#define DD 512
#define HH 8
#define DK 64
#define FFD 2048
#define MM (BB*SS)          // 4096 rows
#define L2E 1.4426950408889634f

// ---------------- scratch (static device arrays; no runtime alloc) -------------
__device__ float g_xm[MM*DD];
__device__ float g_v [MM*DD];
__device__ float g_ao[MM*DD];
__device__ float g_y1[MM*DD];
__device__ float g_f2[MM*DD];
__device__ float g_diag[BB*HH*SS];
__device__ float g_bqkv[3*DD];
// bf16 hi/lo planes
__device__ __nv_bfloat16 g_xh [MM*DD],  g_xl [MM*DD];
__device__ __nv_bfloat16 g_qh [MM*DD],  g_ql [MM*DD];
__device__ __nv_bfloat16 g_kh [MM*DD],  g_kl [MM*DD];
__device__ __nv_bfloat16 g_wvh[MM*DD],  g_wvl[MM*DD];
__device__ __nv_bfloat16 g_y1h[MM*DD],  g_y1l[MM*DD];
__device__ __nv_bfloat16 g_h1h[MM*FFD], g_h1l[MM*FFD];
// transposed weights [N, K] bf16 hi/lo
__device__ __nv_bfloat16 g_wqkvth[3*DD*DD], g_wqkvtl[3*DD*DD];
__device__ __nv_bfloat16 g_woth[DD*DD], g_wotl[DD*DD];
__device__ __nv_bfloat16 g_w1th[FFD*DD], g_w1tl[FFD*DD];
__device__ __nv_bfloat16 g_w2th[DD*FFD], g_w2tl[DD*FFD];

// ---------------- PTX helpers ---------------------------------------------------
__device__ __forceinline__ uint32_t smem_u32(const void* p) {
    uint32_t a;
    asm("{ .reg .u64 t; cvta.to.shared.u64 t, %1; cvt.u32.u64 %0, t; }" : "=r"(a) : "l"(p));
    return a;
}
__device__ __forceinline__ void mma_bf16(float* c, const uint32_t* a, const uint32_t* b) {
    asm volatile(
        "mma.sync.aligned.m16n8k16.row.col.f32.bf16.bf16.f32 "
        "{%0,%1,%2,%3},{%4,%5,%6,%7},{%8,%9},{%0,%1,%2,%3};"
        : "+f"(c[0]), "+f"(c[1]), "+f"(c[2]), "+f"(c[3])
        : "r"(a[0]), "r"(a[1]), "r"(a[2]), "r"(a[3]), "r"(b[0]), "r"(b[1]));
}
__device__ __forceinline__ void ldsm4(uint32_t* r, uint32_t addr) {
    asm volatile("ldmatrix.sync.aligned.m8n8.x4.shared.b16 {%0,%1,%2,%3},[%4];"
                 : "=r"(r[0]), "=r"(r[1]), "=r"(r[2]), "=r"(r[3]) : "r"(addr));
}
__device__ __forceinline__ void cpa16(uint32_t dst, const void* src) {
    asm volatile("cp.async.cg.shared.global [%0],[%1],16;" :: "r"(dst), "l"(src));
}
__device__ __forceinline__ void split1(float a, __nv_bfloat16& h, __nv_bfloat16& l) {
    h = __float2bfloat16(a);
    l = __float2bfloat16(a - __bfloat162float(h));
}

// ---------------- weight transpose+split: oh/ol[C][R] = split(in[R][C]) --------
__global__ __launch_bounds__(256)
void transpose_split_kernel(const float* __restrict__ in,
                            __nv_bfloat16* __restrict__ oh, __nv_bfloat16* __restrict__ ol,
                            int R, int C)
{
    __shared__ float t[32][33];
    int bx = blockIdx.x * 32, by = blockIdx.y * 32;
    int tx = threadIdx.x, ty = threadIdx.y;   // (32, 8)
#pragma unroll
    for (int i = 0; i < 32; i += 8)
        t[ty + i][tx] = in[(size_t)(by + ty + i) * C + bx + tx];
    __syncthreads();
#pragma unroll
    for (int i = 0; i < 32; i += 8) {
        float v = t[tx][ty + i];
        __nv_bfloat16 h, l;
        split1(v, h, l);
        size_t o = (size_t)(bx + ty + i) * R + by + tx;
        oh[o] = h; ol[o] = l;
    }
}

// batched version: 4 square DxD transposes in one launch (z selects matrix)
__global__ __launch_bounds__(256)
void transpose_split4_kernel(const float* __restrict__ i0, const float* __restrict__ i1,
                             const float* __restrict__ i2, const float* __restrict__ i3,
                             __nv_bfloat16* __restrict__ h0, __nv_bfloat16* __restrict__ l0,
                             __nv_bfloat16* __restrict__ h1, __nv_bfloat16* __restrict__ l1,
                             __nv_bfloat16* __restrict__ h2, __nv_bfloat16* __restrict__ l2,
                             __nv_bfloat16* __restrict__ h3, __nv_bfloat16* __restrict__ l3)
{
    int z = blockIdx.z;
    const float* in = (z == 0) ? i0 : (z == 1) ? i1 : (z == 2) ? i2 : i3;
    __nv_bfloat16* oh = (z == 0) ? h0 : (z == 1) ? h1 : (z == 2) ? h2 : h3;
    __nv_bfloat16* ol = (z == 0) ? l0 : (z == 1) ? l1 : (z == 2) ? l2 : l3;
    __shared__ float t[32][33];
    int bx = blockIdx.x * 32, by = blockIdx.y * 32;
    int tx = threadIdx.x, ty = threadIdx.y;   // (32, 8)
#pragma unroll
    for (int i = 0; i < 32; i += 8)
        t[ty + i][tx] = in[(size_t)(by + ty + i) * DD + bx + tx];
    __syncthreads();
#pragma unroll
    for (int i = 0; i < 32; i += 8) {
        float v = t[tx][ty + i];
        __nv_bfloat16 h, l;
        split1(v, h, l);
        size_t o = (size_t)(bx + ty + i) * DD + by + tx;
        oh[o] = h; ol[o] = l;
    }
}

__global__ void concat_bias_kernel(const float* __restrict__ a, const float* __restrict__ b,
                                   const float* __restrict__ c, float* __restrict__ o)
{
    int i = blockIdx.x * blockDim.x + threadIdx.x;
    if (i >= 3 * DD) return;
    o[i] = (i < DD) ? a[i] : (i < 2 * DD) ? b[i - DD] : c[i - 2 * DD];
}

// ---------------- HMMA bf16 3-pass GEMM ------------------------------------------
// C[M,N] = (Ah+Al)[M,K] @ (Bh+Bl)[N,K]^T + bias   (drops Al*Bl term)
// MODE 0: fp32 out  MODE 1: relu + bf16 split out  MODE 3: qkv combined out
// skipmode 0: none  1: fully-padded tile -> C=bias  2: fully-padded tile -> row-broadcast
#define STAGE_BYTES 32768
#define SMEM_HGEMM (3 * STAGE_BYTES)

template<int MTN>
__device__ __forceinline__ void gemm_tiles(uint32_t base, int arow, int asel,
                                           int brow, int bsel, int rx, int wm, int wn,
                                           float acc[4][4][4])
{
#pragma unroll
    for (int s = 0; s < 2; s++) {
        uint32_t Ahf[16], Alf[16], Bhf[8], Blf[8];
#pragma unroll
        for (int mt = 0; mt < MTN; mt++) {
            uint32_t ro = base + (wm * 64 + mt * 16 + arow) * 128;
            ldsm4(&Ahf[mt * 4], ro + (((2 * s + asel) ^ rx) << 4));
            ldsm4(&Alf[mt * 4], ro + (((4 + 2 * s + asel) ^ rx) << 4));
        }
#pragma unroll
        for (int nt2 = 0; nt2 < 2; nt2++) {
            uint32_t ro = base + 16384 + (wn * 32 + nt2 * 16 + brow) * 128;
            ldsm4(&Bhf[nt2 * 4], ro + (((2 * s + bsel) ^ rx) << 4));
            ldsm4(&Blf[nt2 * 4], ro + (((4 + 2 * s + bsel) ^ rx) << 4));
        }
#pragma unroll
        for (int mt = 0; mt < MTN; mt++)
#pragma unroll
            for (int nt = 0; nt < 4; nt++)
                mma_bf16(acc[mt][nt], &Ahf[mt * 4], &Bhf[nt * 2]);
#pragma unroll
        for (int mt = 0; mt < MTN; mt++)
#pragma unroll
            for (int nt = 0; nt < 4; nt++)
                mma_bf16(acc[mt][nt], &Ahf[mt * 4], &Blf[nt * 2]);
#pragma unroll
        for (int mt = 0; mt < MTN; mt++)
#pragma unroll
            for (int nt = 0; nt < 4; nt++)
                mma_bf16(acc[mt][nt], &Alf[mt * 4], &Bhf[nt * 2]);
    }
}

template<int MODE>
__global__ __launch_bounds__(256, 1)
void hgemm(const __nv_bfloat16* __restrict__ Ah, const __nv_bfloat16* __restrict__ Al,
           const __nv_bfloat16* __restrict__ Bh, const __nv_bfloat16* __restrict__ Bl,
           const float* __restrict__ bias,
           float* __restrict__ C, __nv_bfloat16* __restrict__ Ch, __nv_bfloat16* __restrict__ Cl,
           __nv_bfloat16* __restrict__ Dh, __nv_bfloat16* __restrict__ Dl,
           const int* __restrict__ lengths, int skipmode,
           int M, int N, int K, int OD)
{
    extern __shared__ char smem[];
    uint32_t sb = smem_u32(smem);
    int tid = threadIdx.x, lane = tid & 31, wid = tid >> 5;
    int bm = blockIdx.y * 128, bn = blockIdx.x * 128;
    int wm = wid & 1, wn = wid >> 1;
    int NK = K >> 5;

    bool padded = false;
    if (skipmode) {
        int b = bm >> 11;
        int s0 = bm & (SS - 1);
        padded = (s0 >= lengths[b]);
    }
    bool skipall = (skipmode == 1) && padded;
    bool reduced = (skipmode == 2) && padded;

    float acc[4][4][4];
#pragma unroll
    for (int i = 0; i < 4; i++)
#pragma unroll
        for (int j = 0; j < 4; j++)
#pragma unroll
            for (int r = 0; r < 4; r++) acc[i][j][r] = 0.f;

    int arow = (lane & 7) + ((lane >> 3) & 1) * 8;
    int asel = lane >> 4;
    int brow = (lane & 7) + (lane >> 4) * 8;
    int bsel = (lane >> 3) & 1;
    int rx = lane & 7;

    if (!skipall) {
        auto issue = [&](int kt) {
            uint32_t base = sb + (kt % 3) * STAGE_BYTES;
            int k0 = kt << 5;
#pragma unroll
            for (int i = 0; i < 4; i++) {
                int ch = i * 256 + tid;
                int row = ch >> 3, col = ch & 7;
                const __nv_bfloat16* src =
                    (col < 4 ? Ah : Al) + (size_t)(bm + row) * K + k0 + (col & 3) * 8;
                cpa16(base + row * 128 + ((col ^ (row & 7)) << 4), src);
            }
#pragma unroll
            for (int i = 0; i < 4; i++) {
                int ch = i * 256 + tid;
                int row = ch >> 3, col = ch & 7;
                const __nv_bfloat16* src =
                    (col < 4 ? Bh : Bl) + (size_t)(bn + row) * K + k0 + (col & 3) * 8;
                cpa16(base + 16384 + row * 128 + ((col ^ (row & 7)) << 4), src);
            }
            asm volatile("cp.async.commit_group;");
        };

        issue(0); issue(1); issue(2);

        if (reduced) {
            for (int kt = 0; kt < NK; kt++) {
                asm volatile("cp.async.wait_group %0;" :: "n"(2));
                __syncthreads();
                gemm_tiles<1>(sb + (kt % 3) * STAGE_BYTES, arow, asel, brow, bsel, rx, wm, wn, acc);
                __syncthreads();
                if (kt + 3 < NK) issue(kt + 3);
            }
            // broadcast row-block 0 to all row blocks (all A rows identical)
#pragma unroll
            for (int mt = 1; mt < 4; mt++)
#pragma unroll
                for (int nt = 0; nt < 4; nt++)
#pragma unroll
                    for (int r = 0; r < 4; r++) acc[mt][nt][r] = acc[0][nt][r];
        } else {
            for (int kt = 0; kt < NK; kt++) {
                asm volatile("cp.async.wait_group %0;" :: "n"(2));
                __syncthreads();
                gemm_tiles<4>(sb + (kt % 3) * STAGE_BYTES, arow, asel, brow, bsel, rx, wm, wn, acc);
                __syncthreads();
                if (kt + 3 < NK) issue(kt + 3);
            }
        }
    }

    // epilogue
    int g = lane >> 2, tig = lane & 3;
    __nv_bfloat16 *oh = Ch, *ol = Cl;
    int seg = 0;
    if (MODE == 3) {
        seg = bn >> 9;              // 0: q, 1: k, 2: v
        if (seg == 1) { oh = Dh; ol = Dl; }
    }
#pragma unroll
    for (int mt = 0; mt < 4; mt++) {
#pragma unroll
        for (int nt = 0; nt < 4; nt++) {
            int colg = bn + wn * 32 + nt * 8 + tig * 2;
            float2 bv = *(const float2*)&bias[colg];
            int r0 = bm + wm * 64 + mt * 16 + g;
            float x0 = acc[mt][nt][0] + bv.x, x1 = acc[mt][nt][1] + bv.y;
            float x2 = acc[mt][nt][2] + bv.x, x3 = acc[mt][nt][3] + bv.y;
            if (MODE == 0) {
                float2 o0 = {x0, x1}, o1 = {x2, x3};
                *(float2*)&C[(size_t)r0 * OD + colg] = o0;
                *(float2*)&C[(size_t)(r0 + 8) * OD + colg] = o1;
            } else if (MODE == 1) {
                x0 = fmaxf(x0, 0.f); x1 = fmaxf(x1, 0.f);
                x2 = fmaxf(x2, 0.f); x3 = fmaxf(x3, 0.f);
                __nv_bfloat16 h0, l0, h1, l1, h2, l2, h3, l3;
                split1(x0, h0, l0); split1(x1, h1, l1);
                split1(x2, h2, l2); split1(x3, h3, l3);
                __nv_bfloat162 hh0 = {h0, h1}, ll0 = {l0, l1};
                __nv_bfloat162 hh1 = {h2, h3}, ll1 = {l2, l3};
                *(__nv_bfloat162*)&oh[(size_t)r0 * OD + colg] = hh0;
                *(__nv_bfloat162*)&ol[(size_t)r0 * OD + colg] = ll0;
                *(__nv_bfloat162*)&oh[(size_t)(r0 + 8) * OD + colg] = hh1;
                *(__nv_bfloat162*)&ol[(size_t)(r0 + 8) * OD + colg] = ll1;
            } else {  // MODE 3
                int col = colg & 511;
                if (seg == 2) {
                    float2 o0 = {x0, x1}, o1 = {x2, x3};
                    *(float2*)&C[(size_t)r0 * DD + col] = o0;
                    *(float2*)&C[(size_t)(r0 + 8) * DD + col] = o1;
                } else {
                    __nv_bfloat16 h0, l0, h1, l1, h2, l2, h3, l3;
                    split1(x0, h0, l0); split1(x1, h1, l1);
                    split1(x2, h2, l2); split1(x3, h3, l3);
                    __nv_bfloat162 hh0 = {h0, h1}, ll0 = {l0, l1};
                    __nv_bfloat162 hh1 = {h2, h3}, ll1 = {l2, l3};
                    *(__nv_bfloat162*)&oh[(size_t)r0 * DD + col] = hh0;
                    *(__nv_bfloat162*)&ol[(size_t)r0 * DD + col] = ll0;
                    *(__nv_bfloat162*)&oh[(size_t)(r0 + 8) * DD + col] = hh1;
                    *(__nv_bfloat162*)&ol[(size_t)(r0 + 8) * DD + col] = ll1;
                }
            }
        }
    }
}

// ---------------- pad-mask + split ----------------------------------------------
__global__ void mask_split_kernel(const float* __restrict__ x, const int* __restrict__ lengths,
                                  float* __restrict__ xm,
                                  __nv_bfloat16* __restrict__ xh, __nv_bfloat16* __restrict__ xl)
{
    int i = blockIdx.x * blockDim.x + threadIdx.x;
    if (i >= (MM*DD)/4) return;
    int row = (i * 4) / DD;
    int s = row & (SS - 1);
    int b = row >> 11;
    float4 val = ((const float4*)x)[i];
    if (s >= lengths[b]) val = make_float4(0.f, 0.f, 0.f, 0.f);
    ((float4*)xm)[i] = val;
    __nv_bfloat16 h0, l0, h1, l1, h2, l2, h3, l3;
    split1(val.x, h0, l0); split1(val.y, h1, l1);
    split1(val.z, h2, l2); split1(val.w, h3, l3);
    __nv_bfloat162* ph = (__nv_bfloat162*)&xh[i * 4];
    __nv_bfloat162* pl = (__nv_bfloat162*)&xl[i * 4];
    ph[0] = {h0, h1}; ph[1] = {h2, h3};
    pl[0] = {l0, l1}; pl[1] = {l2, l3};
}

// ---------------- attention diagonal via HMMA (flash-style, diag only) ----------
// grid (S/64, H, B) reversed-x, 128 threads (4 warps x 16 query rows)
#define SMEM_ATTN 49152
__global__ __launch_bounds__(128, 1)
void attn_diag_hmma(const __nv_bfloat16* __restrict__ qh, const __nv_bfloat16* __restrict__ ql,
                    const __nv_bfloat16* __restrict__ kh, const __nv_bfloat16* __restrict__ kl,
                    const int* __restrict__ lengths, float* __restrict__ diag)
{
    extern __shared__ char sm[];
    uint32_t sb = smem_u32(sm);
    int bx = (int)gridDim.x - 1 - (int)blockIdx.x;
    int h = blockIdx.y, b = blockIdx.z;
    int tid = threadIdx.x, lane = tid & 31, w = tid >> 5;
    int i0 = bx * 64;
    int len = lengths[b];

    // fully padded query tile: diag = 0, no work
    if (i0 >= len) {
        if (tid < 64) diag[(size_t)(b * HH + h) * SS + i0 + tid] = 0.f;
        return;
    }

    const size_t qg = ((size_t)(b * SS + i0)) * DD + h * DK;
#pragma unroll
    for (int i = 0; i < 4; i++) {
        int idx = i * 128 + tid;
        int row = idx >> 3, c = idx & 7;
        cpa16(sb + row * 128 + ((c ^ (row & 7)) << 4), qh + qg + (size_t)row * DD + c * 8);
    }
#pragma unroll
    for (int i = 0; i < 4; i++) {
        int idx = i * 128 + tid;
        int row = idx >> 3, c = idx & 7;
        cpa16(sb + 8192 + row * 128 + ((c ^ (row & 7)) << 4), ql + qg + (size_t)row * DD + c * 8);
    }
    auto issueK = [&](int t, int buf) {
        uint32_t kb = sb + 16384 + buf * 16384;
        size_t g = ((size_t)(b * SS + t * 64)) * DD + h * DK;
#pragma unroll
        for (int i = 0; i < 4; i++) {
            int idx = i * 128 + tid;
            int row = idx >> 3, c = idx & 7;
            cpa16(kb + row * 128 + ((c ^ (row & 7)) << 4), kh + g + (size_t)row * DD + c * 8);
        }
#pragma unroll
        for (int i = 0; i < 4; i++) {
            int idx = i * 128 + tid;
            int row = idx >> 3, c = idx & 7;
            cpa16(kb + 8192 + row * 128 + ((c ^ (row & 7)) << 4), kl + g + (size_t)row * DD + c * 8);
        }
    };
    issueK(0, 0);
    asm volatile("cp.async.commit_group;");
    if (bx >= 1) { issueK(1, 1); asm volatile("cp.async.commit_group;"); }

    int arow = (lane & 7) + ((lane >> 3) & 1) * 8;
    int asel = lane >> 4;
    int brow = (lane & 7) + (lane >> 4) * 8;
    int bsel = (lane >> 3) & 1;
    int g_ = lane >> 2, tig = lane & 3;

    uint32_t Qh[16], Ql[16];
    float m[2] = {-1e30f, -1e30f}, l[2] = {0.f, 0.f}, sd[2] = {-1e30f, -1e30f};

    for (int t = 0; t <= bx; t++) {
        if (t < bx) asm volatile("cp.async.wait_group 1;");
        else        asm volatile("cp.async.wait_group 0;");
        __syncthreads();
        if (t == 0) {
            int r = w * 16 + arow;
#pragma unroll
            for (int kc = 0; kc < 4; kc++) {
                ldsm4(&Qh[kc * 4], sb + r * 128 + (((2 * kc + asel) ^ (r & 7)) << 4));
                ldsm4(&Ql[kc * 4], sb + 8192 + r * 128 + (((2 * kc + asel) ^ (r & 7)) << 4));
            }
        }
        uint32_t kb = sb + 16384 + (t & 1) * 16384;
        float acc[8][4];
#pragma unroll
        for (int nt = 0; nt < 8; nt++)
#pragma unroll
            for (int r = 0; r < 4; r++) acc[nt][r] = 0.f;

#pragma unroll
        for (int kc = 0; kc < 4; kc++) {
            uint32_t Bh[16], Bl[16];
#pragma unroll
            for (int nt2 = 0; nt2 < 4; nt2++) {
                int rr = nt2 * 16 + brow;
                ldsm4(&Bh[nt2 * 4], kb + rr * 128 + (((2 * kc + bsel) ^ (rr & 7)) << 4));
                ldsm4(&Bl[nt2 * 4], kb + 8192 + rr * 128 + (((2 * kc + bsel) ^ (rr & 7)) << 4));
            }
#pragma unroll
            for (int nt = 0; nt < 8; nt++)
                mma_bf16(acc[nt], &Qh[kc * 4], &Bh[(nt >> 1) * 4 + (nt & 1) * 2]);
#pragma unroll
            for (int nt = 0; nt < 8; nt++)
                mma_bf16(acc[nt], &Qh[kc * 4], &Bl[(nt >> 1) * 4 + (nt & 1) * 2]);
#pragma unroll
            for (int nt = 0; nt < 8; nt++)
                mma_bf16(acc[nt], &Ql[kc * 4], &Bh[(nt >> 1) * 4 + (nt & 1) * 2]);
        }

        bool dtile = (t == bx);
#pragma unroll
        for (int r = 0; r < 2; r++) {
            int il = w * 16 + g_ + r * 8;
            float tm = -1e30f;
            float vals[16];
#pragma unroll
            for (int nt = 0; nt < 8; nt++)
#pragma unroll
                for (int c = 0; c < 2; c++) {
                    float v = acc[nt][r * 2 + c];
                    if (dtile) {
                        int jl = nt * 8 + tig * 2 + c;
                        if (jl == il) sd[r] = v;
                        if (jl > il) v = -1e30f;
                    }
                    vals[nt * 2 + c] = v;
                    tm = fmaxf(tm, v);
                }
            float mn = fmaxf(m[r], tm);
            float sc = exp2f((m[r] - mn) * L2E);
            float ls = 0.f;
#pragma unroll
            for (int i = 0; i < 16; i++) ls += exp2f((vals[i] - mn) * L2E);
            l[r] = l[r] * sc + ls;
            m[r] = mn;
        }
        __syncthreads();
        if (t + 2 <= bx) { issueK(t + 2, t & 1); asm volatile("cp.async.commit_group;"); }
    }

    // cross-lane combine within the 4 lanes sharing each row
#pragma unroll
    for (int r = 0; r < 2; r++) {
        float mm = m[r], ll = l[r], ss = sd[r];
#pragma unroll
        for (int o = 1; o <= 2; o <<= 1) {
            float mo = __shfl_xor_sync(0xffffffffu, mm, o);
            float lo = __shfl_xor_sync(0xffffffffu, ll, o);
            float so = __shfl_xor_sync(0xffffffffu, ss, o);
            float mn = fmaxf(mm, mo);
            ll = ll * exp2f((mm - mn) * L2E) + lo * exp2f((mo - mn) * L2E);
            mm = mn;
            ss = fmaxf(ss, so);
        }
        if (tig == 0) {
            int ig = i0 + w * 16 + g_ + r * 8;
            float dv = (ig < len) ? exp2f((ss - mm) * L2E) / ll : 0.f;
            diag[(size_t)(b * HH + h) * SS + ig] = dv;
        }
    }
}

// ---------------- wv = diag * v  (-> bf16 hi/lo planes) -------------------------
__global__ void wv_split_kernel(const float* __restrict__ V, const float* __restrict__ diag,
                                __nv_bfloat16* __restrict__ wh, __nv_bfloat16* __restrict__ wl)
{
    int i = blockIdx.x * blockDim.x + threadIdx.x;
    if (i >= (MM*DD)/4) return;
    int e = i * 4;
    int row = e / DD;
    int c = e & (DD - 1);
    int b = row >> 11;
    int s = row & (SS - 1);
    int h = c >> 6;
    float dv = diag[(size_t)(b * HH + h) * SS + s];
    float4 v4 = ((const float4*)V)[i];
    v4.x *= dv; v4.y *= dv; v4.z *= dv; v4.w *= dv;
    __nv_bfloat16 h0, l0, h1, l1, h2, l2, h3, l3;
    split1(v4.x, h0, l0); split1(v4.y, h1, l1);
    split1(v4.z, h2, l2); split1(v4.w, h3, l3);
    __nv_bfloat162* ph = (__nv_bfloat162*)&wh[e];
    __nv_bfloat162* pl = (__nv_bfloat162*)&wl[e];
    ph[0] = {h0, h1}; ph[1] = {h2, h3};
    pl[0] = {l0, l1}; pl[1] = {l2, l3};
}

// ---------------- LayerNorm(a + r)  (optionally also bf16 split out) ------------
template<bool SPLIT>
__global__ __launch_bounds__(256)
void ln_kernel(const float* __restrict__ a, const float* __restrict__ r,
               const float* __restrict__ gamma, const float* __restrict__ beta,
               float* __restrict__ out,
               __nv_bfloat16* __restrict__ oh, __nv_bfloat16* __restrict__ ol)
{
    int row = blockIdx.x;
    int tid = threadIdx.x;
    const float* pa = a + (size_t)row * DD;
    const float* pr = r + (size_t)row * DD;

    float v0 = pa[tid] + pr[tid];
    float v1 = pa[tid + 256] + pr[tid + 256];

    __shared__ float sred[8];
    __shared__ float smean, srstd;

    float s = v0 + v1;
#pragma unroll
    for (int o = 16; o > 0; o >>= 1) s += __shfl_xor_sync(0xffffffffu, s, o);
    if ((tid & 31) == 0) sred[tid >> 5] = s;
    __syncthreads();
    if (tid == 0) {
        float t = 0.f;
#pragma unroll
        for (int i = 0; i < 8; i++) t += sred[i];
        smean = t * (1.0f / DD);
    }
    __syncthreads();
    float mean = smean;
    float d0 = v0 - mean, d1 = v1 - mean;
    float vs = d0 * d0 + d1 * d1;
#pragma unroll
    for (int o = 16; o > 0; o >>= 1) vs += __shfl_xor_sync(0xffffffffu, vs, o);
    if ((tid & 31) == 0) sred[tid >> 5] = vs;
    __syncthreads();
    if (tid == 0) {
        float t = 0.f;
#pragma unroll
        for (int i = 0; i < 8; i++) t += sred[i];
        srstd = rsqrtf(t * (1.0f / DD) + 1e-3f);
    }
    __syncthreads();
    float rstd = srstd;
    float o0 = gamma[tid]       * (d0 * rstd) + beta[tid];
    float o1 = gamma[tid + 256] * (d1 * rstd) + beta[tid + 256];
    out[(size_t)row * DD + tid]       = o0;
    out[(size_t)row * DD + tid + 256] = o1;
    if (SPLIT) {
        __nv_bfloat16 h0, l0, h1, l1;
        split1(o0, h0, l0);
        split1(o1, h1, l1);
        oh[(size_t)row * DD + tid]       = h0;
        ol[(size_t)row * DD + tid]       = l0;
        oh[(size_t)row * DD + tid + 256] = h1;
        ol[(size_t)row * DD + tid + 256] = l1;
    }
}

// ---------------- launch --------------------------------------------------------
extern "C" void kernel_launch(void* const* d_in, const int* in_sizes, int n_in,
                              void* d_out, int out_size)
{
    const float* x       = (const float*)d_in[0];
    const int*   lengths = (const int*)d_in[1];
    const float* Wq = (const float*)d_in[2];
    const float* bq = (const float*)d_in[3];
    const float* Wk = (const float*)d_in[4];
    const float* bk = (const float*)d_in[5];
    const float* Wv = (const float*)d_in[6];
    const float* bv = (const float*)d_in[7];
    const float* Wo = (const float*)d_in[8];
    const float* bo = (const float*)d_in[9];
    const float* W1 = (const float*)d_in[10];
    const float* b1 = (const float*)d_in[11];
    const float* W2 = (const float*)d_in[12];
    const float* b2 = (const float*)d_in[13];
    const float* gamma1 = (const float*)d_in[14];
    const float* beta1  = (const float*)d_in[15];
    const float* gamma2 = (const float*)d_in[16];
    const float* beta2  = (const float*)d_in[17];

    float *xm, *v, *ao, *y1, *f2, *diag, *bqkv;
    __nv_bfloat16 *xh, *xl, *qh, *ql, *kh, *kl, *wvh, *wvl, *y1h, *y1l, *h1h, *h1l;
    __nv_bfloat16 *wqkvth, *wqkvtl, *woth, *wotl, *w1th, *w1tl, *w2th, *w2tl;
    cudaGetSymbolAddress((void**)&xm,   g_xm);
    cudaGetSymbolAddress((void**)&v,    g_v);
    cudaGetSymbolAddress((void**)&ao,   g_ao);
    cudaGetSymbolAddress((void**)&y1,   g_y1);
    cudaGetSymbolAddress((void**)&f2,   g_f2);
    cudaGetSymbolAddress((void**)&diag, g_diag);
    cudaGetSymbolAddress((void**)&bqkv, g_bqkv);
    cudaGetSymbolAddress((void**)&xh,   g_xh);
    cudaGetSymbolAddress((void**)&xl,   g_xl);
    cudaGetSymbolAddress((void**)&qh,   g_qh);
    cudaGetSymbolAddress((void**)&ql,   g_ql);
    cudaGetSymbolAddress((void**)&kh,   g_kh);
    cudaGetSymbolAddress((void**)&kl,   g_kl);
    cudaGetSymbolAddress((void**)&wvh,  g_wvh);
    cudaGetSymbolAddress((void**)&wvl,  g_wvl);
    cudaGetSymbolAddress((void**)&y1h,  g_y1h);
    cudaGetSymbolAddress((void**)&y1l,  g_y1l);
    cudaGetSymbolAddress((void**)&h1h,  g_h1h);
    cudaGetSymbolAddress((void**)&h1l,  g_h1l);
    cudaGetSymbolAddress((void**)&wqkvth, g_wqkvth);
    cudaGetSymbolAddress((void**)&wqkvtl, g_wqkvtl);
    cudaGetSymbolAddress((void**)&woth, g_woth);
    cudaGetSymbolAddress((void**)&wotl, g_wotl);
    cudaGetSymbolAddress((void**)&w1th, g_w1th);
    cudaGetSymbolAddress((void**)&w1tl, g_w1tl);
    cudaGetSymbolAddress((void**)&w2th, g_w2th);
    cudaGetSymbolAddress((void**)&w2tl, g_w2tl);

    cudaFuncSetAttribute(hgemm<0>, cudaFuncAttributeMaxDynamicSharedMemorySize, SMEM_HGEMM);
    cudaFuncSetAttribute(hgemm<1>, cudaFuncAttributeMaxDynamicSharedMemorySize, SMEM_HGEMM);
    cudaFuncSetAttribute(hgemm<3>, cudaFuncAttributeMaxDynamicSharedMemorySize, SMEM_HGEMM);
    cudaFuncSetAttribute(attn_diag_hmma, cudaFuncAttributeMaxDynamicSharedMemorySize, SMEM_ATTN);

    int n4 = (MM * DD) / 4;
    mask_split_kernel<<<(n4 + 255) / 256, 256>>>(x, lengths, xm, xh, xl);

    dim3 tb(32, 8);
    transpose_split4_kernel<<<dim3(DD/32, DD/32, 4), tb>>>(
        Wq, Wk, Wv, Wo,
        wqkvth, wqkvtl,
        wqkvth + DD*DD, wqkvtl + DD*DD,
        wqkvth + 2*DD*DD, wqkvtl + 2*DD*DD,
        woth, wotl);
    transpose_split_kernel<<<dim3(FFD/32, DD/32), tb>>>(W1, w1th, w1tl, DD, FFD);
    transpose_split_kernel<<<dim3(DD/32, FFD/32), tb>>>(W2, w2th, w2tl, FFD, DD);
    concat_bias_kernel<<<6, 256>>>(bq, bk, bv, bqkv);

    dim3 g512(DD / 128, MM / 128);       // (4, 32)
    dim3 gQKV(3 * DD / 128, MM / 128);   // (12, 32)
    dim3 gFF (FFD / 128, MM / 128);      // (16, 32)

    // fused QKV: q,k -> bf16 planes; v -> fp32; padded tiles short-circuit to bias
    hgemm<3><<<gQKV, 256, SMEM_HGEMM>>>(xh, xl, wqkvth, wqkvtl, bqkv,
                                        v, qh, ql, kh, kl, lengths, 1, MM, 3 * DD, DD, DD);

    attn_diag_hmma<<<dim3(SS / 64, HH, BB), 128, SMEM_ATTN>>>(qh, ql, kh, kl, lengths, diag);

    wv_split_kernel<<<(n4 + 255) / 256, 256>>>(v, diag, wvh, wvl);

    hgemm<0><<<g512, 256, SMEM_HGEMM>>>(wvh, wvl, woth, wotl, bo,
                                        ao, nullptr, nullptr, nullptr, nullptr, lengths, 1, MM, DD, DD, DD);

    ln_kernel<true><<<MM, 256>>>(xm, ao, gamma1, beta1, y1, y1h, y1l);

    hgemm<1><<<gFF, 256, SMEM_HGEMM>>>(y1h, y1l, w1th, w1tl, b1,
                                       nullptr, h1h, h1l, nullptr, nullptr, lengths, 2, MM, FFD, DD, FFD);
    hgemm<0><<<g512, 256, SMEM_HGEMM>>>(h1h, h1l, w2th, w2tl, b2,
                                        f2, nullptr, nullptr, nullptr, nullptr, lengths, 2, MM, DD, FFD, DD);

    ln_kernel<false><<<MM, 256>>>(y1, f2, gamma2, beta2, (float*)d_out, nullptr, nullptr);
}

// round 11
// speedup vs baseline: 3.2858x; 1.0063x over previous
#include <cuda_runtime.h>
#include <cuda_bf16.h>
#include <math.h>
#include <stdint.h>

#define BB 2
#define SS 2048
#define DD 512
#define HH 8
#define DK 64
#define FFD 2048
#define MM (BB*SS)          // 4096 rows
#define L2E 1.4426950408889634f

// ---------------- scratch (static device arrays; no runtime alloc) -------------
__device__ float g_ao[MM*DD];
__device__ float g_y1[MM*DD];
__device__ float g_f2[MM*DD];
__device__ float g_bqkv[3*DD];
// bf16 hi/lo planes
__device__ __nv_bfloat16 g_xh [MM*DD],  g_xl [MM*DD];
__device__ __nv_bfloat16 g_qh [MM*DD],  g_ql [MM*DD];
__device__ __nv_bfloat16 g_kh [MM*DD],  g_kl [MM*DD];
__device__ __nv_bfloat16 g_wvh[MM*DD],  g_wvl[MM*DD];   // v planes, scaled in place by attn
__device__ __nv_bfloat16 g_y1h[MM*DD],  g_y1l[MM*DD];
__device__ __nv_bfloat16 g_h1h[MM*FFD], g_h1l[MM*FFD];
// transposed weights [N, K] bf16 hi/lo
__device__ __nv_bfloat16 g_wqkvth[3*DD*DD], g_wqkvtl[3*DD*DD];
__device__ __nv_bfloat16 g_woth[DD*DD], g_wotl[DD*DD];
__device__ __nv_bfloat16 g_w1th[FFD*DD], g_w1tl[FFD*DD];
__device__ __nv_bfloat16 g_w2th[DD*FFD], g_w2tl[DD*FFD];

// ---------------- PTX helpers ---------------------------------------------------
__device__ __forceinline__ uint32_t smem_u32(const void* p) {
    uint32_t a;
    asm("{ .reg .u64 t; cvta.to.shared.u64 t, %1; cvt.u32.u64 %0, t; }" : "=r"(a) : "l"(p));
    return a;
}
__device__ __forceinline__ void mma_bf16(float* c, const uint32_t* a, const uint32_t* b) {
    asm volatile(
        "mma.sync.aligned.m16n8k16.row.col.f32.bf16.bf16.f32 "
        "{%0,%1,%2,%3},{%4,%5,%6,%7},{%8,%9},{%0,%1,%2,%3};"
        : "+f"(c[0]), "+f"(c[1]), "+f"(c[2]), "+f"(c[3])
        : "r"(a[0]), "r"(a[1]), "r"(a[2]), "r"(a[3]), "r"(b[0]), "r"(b[1]));
}
__device__ __forceinline__ void ldsm4(uint32_t* r, uint32_t addr) {
    asm volatile("ldmatrix.sync.aligned.m8n8.x4.shared.b16 {%0,%1,%2,%3},[%4];"
                 : "=r"(r[0]), "=r"(r[1]), "=r"(r[2]), "=r"(r[3]) : "r"(addr));
}
__device__ __forceinline__ void cpa16(uint32_t dst, const void* src) {
    asm volatile("cp.async.cg.shared.global [%0],[%1],16;" :: "r"(dst), "l"(src));
}
__device__ __forceinline__ void split1(float a, __nv_bfloat16& h, __nv_bfloat16& l) {
    h = __float2bfloat16(a);
    l = __float2bfloat16(a - __bfloat162float(h));
}

// ---------------- weight transpose+split: oh/ol[C][R] = split(in[R][C]) --------
__global__ __launch_bounds__(256)
void transpose_split_kernel(const float* __restrict__ in,
                            __nv_bfloat16* __restrict__ oh, __nv_bfloat16* __restrict__ ol,
                            int R, int C)
{
    __shared__ float t[32][33];
    int bx = blockIdx.x * 32, by = blockIdx.y * 32;
    int tx = threadIdx.x, ty = threadIdx.y;   // (32, 8)
#pragma unroll
    for (int i = 0; i < 32; i += 8)
        t[ty + i][tx] = in[(size_t)(by + ty + i) * C + bx + tx];
    __syncthreads();
#pragma unroll
    for (int i = 0; i < 32; i += 8) {
        float v = t[tx][ty + i];
        __nv_bfloat16 h, l;
        split1(v, h, l);
        size_t o = (size_t)(bx + ty + i) * R + by + tx;
        oh[o] = h; ol[o] = l;
    }
}

// batched version: 4 square DxD transposes in one launch (z selects matrix)
__global__ __launch_bounds__(256)
void transpose_split4_kernel(const float* __restrict__ i0, const float* __restrict__ i1,
                             const float* __restrict__ i2, const float* __restrict__ i3,
                             __nv_bfloat16* __restrict__ h0, __nv_bfloat16* __restrict__ l0,
                             __nv_bfloat16* __restrict__ h1, __nv_bfloat16* __restrict__ l1,
                             __nv_bfloat16* __restrict__ h2, __nv_bfloat16* __restrict__ l2,
                             __nv_bfloat16* __restrict__ h3, __nv_bfloat16* __restrict__ l3)
{
    int z = blockIdx.z;
    const float* in = (z == 0) ? i0 : (z == 1) ? i1 : (z == 2) ? i2 : i3;
    __nv_bfloat16* oh = (z == 0) ? h0 : (z == 1) ? h1 : (z == 2) ? h2 : h3;
    __nv_bfloat16* ol = (z == 0) ? l0 : (z == 1) ? l1 : (z == 2) ? l2 : l3;
    __shared__ float t[32][33];
    int bx = blockIdx.x * 32, by = blockIdx.y * 32;
    int tx = threadIdx.x, ty = threadIdx.y;
#pragma unroll
    for (int i = 0; i < 32; i += 8)
        t[ty + i][tx] = in[(size_t)(by + ty + i) * DD + bx + tx];
    __syncthreads();
#pragma unroll
    for (int i = 0; i < 32; i += 8) {
        float v = t[tx][ty + i];
        __nv_bfloat16 h, l;
        split1(v, h, l);
        size_t o = (size_t)(bx + ty + i) * DD + by + tx;
        oh[o] = h; ol[o] = l;
    }
}

__global__ void concat_bias_kernel(const float* __restrict__ a, const float* __restrict__ b,
                                   const float* __restrict__ c, float* __restrict__ o)
{
    int i = blockIdx.x * blockDim.x + threadIdx.x;
    if (i >= 3 * DD) return;
    o[i] = (i < DD) ? a[i] : (i < 2 * DD) ? b[i - DD] : c[i - 2 * DD];
}

// ---------------- HMMA bf16 3-pass GEMM ------------------------------------------
// C[M,N] = (Ah+Al)[M,K] @ (Bh+Bl)[N,K]^T + bias   (drops Al*Bl term)
// MODE 0: fp32 out  MODE 1: relu + bf16 split out  MODE 3: qkv -> all bf16 planes
// skipmode 0: none  1: padded tile -> C=bias  2: padded tile -> 16-row compute + bcast
#define STAGE_BYTES 32768
#define SMEM_HGEMM (3 * STAGE_BYTES)

template<int MTN, bool RED>
__device__ __forceinline__ void gemm_tiles(uint32_t base, int arow, int asel,
                                           int brow, int bsel, int rx, int wm, int wn,
                                           float acc[4][4][4])
{
#pragma unroll
    for (int s = 0; s < 2; s++) {
        uint32_t Ahf[16], Alf[16], Bhf[8], Blf[8];
#pragma unroll
        for (int mt = 0; mt < MTN; mt++) {
            uint32_t ro = base + ((RED ? 0 : wm * 64 + mt * 16) + arow) * 128;
            ldsm4(&Ahf[mt * 4], ro + (((2 * s + asel) ^ rx) << 4));
            ldsm4(&Alf[mt * 4], ro + (((4 + 2 * s + asel) ^ rx) << 4));
        }
#pragma unroll
        for (int nt2 = 0; nt2 < 2; nt2++) {
            uint32_t ro = base + 16384 + (wn * 32 + nt2 * 16 + brow) * 128;
            ldsm4(&Bhf[nt2 * 4], ro + (((2 * s + bsel) ^ rx) << 4));
            ldsm4(&Blf[nt2 * 4], ro + (((4 + 2 * s + bsel) ^ rx) << 4));
        }
#pragma unroll
        for (int mt = 0; mt < MTN; mt++)
#pragma unroll
            for (int nt = 0; nt < 4; nt++)
                mma_bf16(acc[mt][nt], &Ahf[mt * 4], &Bhf[nt * 2]);
#pragma unroll
        for (int mt = 0; mt < MTN; mt++)
#pragma unroll
            for (int nt = 0; nt < 4; nt++)
                mma_bf16(acc[mt][nt], &Ahf[mt * 4], &Blf[nt * 2]);
#pragma unroll
        for (int mt = 0; mt < MTN; mt++)
#pragma unroll
            for (int nt = 0; nt < 4; nt++)
                mma_bf16(acc[mt][nt], &Alf[mt * 4], &Bhf[nt * 2]);
    }
}

template<int MODE>
__global__ __launch_bounds__(256, 1)
void hgemm(const __nv_bfloat16* __restrict__ Ah, const __nv_bfloat16* __restrict__ Al,
           const __nv_bfloat16* __restrict__ Bh, const __nv_bfloat16* __restrict__ Bl,
           const float* __restrict__ bias,
           float* __restrict__ C, __nv_bfloat16* __restrict__ Ch, __nv_bfloat16* __restrict__ Cl,
           __nv_bfloat16* __restrict__ Dh, __nv_bfloat16* __restrict__ Dl,
           __nv_bfloat16* __restrict__ Eh, __nv_bfloat16* __restrict__ El,
           const int* __restrict__ lengths, int skipmode,
           int M, int N, int K, int OD)
{
    extern __shared__ char smem[];
    uint32_t sb = smem_u32(smem);
    int tid = threadIdx.x, lane = tid & 31, wid = tid >> 5;
    int bm = blockIdx.y * 128, bn = blockIdx.x * 128;
    int wm = wid & 1, wn = wid >> 1;
    int NK = K >> 5;

    bool padded = false;
    if (skipmode) {
        int b = bm >> 11;
        int s0 = bm & (SS - 1);
        padded = (s0 >= lengths[b]);
    }
    bool skipall = (skipmode == 1) && padded;
    bool reduced = (skipmode == 2) && padded;

    float acc[4][4][4];
#pragma unroll
    for (int i = 0; i < 4; i++)
#pragma unroll
        for (int j = 0; j < 4; j++)
#pragma unroll
            for (int r = 0; r < 4; r++) acc[i][j][r] = 0.f;

    int arow = (lane & 7) + ((lane >> 3) & 1) * 8;
    int asel = lane >> 4;
    int brow = (lane & 7) + (lane >> 4) * 8;
    int bsel = (lane >> 3) & 1;
    int rx = lane & 7;

    if (!skipall) {
        auto issue = [&](int kt) {
            uint32_t base = sb + (kt % 3) * STAGE_BYTES;
            int k0 = kt << 5;
            if (reduced) {
                // only 16 A rows needed (all padded rows identical)
                if (tid < 128) {
                    int row = tid >> 3, col = tid & 7;
                    const __nv_bfloat16* src =
                        (col < 4 ? Ah : Al) + (size_t)(bm + row) * K + k0 + (col & 3) * 8;
                    cpa16(base + row * 128 + ((col ^ (row & 7)) << 4), src);
                }
            } else {
#pragma unroll
                for (int i = 0; i < 4; i++) {
                    int ch = i * 256 + tid;
                    int row = ch >> 3, col = ch & 7;
                    const __nv_bfloat16* src =
                        (col < 4 ? Ah : Al) + (size_t)(bm + row) * K + k0 + (col & 3) * 8;
                    cpa16(base + row * 128 + ((col ^ (row & 7)) << 4), src);
                }
            }
#pragma unroll
            for (int i = 0; i < 4; i++) {
                int ch = i * 256 + tid;
                int row = ch >> 3, col = ch & 7;
                const __nv_bfloat16* src =
                    (col < 4 ? Bh : Bl) + (size_t)(bn + row) * K + k0 + (col & 3) * 8;
                cpa16(base + 16384 + row * 128 + ((col ^ (row & 7)) << 4), src);
            }
            asm volatile("cp.async.commit_group;");
        };

        issue(0); issue(1); issue(2);

        if (reduced) {
            for (int kt = 0; kt < NK; kt++) {
                asm volatile("cp.async.wait_group %0;" :: "n"(2));
                __syncthreads();
                gemm_tiles<1, true>(sb + (kt % 3) * STAGE_BYTES, arow, asel, brow, bsel, rx, wm, wn, acc);
                __syncthreads();
                if (kt + 3 < NK) issue(kt + 3);
            }
#pragma unroll
            for (int mt = 1; mt < 4; mt++)
#pragma unroll
                for (int nt = 0; nt < 4; nt++)
#pragma unroll
                    for (int r = 0; r < 4; r++) acc[mt][nt][r] = acc[0][nt][r];
        } else {
            for (int kt = 0; kt < NK; kt++) {
                asm volatile("cp.async.wait_group %0;" :: "n"(2));
                __syncthreads();
                gemm_tiles<4, false>(sb + (kt % 3) * STAGE_BYTES, arow, asel, brow, bsel, rx, wm, wn, acc);
                __syncthreads();
                if (kt + 3 < NK) issue(kt + 3);
            }
        }
    }

    // epilogue
    int g = lane >> 2, tig = lane & 3;
    __nv_bfloat16 *oh = Ch, *ol = Cl;
    if (MODE == 3) {
        int seg = bn >> 9;              // 0: q, 1: k, 2: v
        if (seg == 1) { oh = Dh; ol = Dl; }
        if (seg == 2) { oh = Eh; ol = El; }
    }
#pragma unroll
    for (int mt = 0; mt < 4; mt++) {
#pragma unroll
        for (int nt = 0; nt < 4; nt++) {
            int colg = bn + wn * 32 + nt * 8 + tig * 2;
            float2 bv = *(const float2*)&bias[colg];
            int r0 = bm + wm * 64 + mt * 16 + g;
            float x0 = acc[mt][nt][0] + bv.x, x1 = acc[mt][nt][1] + bv.y;
            float x2 = acc[mt][nt][2] + bv.x, x3 = acc[mt][nt][3] + bv.y;
            if (MODE == 0) {
                float2 o0 = {x0, x1}, o1 = {x2, x3};
                *(float2*)&C[(size_t)r0 * OD + colg] = o0;
                *(float2*)&C[(size_t)(r0 + 8) * OD + colg] = o1;
            } else {
                if (MODE == 1) {
                    x0 = fmaxf(x0, 0.f); x1 = fmaxf(x1, 0.f);
                    x2 = fmaxf(x2, 0.f); x3 = fmaxf(x3, 0.f);
                }
                int col = (MODE == 3) ? (colg & 511) : colg;
                __nv_bfloat16 h0, l0, h1, l1, h2, l2, h3, l3;
                split1(x0, h0, l0); split1(x1, h1, l1);
                split1(x2, h2, l2); split1(x3, h3, l3);
                __nv_bfloat162 hh0 = {h0, h1}, ll0 = {l0, l1};
                __nv_bfloat162 hh1 = {h2, h3}, ll1 = {l2, l3};
                *(__nv_bfloat162*)&oh[(size_t)r0 * OD + col] = hh0;
                *(__nv_bfloat162*)&ol[(size_t)r0 * OD + col] = ll0;
                *(__nv_bfloat162*)&oh[(size_t)(r0 + 8) * OD + col] = hh1;
                *(__nv_bfloat162*)&ol[(size_t)(r0 + 8) * OD + col] = ll1;
            }
        }
    }
}

// ---------------- pad-mask + split (planes only) --------------------------------
__global__ void mask_split_kernel(const float* __restrict__ x, const int* __restrict__ lengths,
                                  __nv_bfloat16* __restrict__ xh, __nv_bfloat16* __restrict__ xl)
{
    int i = blockIdx.x * blockDim.x + threadIdx.x;
    if (i >= (MM*DD)/4) return;
    int row = (i * 4) / DD;
    int s = row & (SS - 1);
    int b = row >> 11;
    float4 val = ((const float4*)x)[i];
    if (s >= lengths[b]) val = make_float4(0.f, 0.f, 0.f, 0.f);
    __nv_bfloat16 h0, l0, h1, l1, h2, l2, h3, l3;
    split1(val.x, h0, l0); split1(val.y, h1, l1);
    split1(val.z, h2, l2); split1(val.w, h3, l3);
    __nv_bfloat162* ph = (__nv_bfloat162*)&xh[i * 4];
    __nv_bfloat162* pl = (__nv_bfloat162*)&xl[i * 4];
    ph[0] = {h0, h1}; ph[1] = {h2, h3};
    pl[0] = {l0, l1}; pl[1] = {l2, l3};
}

// ---------------- attention diag via HMMA + fused wv = diag*v (in place) --------
// grid (S/64, H, B) reversed-x, 128 threads (4 warps x 16 query rows)
#define SMEM_ATTN 49152
__global__ __launch_bounds__(128, 1)
void attn_diag_hmma(const __nv_bfloat16* __restrict__ qh, const __nv_bfloat16* __restrict__ ql,
                    const __nv_bfloat16* __restrict__ kh, const __nv_bfloat16* __restrict__ kl,
                    __nv_bfloat16* vh, __nv_bfloat16* vl,
                    const int* __restrict__ lengths)
{
    extern __shared__ char sm[];
    uint32_t sb = smem_u32(sm);
    float* sdiag = (float*)sm;
    int bx = (int)gridDim.x - 1 - (int)blockIdx.x;
    int h = blockIdx.y, b = blockIdx.z;
    int tid = threadIdx.x, lane = tid & 31, w = tid >> 5;
    int i0 = bx * 64;
    int len = lengths[b];
    const size_t vbase = ((size_t)(b * SS + i0)) * DD + h * DK;

    // fully padded query tile: wv slice = 0, no attention work
    if (i0 >= len) {
        uint4 z = make_uint4(0, 0, 0, 0);
#pragma unroll
        for (int it = 0; it < 4; it++) {
            int idx = it * 128 + tid;
            int row = idx >> 3, c8 = (idx & 7) * 8;
            *(uint4*)&vh[vbase + (size_t)row * DD + c8] = z;
            *(uint4*)&vl[vbase + (size_t)row * DD + c8] = z;
        }
        return;
    }

    const size_t qg = vbase;
#pragma unroll
    for (int i = 0; i < 4; i++) {
        int idx = i * 128 + tid;
        int row = idx >> 3, c = idx & 7;
        cpa16(sb + row * 128 + ((c ^ (row & 7)) << 4), qh + qg + (size_t)row * DD + c * 8);
    }
#pragma unroll
    for (int i = 0; i < 4; i++) {
        int idx = i * 128 + tid;
        int row = idx >> 3, c = idx & 7;
        cpa16(sb + 8192 + row * 128 + ((c ^ (row & 7)) << 4), ql + qg + (size_t)row * DD + c * 8);
    }
    auto issueK = [&](int t, int buf) {
        uint32_t kb = sb + 16384 + buf * 16384;
        size_t g = ((size_t)(b * SS + t * 64)) * DD + h * DK;
#pragma unroll
        for (int i = 0; i < 4; i++) {
            int idx = i * 128 + tid;
            int row = idx >> 3, c = idx & 7;
            cpa16(kb + row * 128 + ((c ^ (row & 7)) << 4), kh + g + (size_t)row * DD + c * 8);
        }
#pragma unroll
        for (int i = 0; i < 4; i++) {
            int idx = i * 128 + tid;
            int row = idx >> 3, c = idx & 7;
            cpa16(kb + 8192 + row * 128 + ((c ^ (row & 7)) << 4), kl + g + (size_t)row * DD + c * 8);
        }
    };
    issueK(0, 0);
    asm volatile("cp.async.commit_group;");
    if (bx >= 1) { issueK(1, 1); asm volatile("cp.async.commit_group;"); }

    int arow = (lane & 7) + ((lane >> 3) & 1) * 8;
    int asel = lane >> 4;
    int brow = (lane & 7) + (lane >> 4) * 8;
    int bsel = (lane >> 3) & 1;
    int g_ = lane >> 2, tig = lane & 3;

    uint32_t Qh[16], Ql[16];
    float m[2] = {-1e30f, -1e30f}, l[2] = {0.f, 0.f}, sd[2] = {-1e30f, -1e30f};

    for (int t = 0; t <= bx; t++) {
        if (t < bx) asm volatile("cp.async.wait_group 1;");
        else        asm volatile("cp.async.wait_group 0;");
        __syncthreads();
        if (t == 0) {
            int r = w * 16 + arow;
#pragma unroll
            for (int kc = 0; kc < 4; kc++) {
                ldsm4(&Qh[kc * 4], sb + r * 128 + (((2 * kc + asel) ^ (r & 7)) << 4));
                ldsm4(&Ql[kc * 4], sb + 8192 + r * 128 + (((2 * kc + asel) ^ (r & 7)) << 4));
            }
        }
        uint32_t kb = sb + 16384 + (t & 1) * 16384;
        float acc[8][4];
#pragma unroll
        for (int nt = 0; nt < 8; nt++)
#pragma unroll
            for (int r = 0; r < 4; r++) acc[nt][r] = 0.f;

#pragma unroll
        for (int kc = 0; kc < 4; kc++) {
            uint32_t Bh[16], Bl[16];
#pragma unroll
            for (int nt2 = 0; nt2 < 4; nt2++) {
                int rr = nt2 * 16 + brow;
                ldsm4(&Bh[nt2 * 4], kb + rr * 128 + (((2 * kc + bsel) ^ (rr & 7)) << 4));
                ldsm4(&Bl[nt2 * 4], kb + 8192 + rr * 128 + (((2 * kc + bsel) ^ (rr & 7)) << 4));
            }
#pragma unroll
            for (int nt = 0; nt < 8; nt++)
                mma_bf16(acc[nt], &Qh[kc * 4], &Bh[(nt >> 1) * 4 + (nt & 1) * 2]);
#pragma unroll
            for (int nt = 0; nt < 8; nt++)
                mma_bf16(acc[nt], &Qh[kc * 4], &Bl[(nt >> 1) * 4 + (nt & 1) * 2]);
#pragma unroll
            for (int nt = 0; nt < 8; nt++)
                mma_bf16(acc[nt], &Ql[kc * 4], &Bh[(nt >> 1) * 4 + (nt & 1) * 2]);
        }

        bool dtile = (t == bx);
#pragma unroll
        for (int r = 0; r < 2; r++) {
            int il = w * 16 + g_ + r * 8;
            float tm = -1e30f;
            float vals[16];
#pragma unroll
            for (int nt = 0; nt < 8; nt++)
#pragma unroll
                for (int c = 0; c < 2; c++) {
                    float v = acc[nt][r * 2 + c];
                    if (dtile) {
                        int jl = nt * 8 + tig * 2 + c;
                        if (jl == il) sd[r] = v;
                        if (jl > il) v = -1e30f;
                    }
                    vals[nt * 2 + c] = v;
                    tm = fmaxf(tm, v);
                }
            float mn = fmaxf(m[r], tm);
            float sc = exp2f((m[r] - mn) * L2E);
            float ls = 0.f;
#pragma unroll
            for (int i = 0; i < 16; i++) ls += exp2f((vals[i] - mn) * L2E);
            l[r] = l[r] * sc + ls;
            m[r] = mn;
        }
        __syncthreads();
        if (t + 2 <= bx) { issueK(t + 2, t & 1); asm volatile("cp.async.commit_group;"); }
    }

    // cross-lane combine within the 4 lanes sharing each row -> diag into smem
#pragma unroll
    for (int r = 0; r < 2; r++) {
        float mm = m[r], ll = l[r], ss = sd[r];
#pragma unroll
        for (int o = 1; o <= 2; o <<= 1) {
            float mo = __shfl_xor_sync(0xffffffffu, mm, o);
            float lo = __shfl_xor_sync(0xffffffffu, ll, o);
            float so = __shfl_xor_sync(0xffffffffu, ss, o);
            float mn = fmaxf(mm, mo);
            ll = ll * exp2f((mm - mn) * L2E) + lo * exp2f((mo - mn) * L2E);
            mm = mn;
            ss = fmaxf(ss, so);
        }
        if (tig == 0) {
            int rl = w * 16 + g_ + r * 8;
            float dv = (i0 + rl < len) ? exp2f((ss - mm) * L2E) / ll : 0.f;
            sdiag[rl] = dv;
        }
    }
    __syncthreads();

    // fused epilogue: wv = diag * (vh + vl), split, in place
#pragma unroll
    for (int it = 0; it < 4; it++) {
        int idx = it * 128 + tid;
        int row = idx >> 3, c8 = (idx & 7) * 8;
        size_t off = vbase + (size_t)row * DD + c8;
        uint4 hv = *(uint4*)&vh[off];
        uint4 lv = *(uint4*)&vl[off];
        float dv = sdiag[row];
        __nv_bfloat162* hp = (__nv_bfloat162*)&hv;
        __nv_bfloat162* lp = (__nv_bfloat162*)&lv;
        uint4 ho, lo;
        __nv_bfloat162* hop = (__nv_bfloat162*)&ho;
        __nv_bfloat162* lop = (__nv_bfloat162*)&lo;
#pragma unroll
        for (int j = 0; j < 4; j++) {
            float f0 = dv * (__bfloat162float(hp[j].x) + __bfloat162float(lp[j].x));
            float f1 = dv * (__bfloat162float(hp[j].y) + __bfloat162float(lp[j].y));
            __nv_bfloat16 a, bq, c, d;
            split1(f0, a, bq); split1(f1, c, d);
            hop[j] = {a, c}; lop[j] = {bq, d};
        }
        *(uint4*)&vh[off] = ho;
        *(uint4*)&vl[off] = lo;
    }
}

// ---------------- LayerNorm(a + r) -----------------------------------------------
// INP: a given as bf16 hi/lo planes; SPLIT: also emit bf16 planes of output
template<bool INP, bool SPLIT>
__global__ __launch_bounds__(256)
void ln_kernel(const __nv_bfloat16* __restrict__ ah, const __nv_bfloat16* __restrict__ al,
               const float* __restrict__ afp, const float* __restrict__ r,
               const float* __restrict__ gamma, const float* __restrict__ beta,
               float* __restrict__ out,
               __nv_bfloat16* __restrict__ oh, __nv_bfloat16* __restrict__ ol)
{
    int row = blockIdx.x;
    int tid = threadIdx.x;
    size_t base = (size_t)row * DD;

    float a0, a1;
    if (INP) {
        a0 = __bfloat162float(ah[base + tid]) + __bfloat162float(al[base + tid]);
        a1 = __bfloat162float(ah[base + tid + 256]) + __bfloat162float(al[base + tid + 256]);
    } else {
        a0 = afp[base + tid];
        a1 = afp[base + tid + 256];
    }
    float v0 = a0 + r[base + tid];
    float v1 = a1 + r[base + tid + 256];

    __shared__ float sred[8];
    __shared__ float smean, srstd;

    float s = v0 + v1;
#pragma unroll
    for (int o = 16; o > 0; o >>= 1) s += __shfl_xor_sync(0xffffffffu, s, o);
    if ((tid & 31) == 0) sred[tid >> 5] = s;
    __syncthreads();
    if (tid == 0) {
        float t = 0.f;
#pragma unroll
        for (int i = 0; i < 8; i++) t += sred[i];
        smean = t * (1.0f / DD);
    }
    __syncthreads();
    float mean = smean;
    float d0 = v0 - mean, d1 = v1 - mean;
    float vs = d0 * d0 + d1 * d1;
#pragma unroll
    for (int o = 16; o > 0; o >>= 1) vs += __shfl_xor_sync(0xffffffffu, vs, o);
    if ((tid & 31) == 0) sred[tid >> 5] = vs;
    __syncthreads();
    if (tid == 0) {
        float t = 0.f;
#pragma unroll
        for (int i = 0; i < 8; i++) t += sred[i];
        srstd = rsqrtf(t * (1.0f / DD) + 1e-3f);
    }
    __syncthreads();
    float rstd = srstd;
    float o0 = gamma[tid]       * (d0 * rstd) + beta[tid];
    float o1 = gamma[tid + 256] * (d1 * rstd) + beta[tid + 256];
    out[base + tid]       = o0;
    out[base + tid + 256] = o1;
    if (SPLIT) {
        __nv_bfloat16 h0, l0, h1, l1;
        split1(o0, h0, l0);
        split1(o1, h1, l1);
        oh[base + tid]       = h0;
        ol[base + tid]       = l0;
        oh[base + tid + 256] = h1;
        ol[base + tid + 256] = l1;
    }
}

// ---------------- launch --------------------------------------------------------
extern "C" void kernel_launch(void* const* d_in, const int* in_sizes, int n_in,
                              void* d_out, int out_size)
{
    const float* x       = (const float*)d_in[0];
    const int*   lengths = (const int*)d_in[1];
    const float* Wq = (const float*)d_in[2];
    const float* bq = (const float*)d_in[3];
    const float* Wk = (const float*)d_in[4];
    const float* bk = (const float*)d_in[5];
    const float* Wv = (const float*)d_in[6];
    const float* bv = (const float*)d_in[7];
    const float* Wo = (const float*)d_in[8];
    const float* bo = (const float*)d_in[9];
    const float* W1 = (const float*)d_in[10];
    const float* b1 = (const float*)d_in[11];
    const float* W2 = (const float*)d_in[12];
    const float* b2 = (const float*)d_in[13];
    const float* gamma1 = (const float*)d_in[14];
    const float* beta1  = (const float*)d_in[15];
    const float* gamma2 = (const float*)d_in[16];
    const float* beta2  = (const float*)d_in[17];

    float *ao, *y1, *f2, *bqkv;
    __nv_bfloat16 *xh, *xl, *qh, *ql, *kh, *kl, *wvh, *wvl, *y1h, *y1l, *h1h, *h1l;
    __nv_bfloat16 *wqkvth, *wqkvtl, *woth, *wotl, *w1th, *w1tl, *w2th, *w2tl;
    cudaGetSymbolAddress((void**)&ao,   g_ao);
    cudaGetSymbolAddress((void**)&y1,   g_y1);
    cudaGetSymbolAddress((void**)&f2,   g_f2);
    cudaGetSymbolAddress((void**)&bqkv, g_bqkv);
    cudaGetSymbolAddress((void**)&xh,   g_xh);
    cudaGetSymbolAddress((void**)&xl,   g_xl);
    cudaGetSymbolAddress((void**)&qh,   g_qh);
    cudaGetSymbolAddress((void**)&ql,   g_ql);
    cudaGetSymbolAddress((void**)&kh,   g_kh);
    cudaGetSymbolAddress((void**)&kl,   g_kl);
    cudaGetSymbolAddress((void**)&wvh,  g_wvh);
    cudaGetSymbolAddress((void**)&wvl,  g_wvl);
    cudaGetSymbolAddress((void**)&y1h,  g_y1h);
    cudaGetSymbolAddress((void**)&y1l,  g_y1l);
    cudaGetSymbolAddress((void**)&h1h,  g_h1h);
    cudaGetSymbolAddress((void**)&h1l,  g_h1l);
    cudaGetSymbolAddress((void**)&wqkvth, g_wqkvth);
    cudaGetSymbolAddress((void**)&wqkvtl, g_wqkvtl);
    cudaGetSymbolAddress((void**)&woth, g_woth);
    cudaGetSymbolAddress((void**)&wotl, g_wotl);
    cudaGetSymbolAddress((void**)&w1th, g_w1th);
    cudaGetSymbolAddress((void**)&w1tl, g_w1tl);
    cudaGetSymbolAddress((void**)&w2th, g_w2th);
    cudaGetSymbolAddress((void**)&w2tl, g_w2tl);

    cudaFuncSetAttribute(hgemm<0>, cudaFuncAttributeMaxDynamicSharedMemorySize, SMEM_HGEMM);
    cudaFuncSetAttribute(hgemm<1>, cudaFuncAttributeMaxDynamicSharedMemorySize, SMEM_HGEMM);
    cudaFuncSetAttribute(hgemm<3>, cudaFuncAttributeMaxDynamicSharedMemorySize, SMEM_HGEMM);
    cudaFuncSetAttribute(attn_diag_hmma, cudaFuncAttributeMaxDynamicSharedMemorySize, SMEM_ATTN);

    int n4 = (MM * DD) / 4;
    mask_split_kernel<<<(n4 + 255) / 256, 256>>>(x, lengths, xh, xl);

    dim3 tb(32, 8);
    transpose_split4_kernel<<<dim3(DD/32, DD/32, 4), tb>>>(
        Wq, Wk, Wv, Wo,
        wqkvth, wqkvtl,
        wqkvth + DD*DD, wqkvtl + DD*DD,
        wqkvth + 2*DD*DD, wqkvtl + 2*DD*DD,
        woth, wotl);
    transpose_split_kernel<<<dim3(FFD/32, DD/32), tb>>>(W1, w1th, w1tl, DD, FFD);
    transpose_split_kernel<<<dim3(DD/32, FFD/32), tb>>>(W2, w2th, w2tl, FFD, DD);
    concat_bias_kernel<<<6, 256>>>(bq, bk, bv, bqkv);

    dim3 g512(DD / 128, MM / 128);       // (4, 32)
    dim3 gQKV(3 * DD / 128, MM / 128);   // (12, 32)
    dim3 gFF (FFD / 128, MM / 128);      // (16, 32)

    // fused QKV: q,k,v all as bf16 planes; padded tiles short-circuit to bias
    hgemm<3><<<gQKV, 256, SMEM_HGEMM>>>(xh, xl, wqkvth, wqkvtl, bqkv,
                                        nullptr, qh, ql, kh, kl, wvh, wvl,
                                        lengths, 1, MM, 3 * DD, DD, DD);

    // attention diag + in-place wv = diag*v
    attn_diag_hmma<<<dim3(SS / 64, HH, BB), 128, SMEM_ATTN>>>(qh, ql, kh, kl, wvh, wvl, lengths);

    hgemm<0><<<g512, 256, SMEM_HGEMM>>>(wvh, wvl, woth, wotl, bo,
                                        ao, nullptr, nullptr, nullptr, nullptr, nullptr, nullptr,
                                        lengths, 1, MM, DD, DD, DD);

    ln_kernel<true, true><<<MM, 256>>>(xh, xl, nullptr, ao, gamma1, beta1, y1, y1h, y1l);

    hgemm<1><<<gFF, 256, SMEM_HGEMM>>>(y1h, y1l, w1th, w1tl, b1,
                                       nullptr, h1h, h1l, nullptr, nullptr, nullptr, nullptr,
                                       lengths, 2, MM, FFD, DD, FFD);
    hgemm<0><<<g512, 256, SMEM_HGEMM>>>(h1h, h1l, w2th, w2tl, b2,
                                        f2, nullptr, nullptr, nullptr, nullptr, nullptr, nullptr,
                                        lengths, 2, MM, DD, FFD, DD);

    ln_kernel<false, false><<<MM, 256>>>(nullptr, nullptr, y1, f2, gamma2, beta2,
                                         (float*)d_out, nullptr, nullptr);
}

// round 12
// speedup vs baseline: 4.5767x; 1.3929x over previous
#include <cuda_runtime.h>
#include <cuda_fp16.h>
#include <math.h>
#include <stdint.h>

#define BB 2
#define SS 2048
#define DD 512
#define HH 8
#define DK 64
#define FFD 2048
#define MM (BB*SS)          // 4096 rows
#define L2E 1.4426950408889634f

// ---------------- scratch (static device arrays; no runtime alloc) -------------
__device__ float g_ao[MM*DD];
__device__ float g_f2[MM*DD];
__device__ float g_bqkv[3*DD];
// fp16 hi/lo planes (activations)
__device__ __half g_xh [MM*DD],  g_xl [MM*DD];
__device__ __half g_qh [MM*DD],  g_ql [MM*DD];
__device__ __half g_kh [MM*DD],  g_kl [MM*DD];
__device__ __half g_wvh[MM*DD],  g_wvl[MM*DD];   // v planes, scaled in place by attn
__device__ __half g_y1h[MM*DD],  g_y1l[MM*DD];
__device__ __half g_h1h[MM*FFD], g_h1l[MM*FFD];
// transposed weights [N, K], single fp16 plane
__device__ __half g_wqkvt[3*DD*DD];
__device__ __half g_wot[DD*DD];
__device__ __half g_w1t[FFD*DD];
__device__ __half g_w2t[DD*FFD];

// ---------------- PTX helpers ---------------------------------------------------
__device__ __forceinline__ uint32_t smem_u32(const void* p) {
    uint32_t a;
    asm("{ .reg .u64 t; cvta.to.shared.u64 t, %1; cvt.u32.u64 %0, t; }" : "=r"(a) : "l"(p));
    return a;
}
__device__ __forceinline__ void mma_fp16(float* c, const uint32_t* a, const uint32_t* b) {
    asm volatile(
        "mma.sync.aligned.m16n8k16.row.col.f32.f16.f16.f32 "
        "{%0,%1,%2,%3},{%4,%5,%6,%7},{%8,%9},{%0,%1,%2,%3};"
        : "+f"(c[0]), "+f"(c[1]), "+f"(c[2]), "+f"(c[3])
        : "r"(a[0]), "r"(a[1]), "r"(a[2]), "r"(a[3]), "r"(b[0]), "r"(b[1]));
}
__device__ __forceinline__ void ldsm4(uint32_t* r, uint32_t addr) {
    asm volatile("ldmatrix.sync.aligned.m8n8.x4.shared.b16 {%0,%1,%2,%3},[%4];"
                 : "=r"(r[0]), "=r"(r[1]), "=r"(r[2]), "=r"(r[3]) : "r"(addr));
}
__device__ __forceinline__ void cpa16(uint32_t dst, const void* src) {
    asm volatile("cp.async.cg.shared.global [%0],[%1],16;" :: "r"(dst), "l"(src));
}
__device__ __forceinline__ void split1(float a, __half& h, __half& l) {
    h = __float2half(a);
    l = __float2half(a - __half2float(h));
}

// ---------------- weight transpose (single fp16 plane): oh[C][R] = in[R][C] -----
__global__ __launch_bounds__(256)
void transpose_half_kernel(const float* __restrict__ in, __half* __restrict__ oh,
                           int R, int C)
{
    __shared__ float t[32][33];
    int bx = blockIdx.x * 32, by = blockIdx.y * 32;
    int tx = threadIdx.x, ty = threadIdx.y;   // (32, 8)
#pragma unroll
    for (int i = 0; i < 32; i += 8)
        t[ty + i][tx] = in[(size_t)(by + ty + i) * C + bx + tx];
    __syncthreads();
#pragma unroll
    for (int i = 0; i < 32; i += 8)
        oh[(size_t)(bx + ty + i) * R + by + tx] = __float2half(t[tx][ty + i]);
}

// batched: 4 square DxD transposes in one launch
__global__ __launch_bounds__(256)
void transpose_half4_kernel(const float* __restrict__ i0, const float* __restrict__ i1,
                            const float* __restrict__ i2, const float* __restrict__ i3,
                            __half* __restrict__ h0, __half* __restrict__ h1,
                            __half* __restrict__ h2, __half* __restrict__ h3)
{
    int z = blockIdx.z;
    const float* in = (z == 0) ? i0 : (z == 1) ? i1 : (z == 2) ? i2 : i3;
    __half* oh = (z == 0) ? h0 : (z == 1) ? h1 : (z == 2) ? h2 : h3;
    __shared__ float t[32][33];
    int bx = blockIdx.x * 32, by = blockIdx.y * 32;
    int tx = threadIdx.x, ty = threadIdx.y;
#pragma unroll
    for (int i = 0; i < 32; i += 8)
        t[ty + i][tx] = in[(size_t)(by + ty + i) * DD + bx + tx];
    __syncthreads();
#pragma unroll
    for (int i = 0; i < 32; i += 8)
        oh[(size_t)(bx + ty + i) * DD + by + tx] = __float2half(t[tx][ty + i]);
}

__global__ void concat_bias_kernel(const float* __restrict__ a, const float* __restrict__ b,
                                   const float* __restrict__ c, float* __restrict__ o)
{
    int i = blockIdx.x * blockDim.x + threadIdx.x;
    if (i >= 3 * DD) return;
    o[i] = (i < DD) ? a[i] : (i < 2 * DD) ? b[i - DD] : c[i - 2 * DD];
}

// ---------------- HMMA fp16 2-pass GEMM ------------------------------------------
// C[M,N] = (Ah+Al)[M,K] @ Bh[N,K]^T + bias   (B single fp16 plane)
// tile 128x128, BK=64, 2-stage cp.async, 8 warps 64x32
// MODE 0: fp32 out  MODE 1: relu + fp16 split out  MODE 3: qkv -> all fp16 planes
// skipmode 0: none  1: padded tile -> C=bias  2: padded tile -> 16-row compute+bcast
#define STG 49152
#define SMEM_HGEMM (2 * STG)

template<int MTN, bool RED>
__device__ __forceinline__ void gemm_tiles(uint32_t base, int arow, int asel,
                                           int brow, int bsel, int rx, int wm, int wn,
                                           float acc[4][4][4])
{
#pragma unroll
    for (int s = 0; s < 4; s++) {
        uint32_t Ahf[MTN * 4], Alf[MTN * 4], Bhf[8];
#pragma unroll
        for (int mt = 0; mt < MTN; mt++) {
            uint32_t ro = base + ((RED ? 0 : wm * 64 + mt * 16) + arow) * 128;
            uint32_t sw = ((2 * s + asel) ^ rx) << 4;
            ldsm4(&Ahf[mt * 4], ro + sw);
            ldsm4(&Alf[mt * 4], ro + 16384 + sw);
        }
#pragma unroll
        for (int nt2 = 0; nt2 < 2; nt2++) {
            uint32_t ro = base + 32768 + (wn * 32 + nt2 * 16 + brow) * 128;
            ldsm4(&Bhf[nt2 * 4], ro + (((2 * s + bsel) ^ rx) << 4));
        }
#pragma unroll
        for (int mt = 0; mt < MTN; mt++)
#pragma unroll
            for (int nt = 0; nt < 4; nt++)
                mma_fp16(acc[mt][nt], &Ahf[mt * 4], &Bhf[(nt >> 1) * 4 + (nt & 1) * 2]);
#pragma unroll
        for (int mt = 0; mt < MTN; mt++)
#pragma unroll
            for (int nt = 0; nt < 4; nt++)
                mma_fp16(acc[mt][nt], &Alf[mt * 4], &Bhf[(nt >> 1) * 4 + (nt & 1) * 2]);
    }
}

template<int MODE>
__global__ __launch_bounds__(256, 1)
void hgemm(const __half* __restrict__ Ah, const __half* __restrict__ Al,
           const __half* __restrict__ Bh,
           const float* __restrict__ bias,
           float* __restrict__ C, __half* __restrict__ Ch, __half* __restrict__ Cl,
           __half* __restrict__ Dh, __half* __restrict__ Dl,
           __half* __restrict__ Eh, __half* __restrict__ El,
           const int* __restrict__ lengths, int skipmode,
           int M, int N, int K, int OD)
{
    extern __shared__ char smem[];
    uint32_t sb = smem_u32(smem);
    int tid = threadIdx.x, lane = tid & 31, wid = tid >> 5;
    int bm = blockIdx.y * 128, bn = blockIdx.x * 128;
    int wm = wid & 1, wn = wid >> 1;
    int NK = K >> 6;

    bool padded = false;
    if (skipmode) {
        int b = bm >> 11;
        int s0 = bm & (SS - 1);
        padded = (s0 >= lengths[b]);
    }
    bool skipall = (skipmode == 1) && padded;
    bool reduced = (skipmode == 2) && padded;

    float acc[4][4][4];
#pragma unroll
    for (int i = 0; i < 4; i++)
#pragma unroll
        for (int j = 0; j < 4; j++)
#pragma unroll
            for (int r = 0; r < 4; r++) acc[i][j][r] = 0.f;

    int arow = (lane & 7) + ((lane >> 3) & 1) * 8;
    int asel = lane >> 4;
    int brow = (lane & 7) + (lane >> 4) * 8;
    int bsel = (lane >> 3) & 1;
    int rx = lane & 7;

    if (!skipall) {
        auto issue = [&](int kt) {
            uint32_t base = sb + (kt & 1) * STG;
            int k0 = kt << 6;
            if (reduced) {
                // only 16 A rows needed (all padded rows identical): 128 chunks/plane
                if (tid < 128) {
                    int row = tid >> 3, c = tid & 7;
                    cpa16(base + row * 128 + ((c ^ (row & 7)) << 4),
                          Ah + (size_t)(bm + row) * K + k0 + c * 8);
                } else {
                    int t2 = tid - 128;
                    int row = t2 >> 3, c = t2 & 7;
                    cpa16(base + 16384 + row * 128 + ((c ^ (row & 7)) << 4),
                          Al + (size_t)(bm + row) * K + k0 + c * 8);
                }
            } else {
#pragma unroll
                for (int i = 0; i < 4; i++) {
                    int idx = i * 256 + tid;
                    int row = idx >> 3, c = idx & 7;
                    uint32_t sw = row * 128 + ((c ^ (row & 7)) << 4);
                    cpa16(base + sw, Ah + (size_t)(bm + row) * K + k0 + c * 8);
                    cpa16(base + 16384 + sw, Al + (size_t)(bm + row) * K + k0 + c * 8);
                }
            }
#pragma unroll
            for (int i = 0; i < 4; i++) {
                int idx = i * 256 + tid;
                int row = idx >> 3, c = idx & 7;
                cpa16(base + 32768 + row * 128 + ((c ^ (row & 7)) << 4),
                      Bh + (size_t)(bn + row) * K + k0 + c * 8);
            }
            asm volatile("cp.async.commit_group;");
        };

        issue(0);
        if (NK > 1) issue(1);

        for (int kt = 0; kt < NK; kt++) {
            if (kt == NK - 1) asm volatile("cp.async.wait_group 0;");
            else              asm volatile("cp.async.wait_group 1;");
            __syncthreads();
            uint32_t base = sb + (kt & 1) * STG;
            if (reduced) gemm_tiles<1, true >(base, arow, asel, brow, bsel, rx, wm, wn, acc);
            else         gemm_tiles<4, false>(base, arow, asel, brow, bsel, rx, wm, wn, acc);
            __syncthreads();
            if (kt + 2 < NK) issue(kt + 2);
        }

        if (reduced) {
#pragma unroll
            for (int mt = 1; mt < 4; mt++)
#pragma unroll
                for (int nt = 0; nt < 4; nt++)
#pragma unroll
                    for (int r = 0; r < 4; r++) acc[mt][nt][r] = acc[0][nt][r];
        }
    }

    // epilogue
    int g = lane >> 2, tig = lane & 3;
    __half *oh = Ch, *ol = Cl;
    if (MODE == 3) {
        int seg = bn >> 9;              // 0: q, 1: k, 2: v
        if (seg == 1) { oh = Dh; ol = Dl; }
        if (seg == 2) { oh = Eh; ol = El; }
    }
#pragma unroll
    for (int mt = 0; mt < 4; mt++) {
#pragma unroll
        for (int nt = 0; nt < 4; nt++) {
            int colg = bn + wn * 32 + nt * 8 + tig * 2;
            float2 bv = *(const float2*)&bias[colg];
            int r0 = bm + wm * 64 + mt * 16 + g;
            float x0 = acc[mt][nt][0] + bv.x, x1 = acc[mt][nt][1] + bv.y;
            float x2 = acc[mt][nt][2] + bv.x, x3 = acc[mt][nt][3] + bv.y;
            if (MODE == 0) {
                float2 o0 = {x0, x1}, o1 = {x2, x3};
                *(float2*)&C[(size_t)r0 * OD + colg] = o0;
                *(float2*)&C[(size_t)(r0 + 8) * OD + colg] = o1;
            } else {
                if (MODE == 1) {
                    x0 = fmaxf(x0, 0.f); x1 = fmaxf(x1, 0.f);
                    x2 = fmaxf(x2, 0.f); x3 = fmaxf(x3, 0.f);
                }
                int col = (MODE == 3) ? (colg & 511) : colg;
                __half h0, l0, h1, l1, h2, l2, h3, l3;
                split1(x0, h0, l0); split1(x1, h1, l1);
                split1(x2, h2, l2); split1(x3, h3, l3);
                __half2 hh0 = {h0, h1}, ll0 = {l0, l1};
                __half2 hh1 = {h2, h3}, ll1 = {l2, l3};
                *(__half2*)&oh[(size_t)r0 * OD + col] = hh0;
                *(__half2*)&ol[(size_t)r0 * OD + col] = ll0;
                *(__half2*)&oh[(size_t)(r0 + 8) * OD + col] = hh1;
                *(__half2*)&ol[(size_t)(r0 + 8) * OD + col] = ll1;
            }
        }
    }
}

// ---------------- pad-mask + split (fp16 planes) ---------------------------------
__global__ void mask_split_kernel(const float* __restrict__ x, const int* __restrict__ lengths,
                                  __half* __restrict__ xh, __half* __restrict__ xl)
{
    int i = blockIdx.x * blockDim.x + threadIdx.x;
    if (i >= (MM*DD)/4) return;
    int row = (i * 4) / DD;
    int s = row & (SS - 1);
    int b = row >> 11;
    float4 val = ((const float4*)x)[i];
    if (s >= lengths[b]) val = make_float4(0.f, 0.f, 0.f, 0.f);
    __half h0, l0, h1, l1, h2, l2, h3, l3;
    split1(val.x, h0, l0); split1(val.y, h1, l1);
    split1(val.z, h2, l2); split1(val.w, h3, l3);
    __half2* ph = (__half2*)&xh[i * 4];
    __half2* pl = (__half2*)&xl[i * 4];
    ph[0] = {h0, h1}; ph[1] = {h2, h3};
    pl[0] = {l0, l1}; pl[1] = {l2, l3};
}

// ---------------- attention diag via HMMA (fp16 3-pass) + fused wv (in place) ----
#define SMEM_ATTN 49152
__global__ __launch_bounds__(128, 1)
void attn_diag_hmma(const __half* __restrict__ qh, const __half* __restrict__ ql,
                    const __half* __restrict__ kh, const __half* __restrict__ kl,
                    __half* vh, __half* vl,
                    const int* __restrict__ lengths)
{
    extern __shared__ char sm[];
    uint32_t sb = smem_u32(sm);
    float* sdiag = (float*)sm;
    int bx = (int)gridDim.x - 1 - (int)blockIdx.x;
    int h = blockIdx.y, b = blockIdx.z;
    int tid = threadIdx.x, lane = tid & 31, w = tid >> 5;
    int i0 = bx * 64;
    int len = lengths[b];
    const size_t vbase = ((size_t)(b * SS + i0)) * DD + h * DK;

    if (i0 >= len) {
        uint4 z = make_uint4(0, 0, 0, 0);
#pragma unroll
        for (int it = 0; it < 4; it++) {
            int idx = it * 128 + tid;
            int row = idx >> 3, c8 = (idx & 7) * 8;
            *(uint4*)&vh[vbase + (size_t)row * DD + c8] = z;
            *(uint4*)&vl[vbase + (size_t)row * DD + c8] = z;
        }
        return;
    }

    const size_t qg = vbase;
#pragma unroll
    for (int i = 0; i < 4; i++) {
        int idx = i * 128 + tid;
        int row = idx >> 3, c = idx & 7;
        cpa16(sb + row * 128 + ((c ^ (row & 7)) << 4), qh + qg + (size_t)row * DD + c * 8);
    }
#pragma unroll
    for (int i = 0; i < 4; i++) {
        int idx = i * 128 + tid;
        int row = idx >> 3, c = idx & 7;
        cpa16(sb + 8192 + row * 128 + ((c ^ (row & 7)) << 4), ql + qg + (size_t)row * DD + c * 8);
    }
    auto issueK = [&](int t, int buf) {
        uint32_t kb = sb + 16384 + buf * 16384;
        size_t g = ((size_t)(b * SS + t * 64)) * DD + h * DK;
#pragma unroll
        for (int i = 0; i < 4; i++) {
            int idx = i * 128 + tid;
            int row = idx >> 3, c = idx & 7;
            cpa16(kb + row * 128 + ((c ^ (row & 7)) << 4), kh + g + (size_t)row * DD + c * 8);
        }
#pragma unroll
        for (int i = 0; i < 4; i++) {
            int idx = i * 128 + tid;
            int row = idx >> 3, c = idx & 7;
            cpa16(kb + 8192 + row * 128 + ((c ^ (row & 7)) << 4), kl + g + (size_t)row * DD + c * 8);
        }
    };
    issueK(0, 0);
    asm volatile("cp.async.commit_group;");
    if (bx >= 1) { issueK(1, 1); asm volatile("cp.async.commit_group;"); }

    int arow = (lane & 7) + ((lane >> 3) & 1) * 8;
    int asel = lane >> 4;
    int brow = (lane & 7) + (lane >> 4) * 8;
    int bsel = (lane >> 3) & 1;
    int g_ = lane >> 2, tig = lane & 3;

    uint32_t Qh[16], Ql[16];
    float m[2] = {-1e30f, -1e30f}, l[2] = {0.f, 0.f}, sd[2] = {-1e30f, -1e30f};

    for (int t = 0; t <= bx; t++) {
        if (t < bx) asm volatile("cp.async.wait_group 1;");
        else        asm volatile("cp.async.wait_group 0;");
        __syncthreads();
        if (t == 0) {
            int r = w * 16 + arow;
#pragma unroll
            for (int kc = 0; kc < 4; kc++) {
                ldsm4(&Qh[kc * 4], sb + r * 128 + (((2 * kc + asel) ^ (r & 7)) << 4));
                ldsm4(&Ql[kc * 4], sb + 8192 + r * 128 + (((2 * kc + asel) ^ (r & 7)) << 4));
            }
        }
        uint32_t kb = sb + 16384 + (t & 1) * 16384;
        float acc[8][4];
#pragma unroll
        for (int nt = 0; nt < 8; nt++)
#pragma unroll
            for (int r = 0; r < 4; r++) acc[nt][r] = 0.f;

#pragma unroll
        for (int kc = 0; kc < 4; kc++) {
            uint32_t Bh[16], Bl[16];
#pragma unroll
            for (int nt2 = 0; nt2 < 4; nt2++) {
                int rr = nt2 * 16 + brow;
                ldsm4(&Bh[nt2 * 4], kb + rr * 128 + (((2 * kc + bsel) ^ (rr & 7)) << 4));
                ldsm4(&Bl[nt2 * 4], kb + 8192 + rr * 128 + (((2 * kc + bsel) ^ (rr & 7)) << 4));
            }
#pragma unroll
            for (int nt = 0; nt < 8; nt++)
                mma_fp16(acc[nt], &Qh[kc * 4], &Bh[(nt >> 1) * 4 + (nt & 1) * 2]);
#pragma unroll
            for (int nt = 0; nt < 8; nt++)
                mma_fp16(acc[nt], &Qh[kc * 4], &Bl[(nt >> 1) * 4 + (nt & 1) * 2]);
#pragma unroll
            for (int nt = 0; nt < 8; nt++)
                mma_fp16(acc[nt], &Ql[kc * 4], &Bh[(nt >> 1) * 4 + (nt & 1) * 2]);
        }

        bool dtile = (t == bx);
#pragma unroll
        for (int r = 0; r < 2; r++) {
            int il = w * 16 + g_ + r * 8;
            float tm = -1e30f;
            float vals[16];
#pragma unroll
            for (int nt = 0; nt < 8; nt++)
#pragma unroll
                for (int c = 0; c < 2; c++) {
                    float v = acc[nt][r * 2 + c];
                    if (dtile) {
                        int jl = nt * 8 + tig * 2 + c;
                        if (jl == il) sd[r] = v;
                        if (jl > il) v = -1e30f;
                    }
                    vals[nt * 2 + c] = v;
                    tm = fmaxf(tm, v);
                }
            float mn = fmaxf(m[r], tm);
            float sc = exp2f((m[r] - mn) * L2E);
            float ls = 0.f;
#pragma unroll
            for (int i = 0; i < 16; i++) ls += exp2f((vals[i] - mn) * L2E);
            l[r] = l[r] * sc + ls;
            m[r] = mn;
        }
        __syncthreads();
        if (t + 2 <= bx) { issueK(t + 2, t & 1); asm volatile("cp.async.commit_group;"); }
    }

#pragma unroll
    for (int r = 0; r < 2; r++) {
        float mm = m[r], ll = l[r], ss = sd[r];
#pragma unroll
        for (int o = 1; o <= 2; o <<= 1) {
            float mo = __shfl_xor_sync(0xffffffffu, mm, o);
            float lo = __shfl_xor_sync(0xffffffffu, ll, o);
            float so = __shfl_xor_sync(0xffffffffu, ss, o);
            float mn = fmaxf(mm, mo);
            ll = ll * exp2f((mm - mn) * L2E) + lo * exp2f((mo - mn) * L2E);
            mm = mn;
            ss = fmaxf(ss, so);
        }
        if (tig == 0) {
            int rl = w * 16 + g_ + r * 8;
            float dv = (i0 + rl < len) ? exp2f((ss - mm) * L2E) / ll : 0.f;
            sdiag[rl] = dv;
        }
    }
    __syncthreads();

    // fused epilogue: wv = diag * (vh + vl), split, in place
#pragma unroll
    for (int it = 0; it < 4; it++) {
        int idx = it * 128 + tid;
        int row = idx >> 3, c8 = (idx & 7) * 8;
        size_t off = vbase + (size_t)row * DD + c8;
        uint4 hv = *(uint4*)&vh[off];
        uint4 lv = *(uint4*)&vl[off];
        float dv = sdiag[row];
        __half2* hp = (__half2*)&hv;
        __half2* lp = (__half2*)&lv;
        uint4 ho, lo;
        __half2* hop = (__half2*)&ho;
        __half2* lop = (__half2*)&lo;
#pragma unroll
        for (int j = 0; j < 4; j++) {
            float f0 = dv * (__half2float(hp[j].x) + __half2float(lp[j].x));
            float f1 = dv * (__half2float(hp[j].y) + __half2float(lp[j].y));
            __half a, bq, c, d;
            split1(f0, a, bq); split1(f1, c, d);
            hop[j] = {a, c}; lop[j] = {bq, d};
        }
        *(uint4*)&vh[off] = ho;
        *(uint4*)&vl[off] = lo;
    }
}

// ---------------- LayerNorm(a + r) -----------------------------------------------
// a given as fp16 hi/lo planes; r fp32. SPLIT: emit fp16 planes. OUTF: emit fp32.
template<bool SPLIT, bool OUTF>
__global__ __launch_bounds__(256)
void ln_kernel(const __half* __restrict__ ah, const __half* __restrict__ al,
               const float* __restrict__ r,
               const float* __restrict__ gamma, const float* __restrict__ beta,
               float* __restrict__ out,
               __half* __restrict__ oh, __half* __restrict__ ol)
{
    int row = blockIdx.x;
    int tid = threadIdx.x;
    size_t base = (size_t)row * DD;

    float a0 = __half2float(ah[base + tid]) + __half2float(al[base + tid]);
    float a1 = __half2float(ah[base + tid + 256]) + __half2float(al[base + tid + 256]);
    float v0 = a0 + r[base + tid];
    float v1 = a1 + r[base + tid + 256];

    __shared__ float sred[8];
    __shared__ float smean, srstd;

    float s = v0 + v1;
#pragma unroll
    for (int o = 16; o > 0; o >>= 1) s += __shfl_xor_sync(0xffffffffu, s, o);
    if ((tid & 31) == 0) sred[tid >> 5] = s;
    __syncthreads();
    if (tid == 0) {
        float t = 0.f;
#pragma unroll
        for (int i = 0; i < 8; i++) t += sred[i];
        smean = t * (1.0f / DD);
    }
    __syncthreads();
    float mean = smean;
    float d0 = v0 - mean, d1 = v1 - mean;
    float vs = d0 * d0 + d1 * d1;
#pragma unroll
    for (int o = 16; o > 0; o >>= 1) vs += __shfl_xor_sync(0xffffffffu, vs, o);
    if ((tid & 31) == 0) sred[tid >> 5] = vs;
    __syncthreads();
    if (tid == 0) {
        float t = 0.f;
#pragma unroll
        for (int i = 0; i < 8; i++) t += sred[i];
        srstd = rsqrtf(t * (1.0f / DD) + 1e-3f);
    }
    __syncthreads();
    float rstd = srstd;
    float o0 = gamma[tid]       * (d0 * rstd) + beta[tid];
    float o1 = gamma[tid + 256] * (d1 * rstd) + beta[tid + 256];
    if (OUTF) {
        out[base + tid]       = o0;
        out[base + tid + 256] = o1;
    }
    if (SPLIT) {
        __half h0, l0, h1, l1;
        split1(o0, h0, l0);
        split1(o1, h1, l1);
        oh[base + tid]       = h0;
        ol[base + tid]       = l0;
        oh[base + tid + 256] = h1;
        ol[base + tid + 256] = l1;
    }
}

// ---------------- launch --------------------------------------------------------
extern "C" void kernel_launch(void* const* d_in, const int* in_sizes, int n_in,
                              void* d_out, int out_size)
{
    const float* x       = (const float*)d_in[0];
    const int*   lengths = (const int*)d_in[1];
    const float* Wq = (const float*)d_in[2];
    const float* bq = (const float*)d_in[3];
    const float* Wk = (const float*)d_in[4];
    const float* bk = (const float*)d_in[5];
    const float* Wv = (const float*)d_in[6];
    const float* bv = (const float*)d_in[7];
    const float* Wo = (const float*)d_in[8];
    const float* bo = (const float*)d_in[9];
    const float* W1 = (const float*)d_in[10];
    const float* b1 = (const float*)d_in[11];
    const float* W2 = (const float*)d_in[12];
    const float* b2 = (const float*)d_in[13];
    const float* gamma1 = (const float*)d_in[14];
    const float* beta1  = (const float*)d_in[15];
    const float* gamma2 = (const float*)d_in[16];
    const float* beta2  = (const float*)d_in[17];

    float *ao, *f2, *bqkv;
    __half *xh, *xl, *qh, *ql, *kh, *kl, *wvh, *wvl, *y1h, *y1l, *h1h, *h1l;
    __half *wqkvt, *wot, *w1t, *w2t;
    cudaGetSymbolAddress((void**)&ao,   g_ao);
    cudaGetSymbolAddress((void**)&f2,   g_f2);
    cudaGetSymbolAddress((void**)&bqkv, g_bqkv);
    cudaGetSymbolAddress((void**)&xh,   g_xh);
    cudaGetSymbolAddress((void**)&xl,   g_xl);
    cudaGetSymbolAddress((void**)&qh,   g_qh);
    cudaGetSymbolAddress((void**)&ql,   g_ql);
    cudaGetSymbolAddress((void**)&kh,   g_kh);
    cudaGetSymbolAddress((void**)&kl,   g_kl);
    cudaGetSymbolAddress((void**)&wvh,  g_wvh);
    cudaGetSymbolAddress((void**)&wvl,  g_wvl);
    cudaGetSymbolAddress((void**)&y1h,  g_y1h);
    cudaGetSymbolAddress((void**)&y1l,  g_y1l);
    cudaGetSymbolAddress((void**)&h1h,  g_h1h);
    cudaGetSymbolAddress((void**)&h1l,  g_h1l);
    cudaGetSymbolAddress((void**)&wqkvt, g_wqkvt);
    cudaGetSymbolAddress((void**)&wot,  g_wot);
    cudaGetSymbolAddress((void**)&w1t,  g_w1t);
    cudaGetSymbolAddress((void**)&w2t,  g_w2t);

    cudaFuncSetAttribute(hgemm<0>, cudaFuncAttributeMaxDynamicSharedMemorySize, SMEM_HGEMM);
    cudaFuncSetAttribute(hgemm<1>, cudaFuncAttributeMaxDynamicSharedMemorySize, SMEM_HGEMM);
    cudaFuncSetAttribute(hgemm<3>, cudaFuncAttributeMaxDynamicSharedMemorySize, SMEM_HGEMM);
    cudaFuncSetAttribute(attn_diag_hmma, cudaFuncAttributeMaxDynamicSharedMemorySize, SMEM_ATTN);

    int n4 = (MM * DD) / 4;
    mask_split_kernel<<<(n4 + 255) / 256, 256>>>(x, lengths, xh, xl);

    dim3 tb(32, 8);
    transpose_half4_kernel<<<dim3(DD/32, DD/32, 4), tb>>>(
        Wq, Wk, Wv, Wo,
        wqkvt, wqkvt + DD*DD, wqkvt + 2*DD*DD, wot);
    transpose_half_kernel<<<dim3(FFD/32, DD/32), tb>>>(W1, w1t, DD, FFD);
    transpose_half_kernel<<<dim3(DD/32, FFD/32), tb>>>(W2, w2t, FFD, DD);
    concat_bias_kernel<<<6, 256>>>(bq, bk, bv, bqkv);

    dim3 g512(DD / 128, MM / 128);       // (4, 32)
    dim3 gQKV(3 * DD / 128, MM / 128);   // (12, 32)
    dim3 gFF (FFD / 128, MM / 128);      // (16, 32)

    // fused QKV: q,k,v all as fp16 planes; padded tiles short-circuit to bias
    hgemm<3><<<gQKV, 256, SMEM_HGEMM>>>(xh, xl, wqkvt, bqkv,
                                        nullptr, qh, ql, kh, kl, wvh, wvl,
                                        lengths, 1, MM, 3 * DD, DD, DD);

    // attention diag + in-place wv = diag*v
    attn_diag_hmma<<<dim3(SS / 64, HH, BB), 128, SMEM_ATTN>>>(qh, ql, kh, kl, wvh, wvl, lengths);

    hgemm<0><<<g512, 256, SMEM_HGEMM>>>(wvh, wvl, wot, bo,
                                        ao, nullptr, nullptr, nullptr, nullptr, nullptr, nullptr,
                                        lengths, 1, MM, DD, DD, DD);

    // ln1: LN(x + ao) -> fp16 planes only
    ln_kernel<true, false><<<MM, 256>>>(xh, xl, ao, gamma1, beta1, nullptr, y1h, y1l);

    hgemm<1><<<gFF, 256, SMEM_HGEMM>>>(y1h, y1l, w1t, b1,
                                       nullptr, h1h, h1l, nullptr, nullptr, nullptr, nullptr,
                                       lengths, 2, MM, FFD, DD, FFD);
    hgemm<0><<<g512, 256, SMEM_HGEMM>>>(h1h, h1l, w2t, b2,
                                        f2, nullptr, nullptr, nullptr, nullptr, nullptr, nullptr,
                                        lengths, 2, MM, DD, FFD, DD);

    // ln2: LN(y1 + f2) -> fp32 output
    ln_kernel<false, true><<<MM, 256>>>(y1h, y1l, f2, gamma2, beta2,
                                        (float*)d_out, nullptr, nullptr);
}

// round 13
// speedup vs baseline: 5.5873x; 1.2208x over previous
#include <cuda_runtime.h>
#include <cuda_fp16.h>
#include <math.h>
#include <stdint.h>

#define BB 2
#define SS 2048
#define DD 512
#define HH 8
#define DK 64
#define FFD 2048
#define MM (BB*SS)          // 4096 rows
#define L2E 1.4426950408889634f

// ---------------- scratch (static device arrays; no runtime alloc) -------------
__device__ float g_ao[MM*DD];
__device__ float g_f2[MM*DD];
__device__ float g_bqkv[3*DD];
// fp16 planes
__device__ __half g_xh [MM*DD],  g_xl [MM*DD];
__device__ __half g_qh [MM*DD],  g_ql [MM*DD];
__device__ __half g_kh [MM*DD],  g_kl [MM*DD];
__device__ __half g_wvh[MM*DD];                 // v single plane, scaled in place by attn
__device__ __half g_y1h[MM*DD],  g_y1l[MM*DD];  // hi/lo kept for residual accuracy
__device__ __half g_h1h[MM*FFD];                // single plane
// transposed weights [N, K], single fp16 plane
__device__ __half g_wqkvt[3*DD*DD];
__device__ __half g_wot[DD*DD];
__device__ __half g_w1t[FFD*DD];
__device__ __half g_w2t[DD*FFD];

// ---------------- PTX helpers ---------------------------------------------------
__device__ __forceinline__ uint32_t smem_u32(const void* p) {
    uint32_t a;
    asm("{ .reg .u64 t; cvta.to.shared.u64 t, %1; cvt.u32.u64 %0, t; }" : "=r"(a) : "l"(p));
    return a;
}
__device__ __forceinline__ void mma_fp16(float* c, const uint32_t* a, const uint32_t* b) {
    asm volatile(
        "mma.sync.aligned.m16n8k16.row.col.f32.f16.f16.f32 "
        "{%0,%1,%2,%3},{%4,%5,%6,%7},{%8,%9},{%0,%1,%2,%3};"
        : "+f"(c[0]), "+f"(c[1]), "+f"(c[2]), "+f"(c[3])
        : "r"(a[0]), "r"(a[1]), "r"(a[2]), "r"(a[3]), "r"(b[0]), "r"(b[1]));
}
__device__ __forceinline__ void ldsm4(uint32_t* r, uint32_t addr) {
    asm volatile("ldmatrix.sync.aligned.m8n8.x4.shared.b16 {%0,%1,%2,%3},[%4];"
                 : "=r"(r[0]), "=r"(r[1]), "=r"(r[2]), "=r"(r[3]) : "r"(addr));
}
__device__ __forceinline__ void cpa16(uint32_t dst, const void* src) {
    asm volatile("cp.async.cg.shared.global [%0],[%1],16;" :: "r"(dst), "l"(src));
}
__device__ __forceinline__ void split1(float a, __half& h, __half& l) {
    h = __float2half(a);
    l = __float2half(a - __half2float(h));
}

// ---------------- weight transposes ----------------------------------------------
// batched: 4 square DxD transposes in one launch
__global__ __launch_bounds__(256)
void transpose_half4_kernel(const float* __restrict__ i0, const float* __restrict__ i1,
                            const float* __restrict__ i2, const float* __restrict__ i3,
                            __half* __restrict__ h0, __half* __restrict__ h1,
                            __half* __restrict__ h2, __half* __restrict__ h3)
{
    int z = blockIdx.z;
    const float* in = (z == 0) ? i0 : (z == 1) ? i1 : (z == 2) ? i2 : i3;
    __half* oh = (z == 0) ? h0 : (z == 1) ? h1 : (z == 2) ? h2 : h3;
    __shared__ float t[32][33];
    int bx = blockIdx.x * 32, by = blockIdx.y * 32;
    int tx = threadIdx.x, ty = threadIdx.y;
#pragma unroll
    for (int i = 0; i < 32; i += 8)
        t[ty + i][tx] = in[(size_t)(by + ty + i) * DD + bx + tx];
    __syncthreads();
#pragma unroll
    for (int i = 0; i < 32; i += 8)
        oh[(size_t)(bx + ty + i) * DD + by + tx] = __float2half(t[tx][ty + i]);
}

// W1 [DD,FFD] and W2 [FFD,DD] in one launch (z=1 swaps block roles)
__global__ __launch_bounds__(256)
void transpose_half_ff_kernel(const float* __restrict__ w1, const float* __restrict__ w2,
                              __half* __restrict__ o1, __half* __restrict__ o2)
{
    int z = blockIdx.z;
    const float* in = z ? w2 : w1;
    __half* oh = z ? o2 : o1;
    int R = z ? FFD : DD;       // in rows
    int C = z ? DD : FFD;       // in cols
    int bxi = z ? (int)blockIdx.y : (int)blockIdx.x;
    int byi = z ? (int)blockIdx.x : (int)blockIdx.y;
    __shared__ float t[32][33];
    int bx = bxi * 32, by = byi * 32;
    int tx = threadIdx.x, ty = threadIdx.y;
#pragma unroll
    for (int i = 0; i < 32; i += 8)
        t[ty + i][tx] = in[(size_t)(by + ty + i) * C + bx + tx];
    __syncthreads();
#pragma unroll
    for (int i = 0; i < 32; i += 8)
        oh[(size_t)(bx + ty + i) * R + by + tx] = __float2half(t[tx][ty + i]);
}

__global__ void concat_bias_kernel(const float* __restrict__ a, const float* __restrict__ b,
                                   const float* __restrict__ c, float* __restrict__ o)
{
    int i = blockIdx.x * blockDim.x + threadIdx.x;
    if (i >= 3 * DD) return;
    o[i] = (i < DD) ? a[i] : (i < 2 * DD) ? b[i - DD] : c[i - 2 * DD];
}

// ---------------- HMMA fp16 GEMM (AP = activation passes: 1 or 2) ----------------
// C[M,N] = (Ah[+Al])[M,K] @ Bh[N,K]^T + bias
// tile 128x128, BK=64, 2-stage cp.async, 8 warps 64x32
// MODE 0: fp32 out  MODE 1: relu + fp16 single plane out
// MODE 3: qkv -> q,k hi/lo planes; v single plane
// skipmode 0: none  1: padded tile -> C=bias  2: padded tile -> 16-row compute+bcast

template<int MTN, bool RED, int AP>
__device__ __forceinline__ void gemm_tiles(uint32_t base, int arow, int asel,
                                           int brow, int bsel, int rx, int wm, int wn,
                                           float acc[4][4][4])
{
    constexpr uint32_t BO = AP * 16384u;
#pragma unroll
    for (int s = 0; s < 4; s++) {
        uint32_t Ahf[MTN * 4], Alf[MTN * 4], Bhf[8];
#pragma unroll
        for (int mt = 0; mt < MTN; mt++) {
            uint32_t ro = base + ((RED ? 0 : wm * 64 + mt * 16) + arow) * 128;
            uint32_t sw = ((2 * s + asel) ^ rx) << 4;
            ldsm4(&Ahf[mt * 4], ro + sw);
            if (AP == 2) ldsm4(&Alf[mt * 4], ro + 16384 + sw);
        }
#pragma unroll
        for (int nt2 = 0; nt2 < 2; nt2++) {
            uint32_t ro = base + BO + (wn * 32 + nt2 * 16 + brow) * 128;
            ldsm4(&Bhf[nt2 * 4], ro + (((2 * s + bsel) ^ rx) << 4));
        }
#pragma unroll
        for (int mt = 0; mt < MTN; mt++)
#pragma unroll
            for (int nt = 0; nt < 4; nt++)
                mma_fp16(acc[mt][nt], &Ahf[mt * 4], &Bhf[(nt >> 1) * 4 + (nt & 1) * 2]);
        if (AP == 2) {
#pragma unroll
            for (int mt = 0; mt < MTN; mt++)
#pragma unroll
                for (int nt = 0; nt < 4; nt++)
                    mma_fp16(acc[mt][nt], &Alf[mt * 4], &Bhf[(nt >> 1) * 4 + (nt & 1) * 2]);
        }
    }
}

template<int MODE, int AP>
__global__ __launch_bounds__(256, 1)
void hgemm(const __half* __restrict__ Ah, const __half* __restrict__ Al,
           const __half* __restrict__ Bh,
           const float* __restrict__ bias,
           float* __restrict__ C, __half* __restrict__ Ch, __half* __restrict__ Cl,
           __half* __restrict__ Dh, __half* __restrict__ Dl,
           __half* __restrict__ Eh,
           const int* __restrict__ lengths, int skipmode,
           int M, int N, int K, int OD)
{
    constexpr uint32_t BO  = AP * 16384u;
    constexpr uint32_t STG = (AP + 1) * 16384u;
    extern __shared__ char smem[];
    uint32_t sb = smem_u32(smem);
    int tid = threadIdx.x, lane = tid & 31, wid = tid >> 5;
    int bm = blockIdx.y * 128, bn = blockIdx.x * 128;
    int wm = wid & 1, wn = wid >> 1;
    int NK = K >> 6;

    bool padded = false;
    if (skipmode) {
        int b = bm >> 11;
        int s0 = bm & (SS - 1);
        padded = (s0 >= lengths[b]);
    }
    bool skipall = (skipmode == 1) && padded;
    bool reduced = (skipmode == 2) && padded;

    float acc[4][4][4];
#pragma unroll
    for (int i = 0; i < 4; i++)
#pragma unroll
        for (int j = 0; j < 4; j++)
#pragma unroll
            for (int r = 0; r < 4; r++) acc[i][j][r] = 0.f;

    int arow = (lane & 7) + ((lane >> 3) & 1) * 8;
    int asel = lane >> 4;
    int brow = (lane & 7) + (lane >> 4) * 8;
    int bsel = (lane >> 3) & 1;
    int rx = lane & 7;

    if (!skipall) {
        auto issue = [&](int kt) {
            uint32_t base = sb + (kt & 1) * STG;
            int k0 = kt << 6;
            if (reduced) {
                // only 16 A rows needed (all padded rows identical)
                if (tid < 128) {
                    int row = tid >> 3, c = tid & 7;
                    cpa16(base + row * 128 + ((c ^ (row & 7)) << 4),
                          Ah + (size_t)(bm + row) * K + k0 + c * 8);
                } else if (AP == 2 && tid < 256) {
                    int t2 = tid - 128;
                    int row = t2 >> 3, c = t2 & 7;
                    cpa16(base + 16384 + row * 128 + ((c ^ (row & 7)) << 4),
                          Al + (size_t)(bm + row) * K + k0 + c * 8);
                }
            } else {
#pragma unroll
                for (int i = 0; i < 4; i++) {
                    int idx = i * 256 + tid;
                    int row = idx >> 3, c = idx & 7;
                    uint32_t sw = row * 128 + ((c ^ (row & 7)) << 4);
                    cpa16(base + sw, Ah + (size_t)(bm + row) * K + k0 + c * 8);
                    if (AP == 2)
                        cpa16(base + 16384 + sw, Al + (size_t)(bm + row) * K + k0 + c * 8);
                }
            }
#pragma unroll
            for (int i = 0; i < 4; i++) {
                int idx = i * 256 + tid;
                int row = idx >> 3, c = idx & 7;
                cpa16(base + BO + row * 128 + ((c ^ (row & 7)) << 4),
                      Bh + (size_t)(bn + row) * K + k0 + c * 8);
            }
            asm volatile("cp.async.commit_group;");
        };

        issue(0);
        if (NK > 1) issue(1);

        for (int kt = 0; kt < NK; kt++) {
            if (kt == NK - 1) asm volatile("cp.async.wait_group 0;");
            else              asm volatile("cp.async.wait_group 1;");
            __syncthreads();
            uint32_t base = sb + (kt & 1) * STG;
            if (reduced) gemm_tiles<1, true,  AP>(base, arow, asel, brow, bsel, rx, wm, wn, acc);
            else         gemm_tiles<4, false, AP>(base, arow, asel, brow, bsel, rx, wm, wn, acc);
            __syncthreads();
            if (kt + 2 < NK) issue(kt + 2);
        }

        if (reduced) {
#pragma unroll
            for (int mt = 1; mt < 4; mt++)
#pragma unroll
                for (int nt = 0; nt < 4; nt++)
#pragma unroll
                    for (int r = 0; r < 4; r++) acc[mt][nt][r] = acc[0][nt][r];
        }
    }

    // epilogue
    int g = lane >> 2, tig = lane & 3;
    int seg = (MODE == 3) ? (bn >> 9) : 0;   // 0: q, 1: k, 2: v
#pragma unroll
    for (int mt = 0; mt < 4; mt++) {
#pragma unroll
        for (int nt = 0; nt < 4; nt++) {
            int colg = bn + wn * 32 + nt * 8 + tig * 2;
            float2 bv = *(const float2*)&bias[colg];
            int r0 = bm + wm * 64 + mt * 16 + g;
            float x0 = acc[mt][nt][0] + bv.x, x1 = acc[mt][nt][1] + bv.y;
            float x2 = acc[mt][nt][2] + bv.x, x3 = acc[mt][nt][3] + bv.y;
            if (MODE == 0) {
                float2 o0 = {x0, x1}, o1 = {x2, x3};
                *(float2*)&C[(size_t)r0 * OD + colg] = o0;
                *(float2*)&C[(size_t)(r0 + 8) * OD + colg] = o1;
            } else if (MODE == 1) {
                x0 = fmaxf(x0, 0.f); x1 = fmaxf(x1, 0.f);
                x2 = fmaxf(x2, 0.f); x3 = fmaxf(x3, 0.f);
                __half2 hh0 = {__float2half(x0), __float2half(x1)};
                __half2 hh1 = {__float2half(x2), __float2half(x3)};
                *(__half2*)&Ch[(size_t)r0 * OD + colg] = hh0;
                *(__half2*)&Ch[(size_t)(r0 + 8) * OD + colg] = hh1;
            } else {  // MODE 3
                int col = colg & 511;
                if (seg == 2) {
                    __half2 hh0 = {__float2half(x0), __float2half(x1)};
                    __half2 hh1 = {__float2half(x2), __float2half(x3)};
                    *(__half2*)&Eh[(size_t)r0 * OD + col] = hh0;
                    *(__half2*)&Eh[(size_t)(r0 + 8) * OD + col] = hh1;
                } else {
                    __half* oh = seg ? Dh : Ch;
                    __half* ol = seg ? Dl : Cl;
                    __half h0, l0, h1, l1, h2, l2, h3, l3;
                    split1(x0, h0, l0); split1(x1, h1, l1);
                    split1(x2, h2, l2); split1(x3, h3, l3);
                    __half2 hh0 = {h0, h1}, ll0 = {l0, l1};
                    __half2 hh1 = {h2, h3}, ll1 = {l2, l3};
                    *(__half2*)&oh[(size_t)r0 * OD + col] = hh0;
                    *(__half2*)&ol[(size_t)r0 * OD + col] = ll0;
                    *(__half2*)&oh[(size_t)(r0 + 8) * OD + col] = hh1;
                    *(__half2*)&ol[(size_t)(r0 + 8) * OD + col] = ll1;
                }
            }
        }
    }
}

// ---------------- pad-mask + split (fp16 planes) ---------------------------------
__global__ void mask_split_kernel(const float* __restrict__ x, const int* __restrict__ lengths,
                                  __half* __restrict__ xh, __half* __restrict__ xl)
{
    int i = blockIdx.x * blockDim.x + threadIdx.x;
    if (i >= (MM*DD)/4) return;
    int row = (i * 4) / DD;
    int s = row & (SS - 1);
    int b = row >> 11;
    float4 val = ((const float4*)x)[i];
    if (s >= lengths[b]) val = make_float4(0.f, 0.f, 0.f, 0.f);
    __half h0, l0, h1, l1, h2, l2, h3, l3;
    split1(val.x, h0, l0); split1(val.y, h1, l1);
    split1(val.z, h2, l2); split1(val.w, h3, l3);
    __half2* ph = (__half2*)&xh[i * 4];
    __half2* pl = (__half2*)&xl[i * 4];
    ph[0] = {h0, h1}; ph[1] = {h2, h3};
    pl[0] = {l0, l1}; pl[1] = {l2, l3};
}

// ---------------- attention diag via HMMA (fp16 3-pass) + fused wv (in place) ----
#define SMEM_ATTN 49152
__global__ __launch_bounds__(128, 1)
void attn_diag_hmma(const __half* __restrict__ qh, const __half* __restrict__ ql,
                    const __half* __restrict__ kh, const __half* __restrict__ kl,
                    __half* vh,
                    const int* __restrict__ lengths)
{
    extern __shared__ char sm[];
    uint32_t sb = smem_u32(sm);
    float* sdiag = (float*)sm;
    int bx = (int)gridDim.x - 1 - (int)blockIdx.x;
    int h = blockIdx.y, b = blockIdx.z;
    int tid = threadIdx.x, lane = tid & 31, w = tid >> 5;
    int i0 = bx * 64;
    int len = lengths[b];
    const size_t vbase = ((size_t)(b * SS + i0)) * DD + h * DK;

    if (i0 >= len) {
        uint4 z = make_uint4(0, 0, 0, 0);
#pragma unroll
        for (int it = 0; it < 4; it++) {
            int idx = it * 128 + tid;
            int row = idx >> 3, c8 = (idx & 7) * 8;
            *(uint4*)&vh[vbase + (size_t)row * DD + c8] = z;
        }
        return;
    }

    const size_t qg = vbase;
#pragma unroll
    for (int i = 0; i < 4; i++) {
        int idx = i * 128 + tid;
        int row = idx >> 3, c = idx & 7;
        cpa16(sb + row * 128 + ((c ^ (row & 7)) << 4), qh + qg + (size_t)row * DD + c * 8);
    }
#pragma unroll
    for (int i = 0; i < 4; i++) {
        int idx = i * 128 + tid;
        int row = idx >> 3, c = idx & 7;
        cpa16(sb + 8192 + row * 128 + ((c ^ (row & 7)) << 4), ql + qg + (size_t)row * DD + c * 8);
    }
    auto issueK = [&](int t, int buf) {
        uint32_t kb = sb + 16384 + buf * 16384;
        size_t g = ((size_t)(b * SS + t * 64)) * DD + h * DK;
#pragma unroll
        for (int i = 0; i < 4; i++) {
            int idx = i * 128 + tid;
            int row = idx >> 3, c = idx & 7;
            cpa16(kb + row * 128 + ((c ^ (row & 7)) << 4), kh + g + (size_t)row * DD + c * 8);
        }
#pragma unroll
        for (int i = 0; i < 4; i++) {
            int idx = i * 128 + tid;
            int row = idx >> 3, c = idx & 7;
            cpa16(kb + 8192 + row * 128 + ((c ^ (row & 7)) << 4), kl + g + (size_t)row * DD + c * 8);
        }
    };
    issueK(0, 0);
    asm volatile("cp.async.commit_group;");
    if (bx >= 1) { issueK(1, 1); asm volatile("cp.async.commit_group;"); }

    int arow = (lane & 7) + ((lane >> 3) & 1) * 8;
    int asel = lane >> 4;
    int brow = (lane & 7) + (lane >> 4) * 8;
    int bsel = (lane >> 3) & 1;
    int g_ = lane >> 2, tig = lane & 3;

    uint32_t Qh[16], Ql[16];
    float m[2] = {-1e30f, -1e30f}, l[2] = {0.f, 0.f}, sd[2] = {-1e30f, -1e30f};

    for (int t = 0; t <= bx; t++) {
        if (t < bx) asm volatile("cp.async.wait_group 1;");
        else        asm volatile("cp.async.wait_group 0;");
        __syncthreads();
        if (t == 0) {
            int r = w * 16 + arow;
#pragma unroll
            for (int kc = 0; kc < 4; kc++) {
                ldsm4(&Qh[kc * 4], sb + r * 128 + (((2 * kc + asel) ^ (r & 7)) << 4));
                ldsm4(&Ql[kc * 4], sb + 8192 + r * 128 + (((2 * kc + asel) ^ (r & 7)) << 4));
            }
        }
        uint32_t kb = sb + 16384 + (t & 1) * 16384;
        float acc[8][4];
#pragma unroll
        for (int nt = 0; nt < 8; nt++)
#pragma unroll
            for (int r = 0; r < 4; r++) acc[nt][r] = 0.f;

#pragma unroll
        for (int kc = 0; kc < 4; kc++) {
            uint32_t Bh[16], Bl[16];
#pragma unroll
            for (int nt2 = 0; nt2 < 4; nt2++) {
                int rr = nt2 * 16 + brow;
                ldsm4(&Bh[nt2 * 4], kb + rr * 128 + (((2 * kc + bsel) ^ (rr & 7)) << 4));
                ldsm4(&Bl[nt2 * 4], kb + 8192 + rr * 128 + (((2 * kc + bsel) ^ (rr & 7)) << 4));
            }
#pragma unroll
            for (int nt = 0; nt < 8; nt++)
                mma_fp16(acc[nt], &Qh[kc * 4], &Bh[(nt >> 1) * 4 + (nt & 1) * 2]);
#pragma unroll
            for (int nt = 0; nt < 8; nt++)
                mma_fp16(acc[nt], &Qh[kc * 4], &Bl[(nt >> 1) * 4 + (nt & 1) * 2]);
#pragma unroll
            for (int nt = 0; nt < 8; nt++)
                mma_fp16(acc[nt], &Ql[kc * 4], &Bh[(nt >> 1) * 4 + (nt & 1) * 2]);
        }

        bool dtile = (t == bx);
#pragma unroll
        for (int r = 0; r < 2; r++) {
            int il = w * 16 + g_ + r * 8;
            float tm = -1e30f;
            float vals[16];
#pragma unroll
            for (int nt = 0; nt < 8; nt++)
#pragma unroll
                for (int c = 0; c < 2; c++) {
                    float v = acc[nt][r * 2 + c];
                    if (dtile) {
                        int jl = nt * 8 + tig * 2 + c;
                        if (jl == il) sd[r] = v;
                        if (jl > il) v = -1e30f;
                    }
                    vals[nt * 2 + c] = v;
                    tm = fmaxf(tm, v);
                }
            float mn = fmaxf(m[r], tm);
            float sc = exp2f((m[r] - mn) * L2E);
            float ls = 0.f;
#pragma unroll
            for (int i = 0; i < 16; i++) ls += exp2f((vals[i] - mn) * L2E);
            l[r] = l[r] * sc + ls;
            m[r] = mn;
        }
        __syncthreads();
        if (t + 2 <= bx) { issueK(t + 2, t & 1); asm volatile("cp.async.commit_group;"); }
    }

#pragma unroll
    for (int r = 0; r < 2; r++) {
        float mm = m[r], ll = l[r], ss = sd[r];
#pragma unroll
        for (int o = 1; o <= 2; o <<= 1) {
            float mo = __shfl_xor_sync(0xffffffffu, mm, o);
            float lo = __shfl_xor_sync(0xffffffffu, ll, o);
            float so = __shfl_xor_sync(0xffffffffu, ss, o);
            float mn = fmaxf(mm, mo);
            ll = ll * exp2f((mm - mn) * L2E) + lo * exp2f((mo - mn) * L2E);
            mm = mn;
            ss = fmaxf(ss, so);
        }
        if (tig == 0) {
            int rl = w * 16 + g_ + r * 8;
            float dv = (i0 + rl < len) ? exp2f((ss - mm) * L2E) / ll : 0.f;
            sdiag[rl] = dv;
        }
    }
    __syncthreads();

    // fused epilogue: v *= diag, single plane, in place
#pragma unroll
    for (int it = 0; it < 4; it++) {
        int idx = it * 128 + tid;
        int row = idx >> 3, c8 = (idx & 7) * 8;
        size_t off = vbase + (size_t)row * DD + c8;
        uint4 hv = *(uint4*)&vh[off];
        float dv = sdiag[row];
        __half2* hp = (__half2*)&hv;
        uint4 ho;
        __half2* hop = (__half2*)&ho;
#pragma unroll
        for (int j = 0; j < 4; j++) {
            hop[j] = {__float2half(dv * __half2float(hp[j].x)),
                      __float2half(dv * __half2float(hp[j].y))};
        }
        *(uint4*)&vh[off] = ho;
    }
}

// ---------------- LayerNorm(a + r) -----------------------------------------------
// a given as fp16 hi/lo planes; r fp32. SPLIT: emit fp16 hi/lo. OUTF: emit fp32.
template<bool SPLIT, bool OUTF>
__global__ __launch_bounds__(256)
void ln_kernel(const __half* __restrict__ ah, const __half* __restrict__ al,
               const float* __restrict__ r,
               const float* __restrict__ gamma, const float* __restrict__ beta,
               float* __restrict__ out,
               __half* __restrict__ oh, __half* __restrict__ ol)
{
    int row = blockIdx.x;
    int tid = threadIdx.x;
    size_t base = (size_t)row * DD;

    float a0 = __half2float(ah[base + tid]) + __half2float(al[base + tid]);
    float a1 = __half2float(ah[base + tid + 256]) + __half2float(al[base + tid + 256]);
    float v0 = a0 + r[base + tid];
    float v1 = a1 + r[base + tid + 256];

    __shared__ float sred[8];
    __shared__ float smean, srstd;

    float s = v0 + v1;
#pragma unroll
    for (int o = 16; o > 0; o >>= 1) s += __shfl_xor_sync(0xffffffffu, s, o);
    if ((tid & 31) == 0) sred[tid >> 5] = s;
    __syncthreads();
    if (tid == 0) {
        float t = 0.f;
#pragma unroll
        for (int i = 0; i < 8; i++) t += sred[i];
        smean = t * (1.0f / DD);
    }
    __syncthreads();
    float mean = smean;
    float d0 = v0 - mean, d1 = v1 - mean;
    float vs = d0 * d0 + d1 * d1;
#pragma unroll
    for (int o = 16; o > 0; o >>= 1) vs += __shfl_xor_sync(0xffffffffu, vs, o);
    if ((tid & 31) == 0) sred[tid >> 5] = vs;
    __syncthreads();
    if (tid == 0) {
        float t = 0.f;
#pragma unroll
        for (int i = 0; i < 8; i++) t += sred[i];
        srstd = rsqrtf(t * (1.0f / DD) + 1e-3f);
    }
    __syncthreads();
    float rstd = srstd;
    float o0 = gamma[tid]       * (d0 * rstd) + beta[tid];
    float o1 = gamma[tid + 256] * (d1 * rstd) + beta[tid + 256];
    if (OUTF) {
        out[base + tid]       = o0;
        out[base + tid + 256] = o1;
    }
    if (SPLIT) {
        __half h0, l0, h1, l1;
        split1(o0, h0, l0);
        split1(o1, h1, l1);
        oh[base + tid]       = h0;
        ol[base + tid]       = l0;
        oh[base + tid + 256] = h1;
        ol[base + tid + 256] = l1;
    }
}

// ---------------- launch --------------------------------------------------------
extern "C" void kernel_launch(void* const* d_in, const int* in_sizes, int n_in,
                              void* d_out, int out_size)
{
    const float* x       = (const float*)d_in[0];
    const int*   lengths = (const int*)d_in[1];
    const float* Wq = (const float*)d_in[2];
    const float* bq = (const float*)d_in[3];
    const float* Wk = (const float*)d_in[4];
    const float* bk = (const float*)d_in[5];
    const float* Wv = (const float*)d_in[6];
    const float* bv = (const float*)d_in[7];
    const float* Wo = (const float*)d_in[8];
    const float* bo = (const float*)d_in[9];
    const float* W1 = (const float*)d_in[10];
    const float* b1 = (const float*)d_in[11];
    const float* W2 = (const float*)d_in[12];
    const float* b2 = (const float*)d_in[13];
    const float* gamma1 = (const float*)d_in[14];
    const float* beta1  = (const float*)d_in[15];
    const float* gamma2 = (const float*)d_in[16];
    const float* beta2  = (const float*)d_in[17];

    float *ao, *f2, *bqkv;
    __half *xh, *xl, *qh, *ql, *kh, *kl, *wvh, *y1h, *y1l, *h1h;
    __half *wqkvt, *wot, *w1t, *w2t;
    cudaGetSymbolAddress((void**)&ao,   g_ao);
    cudaGetSymbolAddress((void**)&f2,   g_f2);
    cudaGetSymbolAddress((void**)&bqkv, g_bqkv);
    cudaGetSymbolAddress((void**)&xh,   g_xh);
    cudaGetSymbolAddress((void**)&xl,   g_xl);
    cudaGetSymbolAddress((void**)&qh,   g_qh);
    cudaGetSymbolAddress((void**)&ql,   g_ql);
    cudaGetSymbolAddress((void**)&kh,   g_kh);
    cudaGetSymbolAddress((void**)&kl,   g_kl);
    cudaGetSymbolAddress((void**)&wvh,  g_wvh);
    cudaGetSymbolAddress((void**)&y1h,  g_y1h);
    cudaGetSymbolAddress((void**)&y1l,  g_y1l);
    cudaGetSymbolAddress((void**)&h1h,  g_h1h);
    cudaGetSymbolAddress((void**)&wqkvt, g_wqkvt);
    cudaGetSymbolAddress((void**)&wot,  g_wot);
    cudaGetSymbolAddress((void**)&w1t,  g_w1t);
    cudaGetSymbolAddress((void**)&w2t,  g_w2t);

    const int SM_AP2 = 2 * 3 * 16384;   // 96 KB
    const int SM_AP1 = 2 * 2 * 16384;   // 64 KB
    cudaFuncSetAttribute((const void*)hgemm<3,2>, cudaFuncAttributeMaxDynamicSharedMemorySize, SM_AP2);
    cudaFuncSetAttribute((const void*)hgemm<0,1>, cudaFuncAttributeMaxDynamicSharedMemorySize, SM_AP1);
    cudaFuncSetAttribute((const void*)hgemm<1,1>, cudaFuncAttributeMaxDynamicSharedMemorySize, SM_AP1);
    cudaFuncSetAttribute((const void*)attn_diag_hmma, cudaFuncAttributeMaxDynamicSharedMemorySize, SMEM_ATTN);

    int n4 = (MM * DD) / 4;
    mask_split_kernel<<<(n4 + 255) / 256, 256>>>(x, lengths, xh, xl);

    dim3 tb(32, 8);
    transpose_half4_kernel<<<dim3(DD/32, DD/32, 4), tb>>>(
        Wq, Wk, Wv, Wo,
        wqkvt, wqkvt + DD*DD, wqkvt + 2*DD*DD, wot);
    transpose_half_ff_kernel<<<dim3(FFD/32, DD/32, 2), tb>>>(W1, W2, w1t, w2t);
    concat_bias_kernel<<<6, 256>>>(bq, bk, bv, bqkv);

    dim3 g512(DD / 128, MM / 128);       // (4, 32)
    dim3 gQKV(3 * DD / 128, MM / 128);   // (12, 32)
    dim3 gFF (FFD / 128, MM / 128);      // (16, 32)

    // fused QKV (2-pass): q,k hi/lo planes; v single plane; padded tiles -> bias
    hgemm<3,2><<<gQKV, 256, SM_AP2>>>(xh, xl, wqkvt, bqkv,
                                      nullptr, qh, ql, kh, kl, wvh,
                                      lengths, 1, MM, 3 * DD, DD, DD);

    // attention diag + in-place v *= diag
    attn_diag_hmma<<<dim3(SS / 64, HH, BB), 128, SMEM_ATTN>>>(qh, ql, kh, kl, wvh, lengths);

    // Wo (1-pass)
    hgemm<0,1><<<g512, 256, SM_AP1>>>(wvh, nullptr, wot, bo,
                                      ao, nullptr, nullptr, nullptr, nullptr, nullptr,
                                      lengths, 1, MM, DD, DD, DD);

    // ln1: LN(x + ao) -> fp16 hi/lo planes
    ln_kernel<true, false><<<MM, 256>>>(xh, xl, ao, gamma1, beta1, nullptr, y1h, y1l);

    // W1 (1-pass, relu, single-plane out)
    hgemm<1,1><<<gFF, 256, SM_AP1>>>(y1h, nullptr, w1t, b1,
                                     nullptr, h1h, nullptr, nullptr, nullptr, nullptr,
                                     lengths, 2, MM, FFD, DD, FFD);
    // W2 (1-pass)
    hgemm<0,1><<<g512, 256, SM_AP1>>>(h1h, nullptr, w2t, b2,
                                      f2, nullptr, nullptr, nullptr, nullptr, nullptr,
                                      lengths, 2, MM, DD, FFD, DD);

    // ln2: LN(y1 + f2) -> fp32 output
    ln_kernel<false, true><<<MM, 256>>>(y1h, y1l, f2, gamma2, beta2,
                                        (float*)d_out, nullptr, nullptr);
}

// round 14
// speedup vs baseline: 6.0835x; 1.0888x over previous
#include <cuda_runtime.h>
#include <cuda_fp16.h>
#include <math.h>
#include <stdint.h>

#define BB 2
#define SS 2048
#define DD 512
#define HH 8
#define DK 64
#define FFD 2048
#define MM (BB*SS)          // 4096 rows
#define L2E 1.4426950408889634f

// ---------------- scratch (static device arrays; no runtime alloc) -------------
__device__ float g_ao[MM*DD];
__device__ float g_f2[MM*DD];
__device__ float g_bqkv[3*DD];
// fp16 planes
__device__ __half g_xh [MM*DD],  g_xl [MM*DD];
__device__ __half g_qh [MM*DD],  g_ql [MM*DD];
__device__ __half g_kh [MM*DD];                 // k single plane
__device__ __half g_wvh[MM*DD];                 // v single plane, scaled in place by attn
__device__ __half g_y1h[MM*DD],  g_y1l[MM*DD];  // hi/lo kept for residual accuracy
__device__ __half g_h1h[MM*FFD];                // single plane
// transposed weights [N, K], single fp16 plane
__device__ __half g_wqkvt[3*DD*DD];
__device__ __half g_wot[DD*DD];
__device__ __half g_w1t[FFD*DD];
__device__ __half g_w2t[DD*FFD];

// ---------------- PTX helpers ---------------------------------------------------
__device__ __forceinline__ uint32_t smem_u32(const void* p) {
    uint32_t a;
    asm("{ .reg .u64 t; cvta.to.shared.u64 t, %1; cvt.u32.u64 %0, t; }" : "=r"(a) : "l"(p));
    return a;
}
__device__ __forceinline__ void mma_fp16(float* c, const uint32_t* a, const uint32_t* b) {
    asm volatile(
        "mma.sync.aligned.m16n8k16.row.col.f32.f16.f16.f32 "
        "{%0,%1,%2,%3},{%4,%5,%6,%7},{%8,%9},{%0,%1,%2,%3};"
        : "+f"(c[0]), "+f"(c[1]), "+f"(c[2]), "+f"(c[3])
        : "r"(a[0]), "r"(a[1]), "r"(a[2]), "r"(a[3]), "r"(b[0]), "r"(b[1]));
}
__device__ __forceinline__ void ldsm4(uint32_t* r, uint32_t addr) {
    asm volatile("ldmatrix.sync.aligned.m8n8.x4.shared.b16 {%0,%1,%2,%3},[%4];"
                 : "=r"(r[0]), "=r"(r[1]), "=r"(r[2]), "=r"(r[3]) : "r"(addr));
}
__device__ __forceinline__ void cpa16(uint32_t dst, const void* src) {
    asm volatile("cp.async.cg.shared.global [%0],[%1],16;" :: "r"(dst), "l"(src));
}
__device__ __forceinline__ void split1(float a, __half& h, __half& l) {
    h = __float2half(a);
    l = __float2half(a - __half2float(h));
}

// ---------------- all weight transposes in ONE launch -----------------------------
// z 0..3: DD x DD squares (Wq, Wk, Wv, Wo); z=4: W1 [DD,FFD]; z=5: W2 [FFD,DD]
// grid (FFD/32=64, DD/32=16, 6); square z uses x<16 only
__global__ __launch_bounds__(256)
void transpose_all_kernel(const float* __restrict__ Wq, const float* __restrict__ Wk,
                          const float* __restrict__ Wv, const float* __restrict__ Wo,
                          const float* __restrict__ W1, const float* __restrict__ W2,
                          __half* __restrict__ oqkv, __half* __restrict__ oo,
                          __half* __restrict__ o1, __half* __restrict__ o2)
{
    int z = blockIdx.z;
    const float* in;
    __half* oh;
    int R, C, bxi, byi;
    if (z < 4) {
        if (blockIdx.x >= 16) return;
        in = (z == 0) ? Wq : (z == 1) ? Wk : (z == 2) ? Wv : Wo;
        oh = (z < 3) ? (oqkv + (size_t)z * DD * DD) : oo;
        R = DD; C = DD; bxi = blockIdx.x; byi = blockIdx.y;
    } else if (z == 4) {
        in = W1; oh = o1; R = DD; C = FFD;
        bxi = blockIdx.x; byi = blockIdx.y;
    } else {
        in = W2; oh = o2; R = FFD; C = DD;
        bxi = blockIdx.y; byi = blockIdx.x;
    }
    __shared__ float t[32][33];
    int bx = bxi * 32, by = byi * 32;
    int tx = threadIdx.x, ty = threadIdx.y;   // (32, 8)
#pragma unroll
    for (int i = 0; i < 32; i += 8)
        t[ty + i][tx] = in[(size_t)(by + ty + i) * C + bx + tx];
    __syncthreads();
#pragma unroll
    for (int i = 0; i < 32; i += 8)
        oh[(size_t)(bx + ty + i) * R + by + tx] = __float2half(t[tx][ty + i]);
}

// ---------------- pad-mask + split + bias concat (tail blocks) --------------------
#define N4 ((MM*DD)/4)
__global__ void mask_split_kernel(const float* __restrict__ x, const int* __restrict__ lengths,
                                  __half* __restrict__ xh, __half* __restrict__ xl,
                                  const float* __restrict__ bq, const float* __restrict__ bk,
                                  const float* __restrict__ bv, float* __restrict__ bqkv)
{
    int i = blockIdx.x * blockDim.x + threadIdx.x;
    if (i >= N4) {
        int j = i - N4;                       // float4 index into bqkv (0..383)
        if (j < 384) {
            const float* src = (j < 128) ? bq : (j < 256) ? bk : bv;
            int jj = j & 127;
            ((float4*)bqkv)[j] = ((const float4*)src)[jj];
        }
        return;
    }
    int row = (i * 4) / DD;
    int s = row & (SS - 1);
    int b = row >> 11;
    float4 val = ((const float4*)x)[i];
    if (s >= lengths[b]) val = make_float4(0.f, 0.f, 0.f, 0.f);
    __half h0, l0, h1, l1, h2, l2, h3, l3;
    split1(val.x, h0, l0); split1(val.y, h1, l1);
    split1(val.z, h2, l2); split1(val.w, h3, l3);
    __half2* ph = (__half2*)&xh[i * 4];
    __half2* pl = (__half2*)&xl[i * 4];
    ph[0] = {h0, h1}; ph[1] = {h2, h3};
    pl[0] = {l0, l1}; pl[1] = {l2, l3};
}

// ---------------- HMMA fp16 GEMM (AP = activation passes: 1 or 2) ----------------
// C[M,N] = (Ah[+Al])[M,K] @ Bh[N,K]^T + bias
// tile 128x128, BK=64, 2-stage cp.async, 8 warps 64x32
// MODE 0: fp32 out  MODE 1: relu + fp16 single plane out
// MODE 3: qkv -> q hi/lo planes; k,v single plane
// skipmode 0: none  1: padded tile -> C=bias  2: padded tile -> 16-row compute+bcast

template<int MTN, bool RED, int AP>
__device__ __forceinline__ void gemm_tiles(uint32_t base, int arow, int asel,
                                           int brow, int bsel, int rx, int wm, int wn,
                                           float acc[4][4][4])
{
    constexpr uint32_t BO = AP * 16384u;
#pragma unroll
    for (int s = 0; s < 4; s++) {
        uint32_t Ahf[MTN * 4], Alf[MTN * 4], Bhf[8];
#pragma unroll
        for (int mt = 0; mt < MTN; mt++) {
            uint32_t ro = base + ((RED ? 0 : wm * 64 + mt * 16) + arow) * 128;
            uint32_t sw = ((2 * s + asel) ^ rx) << 4;
            ldsm4(&Ahf[mt * 4], ro + sw);
            if (AP == 2) ldsm4(&Alf[mt * 4], ro + 16384 + sw);
        }
#pragma unroll
        for (int nt2 = 0; nt2 < 2; nt2++) {
            uint32_t ro = base + BO + (wn * 32 + nt2 * 16 + brow) * 128;
            ldsm4(&Bhf[nt2 * 4], ro + (((2 * s + bsel) ^ rx) << 4));
        }
#pragma unroll
        for (int mt = 0; mt < MTN; mt++)
#pragma unroll
            for (int nt = 0; nt < 4; nt++)
                mma_fp16(acc[mt][nt], &Ahf[mt * 4], &Bhf[(nt >> 1) * 4 + (nt & 1) * 2]);
        if (AP == 2) {
#pragma unroll
            for (int mt = 0; mt < MTN; mt++)
#pragma unroll
                for (int nt = 0; nt < 4; nt++)
                    mma_fp16(acc[mt][nt], &Alf[mt * 4], &Bhf[(nt >> 1) * 4 + (nt & 1) * 2]);
        }
    }
}

template<int MODE, int AP>
__global__ __launch_bounds__(256, 1)
void hgemm(const __half* __restrict__ Ah, const __half* __restrict__ Al,
           const __half* __restrict__ Bh,
           const float* __restrict__ bias,
           float* __restrict__ C, __half* __restrict__ Ch, __half* __restrict__ Cl,
           __half* __restrict__ Dh, __half* __restrict__ Eh,
           const int* __restrict__ lengths, int skipmode,
           int M, int N, int K, int OD)
{
    constexpr uint32_t BO  = AP * 16384u;
    constexpr uint32_t STG = (AP + 1) * 16384u;
    extern __shared__ char smem[];
    uint32_t sb = smem_u32(smem);
    int tid = threadIdx.x, lane = tid & 31, wid = tid >> 5;
    int bm = blockIdx.y * 128, bn = blockIdx.x * 128;
    int wm = wid & 1, wn = wid >> 1;
    int NK = K >> 6;

    bool padded = false;
    if (skipmode) {
        int b = bm >> 11;
        int s0 = bm & (SS - 1);
        padded = (s0 >= lengths[b]);
    }
    bool skipall = (skipmode == 1) && padded;
    bool reduced = (skipmode == 2) && padded;

    float acc[4][4][4];
#pragma unroll
    for (int i = 0; i < 4; i++)
#pragma unroll
        for (int j = 0; j < 4; j++)
#pragma unroll
            for (int r = 0; r < 4; r++) acc[i][j][r] = 0.f;

    int arow = (lane & 7) + ((lane >> 3) & 1) * 8;
    int asel = lane >> 4;
    int brow = (lane & 7) + (lane >> 4) * 8;
    int bsel = (lane >> 3) & 1;
    int rx = lane & 7;

    if (!skipall) {
        auto issue = [&](int kt) {
            uint32_t base = sb + (kt & 1) * STG;
            int k0 = kt << 6;
            if (reduced) {
                if (tid < 128) {
                    int row = tid >> 3, c = tid & 7;
                    cpa16(base + row * 128 + ((c ^ (row & 7)) << 4),
                          Ah + (size_t)(bm + row) * K + k0 + c * 8);
                } else if (AP == 2 && tid < 256) {
                    int t2 = tid - 128;
                    int row = t2 >> 3, c = t2 & 7;
                    cpa16(base + 16384 + row * 128 + ((c ^ (row & 7)) << 4),
                          Al + (size_t)(bm + row) * K + k0 + c * 8);
                }
            } else {
#pragma unroll
                for (int i = 0; i < 4; i++) {
                    int idx = i * 256 + tid;
                    int row = idx >> 3, c = idx & 7;
                    uint32_t sw = row * 128 + ((c ^ (row & 7)) << 4);
                    cpa16(base + sw, Ah + (size_t)(bm + row) * K + k0 + c * 8);
                    if (AP == 2)
                        cpa16(base + 16384 + sw, Al + (size_t)(bm + row) * K + k0 + c * 8);
                }
            }
#pragma unroll
            for (int i = 0; i < 4; i++) {
                int idx = i * 256 + tid;
                int row = idx >> 3, c = idx & 7;
                cpa16(base + BO + row * 128 + ((c ^ (row & 7)) << 4),
                      Bh + (size_t)(bn + row) * K + k0 + c * 8);
            }
            asm volatile("cp.async.commit_group;");
        };

        issue(0);
        if (NK > 1) issue(1);

        for (int kt = 0; kt < NK; kt++) {
            if (kt == NK - 1) asm volatile("cp.async.wait_group 0;");
            else              asm volatile("cp.async.wait_group 1;");
            __syncthreads();
            uint32_t base = sb + (kt & 1) * STG;
            if (reduced) gemm_tiles<1, true,  AP>(base, arow, asel, brow, bsel, rx, wm, wn, acc);
            else         gemm_tiles<4, false, AP>(base, arow, asel, brow, bsel, rx, wm, wn, acc);
            __syncthreads();
            if (kt + 2 < NK) issue(kt + 2);
        }

        if (reduced) {
#pragma unroll
            for (int mt = 1; mt < 4; mt++)
#pragma unroll
                for (int nt = 0; nt < 4; nt++)
#pragma unroll
                    for (int r = 0; r < 4; r++) acc[mt][nt][r] = acc[0][nt][r];
        }
    }

    // epilogue
    int g = lane >> 2, tig = lane & 3;
    int seg = (MODE == 3) ? (bn >> 9) : 0;   // 0: q, 1: k, 2: v
#pragma unroll
    for (int mt = 0; mt < 4; mt++) {
#pragma unroll
        for (int nt = 0; nt < 4; nt++) {
            int colg = bn + wn * 32 + nt * 8 + tig * 2;
            float2 bv = *(const float2*)&bias[colg];
            int r0 = bm + wm * 64 + mt * 16 + g;
            float x0 = acc[mt][nt][0] + bv.x, x1 = acc[mt][nt][1] + bv.y;
            float x2 = acc[mt][nt][2] + bv.x, x3 = acc[mt][nt][3] + bv.y;
            if (MODE == 0) {
                float2 o0 = {x0, x1}, o1 = {x2, x3};
                *(float2*)&C[(size_t)r0 * OD + colg] = o0;
                *(float2*)&C[(size_t)(r0 + 8) * OD + colg] = o1;
            } else if (MODE == 1) {
                x0 = fmaxf(x0, 0.f); x1 = fmaxf(x1, 0.f);
                x2 = fmaxf(x2, 0.f); x3 = fmaxf(x3, 0.f);
                __half2 hh0 = {__float2half(x0), __float2half(x1)};
                __half2 hh1 = {__float2half(x2), __float2half(x3)};
                *(__half2*)&Ch[(size_t)r0 * OD + colg] = hh0;
                *(__half2*)&Ch[(size_t)(r0 + 8) * OD + colg] = hh1;
            } else {  // MODE 3
                int col = colg & 511;
                if (seg == 0) {
                    __half h0, l0, h1, l1, h2, l2, h3, l3;
                    split1(x0, h0, l0); split1(x1, h1, l1);
                    split1(x2, h2, l2); split1(x3, h3, l3);
                    __half2 hh0 = {h0, h1}, ll0 = {l0, l1};
                    __half2 hh1 = {h2, h3}, ll1 = {l2, l3};
                    *(__half2*)&Ch[(size_t)r0 * OD + col] = hh0;
                    *(__half2*)&Cl[(size_t)r0 * OD + col] = ll0;
                    *(__half2*)&Ch[(size_t)(r0 + 8) * OD + col] = hh1;
                    *(__half2*)&Cl[(size_t)(r0 + 8) * OD + col] = ll1;
                } else {
                    __half* oh = (seg == 1) ? Dh : Eh;
                    __half2 hh0 = {__float2half(x0), __float2half(x1)};
                    __half2 hh1 = {__float2half(x2), __float2half(x3)};
                    *(__half2*)&oh[(size_t)r0 * OD + col] = hh0;
                    *(__half2*)&oh[(size_t)(r0 + 8) * OD + col] = hh1;
                }
            }
        }
    }
}

// ---------------- attention diag via HMMA (fp16 2-pass, K single plane) ----------
// q hi/lo planes [0,16384); K double-buffer single plane at 16384 + buf*8192
#define SMEM_ATTN 32768
__global__ __launch_bounds__(128, 1)
void attn_diag_hmma(const __half* __restrict__ qh, const __half* __restrict__ ql,
                    const __half* __restrict__ kh,
                    __half* vh,
                    const int* __restrict__ lengths)
{
    extern __shared__ char sm[];
    uint32_t sb = smem_u32(sm);
    float* sdiag = (float*)sm;
    int bx = (int)gridDim.x - 1 - (int)blockIdx.x;
    int h = blockIdx.y, b = blockIdx.z;
    int tid = threadIdx.x, lane = tid & 31, w = tid >> 5;
    int i0 = bx * 64;
    int len = lengths[b];
    const size_t vbase = ((size_t)(b * SS + i0)) * DD + h * DK;

    if (i0 >= len) {
        uint4 z = make_uint4(0, 0, 0, 0);
#pragma unroll
        for (int it = 0; it < 4; it++) {
            int idx = it * 128 + tid;
            int row = idx >> 3, c8 = (idx & 7) * 8;
            *(uint4*)&vh[vbase + (size_t)row * DD + c8] = z;
        }
        return;
    }

    const size_t qg = vbase;
#pragma unroll
    for (int i = 0; i < 4; i++) {
        int idx = i * 128 + tid;
        int row = idx >> 3, c = idx & 7;
        cpa16(sb + row * 128 + ((c ^ (row & 7)) << 4), qh + qg + (size_t)row * DD + c * 8);
    }
#pragma unroll
    for (int i = 0; i < 4; i++) {
        int idx = i * 128 + tid;
        int row = idx >> 3, c = idx & 7;
        cpa16(sb + 8192 + row * 128 + ((c ^ (row & 7)) << 4), ql + qg + (size_t)row * DD + c * 8);
    }
    auto issueK = [&](int t, int buf) {
        uint32_t kb = sb + 16384 + buf * 8192;
        size_t g = ((size_t)(b * SS + t * 64)) * DD + h * DK;
#pragma unroll
        for (int i = 0; i < 4; i++) {
            int idx = i * 128 + tid;
            int row = idx >> 3, c = idx & 7;
            cpa16(kb + row * 128 + ((c ^ (row & 7)) << 4), kh + g + (size_t)row * DD + c * 8);
        }
    };
    issueK(0, 0);
    asm volatile("cp.async.commit_group;");
    if (bx >= 1) { issueK(1, 1); asm volatile("cp.async.commit_group;"); }

    int arow = (lane & 7) + ((lane >> 3) & 1) * 8;
    int asel = lane >> 4;
    int brow = (lane & 7) + (lane >> 4) * 8;
    int bsel = (lane >> 3) & 1;
    int g_ = lane >> 2, tig = lane & 3;

    uint32_t Qh[16], Ql[16];
    float m[2] = {-1e30f, -1e30f}, l[2] = {0.f, 0.f}, sd[2] = {-1e30f, -1e30f};

    for (int t = 0; t <= bx; t++) {
        if (t < bx) asm volatile("cp.async.wait_group 1;");
        else        asm volatile("cp.async.wait_group 0;");
        __syncthreads();
        if (t == 0) {
            int r = w * 16 + arow;
#pragma unroll
            for (int kc = 0; kc < 4; kc++) {
                ldsm4(&Qh[kc * 4], sb + r * 128 + (((2 * kc + asel) ^ (r & 7)) << 4));
                ldsm4(&Ql[kc * 4], sb + 8192 + r * 128 + (((2 * kc + asel) ^ (r & 7)) << 4));
            }
        }
        uint32_t kb = sb + 16384 + (t & 1) * 8192;
        float acc[8][4];
#pragma unroll
        for (int nt = 0; nt < 8; nt++)
#pragma unroll
            for (int r = 0; r < 4; r++) acc[nt][r] = 0.f;

#pragma unroll
        for (int kc = 0; kc < 4; kc++) {
            uint32_t Bh[16];
#pragma unroll
            for (int nt2 = 0; nt2 < 4; nt2++) {
                int rr = nt2 * 16 + brow;
                ldsm4(&Bh[nt2 * 4], kb + rr * 128 + (((2 * kc + bsel) ^ (rr & 7)) << 4));
            }
#pragma unroll
            for (int nt = 0; nt < 8; nt++)
                mma_fp16(acc[nt], &Qh[kc * 4], &Bh[(nt >> 1) * 4 + (nt & 1) * 2]);
#pragma unroll
            for (int nt = 0; nt < 8; nt++)
                mma_fp16(acc[nt], &Ql[kc * 4], &Bh[(nt >> 1) * 4 + (nt & 1) * 2]);
        }

        bool dtile = (t == bx);
#pragma unroll
        for (int r = 0; r < 2; r++) {
            int il = w * 16 + g_ + r * 8;
            float tm = -1e30f;
            float vals[16];
#pragma unroll
            for (int nt = 0; nt < 8; nt++)
#pragma unroll
                for (int c = 0; c < 2; c++) {
                    float v = acc[nt][r * 2 + c];
                    if (dtile) {
                        int jl = nt * 8 + tig * 2 + c;
                        if (jl == il) sd[r] = v;
                        if (jl > il) v = -1e30f;
                    }
                    vals[nt * 2 + c] = v;
                    tm = fmaxf(tm, v);
                }
            float mn = fmaxf(m[r], tm);
            float sc = exp2f((m[r] - mn) * L2E);
            float ls = 0.f;
#pragma unroll
            for (int i = 0; i < 16; i++) ls += exp2f((vals[i] - mn) * L2E);
            l[r] = l[r] * sc + ls;
            m[r] = mn;
        }
        __syncthreads();
        if (t + 2 <= bx) { issueK(t + 2, t & 1); asm volatile("cp.async.commit_group;"); }
    }

#pragma unroll
    for (int r = 0; r < 2; r++) {
        float mm = m[r], ll = l[r], ss = sd[r];
#pragma unroll
        for (int o = 1; o <= 2; o <<= 1) {
            float mo = __shfl_xor_sync(0xffffffffu, mm, o);
            float lo = __shfl_xor_sync(0xffffffffu, ll, o);
            float so = __shfl_xor_sync(0xffffffffu, ss, o);
            float mn = fmaxf(mm, mo);
            ll = ll * exp2f((mm - mn) * L2E) + lo * exp2f((mo - mn) * L2E);
            mm = mn;
            ss = fmaxf(ss, so);
        }
        if (tig == 0) {
            int rl = w * 16 + g_ + r * 8;
            float dv = (i0 + rl < len) ? exp2f((ss - mm) * L2E) / ll : 0.f;
            sdiag[rl] = dv;
        }
    }
    __syncthreads();

    // fused epilogue: v *= diag, single plane, in place
#pragma unroll
    for (int it = 0; it < 4; it++) {
        int idx = it * 128 + tid;
        int row = idx >> 3, c8 = (idx & 7) * 8;
        size_t off = vbase + (size_t)row * DD + c8;
        uint4 hv = *(uint4*)&vh[off];
        float dv = sdiag[row];
        __half2* hp = (__half2*)&hv;
        uint4 ho;
        __half2* hop = (__half2*)&ho;
#pragma unroll
        for (int j = 0; j < 4; j++) {
            hop[j] = {__float2half(dv * __half2float(hp[j].x)),
                      __float2half(dv * __half2float(hp[j].y))};
        }
        *(uint4*)&vh[off] = ho;
    }
}

// ---------------- LayerNorm(a + r) -----------------------------------------------
template<bool SPLIT, bool OUTF>
__global__ __launch_bounds__(256)
void ln_kernel(const __half* __restrict__ ah, const __half* __restrict__ al,
               const float* __restrict__ r,
               const float* __restrict__ gamma, const float* __restrict__ beta,
               float* __restrict__ out,
               __half* __restrict__ oh, __half* __restrict__ ol)
{
    int row = blockIdx.x;
    int tid = threadIdx.x;
    size_t base = (size_t)row * DD;

    float a0 = __half2float(ah[base + tid]) + __half2float(al[base + tid]);
    float a1 = __half2float(ah[base + tid + 256]) + __half2float(al[base + tid + 256]);
    float v0 = a0 + r[base + tid];
    float v1 = a1 + r[base + tid + 256];

    __shared__ float sred[8];
    __shared__ float smean, srstd;

    float s = v0 + v1;
#pragma unroll
    for (int o = 16; o > 0; o >>= 1) s += __shfl_xor_sync(0xffffffffu, s, o);
    if ((tid & 31) == 0) sred[tid >> 5] = s;
    __syncthreads();
    if (tid == 0) {
        float t = 0.f;
#pragma unroll
        for (int i = 0; i < 8; i++) t += sred[i];
        smean = t * (1.0f / DD);
    }
    __syncthreads();
    float mean = smean;
    float d0 = v0 - mean, d1 = v1 - mean;
    float vs = d0 * d0 + d1 * d1;
#pragma unroll
    for (int o = 16; o > 0; o >>= 1) vs += __shfl_xor_sync(0xffffffffu, vs, o);
    if ((tid & 31) == 0) sred[tid >> 5] = vs;
    __syncthreads();
    if (tid == 0) {
        float t = 0.f;
#pragma unroll
        for (int i = 0; i < 8; i++) t += sred[i];
        srstd = rsqrtf(t * (1.0f / DD) + 1e-3f);
    }
    __syncthreads();
    float rstd = srstd;
    float o0 = gamma[tid]       * (d0 * rstd) + beta[tid];
    float o1 = gamma[tid + 256] * (d1 * rstd) + beta[tid + 256];
    if (OUTF) {
        out[base + tid]       = o0;
        out[base + tid + 256] = o1;
    }
    if (SPLIT) {
        __half h0, l0, h1, l1;
        split1(o0, h0, l0);
        split1(o1, h1, l1);
        oh[base + tid]       = h0;
        ol[base + tid]       = l0;
        oh[base + tid + 256] = h1;
        ol[base + tid + 256] = l1;
    }
}

// ---------------- launch --------------------------------------------------------
extern "C" void kernel_launch(void* const* d_in, const int* in_sizes, int n_in,
                              void* d_out, int out_size)
{
    const float* x       = (const float*)d_in[0];
    const int*   lengths = (const int*)d_in[1];
    const float* Wq = (const float*)d_in[2];
    const float* bq = (const float*)d_in[3];
    const float* Wk = (const float*)d_in[4];
    const float* bk = (const float*)d_in[5];
    const float* Wv = (const float*)d_in[6];
    const float* bv = (const float*)d_in[7];
    const float* Wo = (const float*)d_in[8];
    const float* bo = (const float*)d_in[9];
    const float* W1 = (const float*)d_in[10];
    const float* b1 = (const float*)d_in[11];
    const float* W2 = (const float*)d_in[12];
    const float* b2 = (const float*)d_in[13];
    const float* gamma1 = (const float*)d_in[14];
    const float* beta1  = (const float*)d_in[15];
    const float* gamma2 = (const float*)d_in[16];
    const float* beta2  = (const float*)d_in[17];

    float *ao, *f2, *bqkv;
    __half *xh, *xl, *qh, *ql, *kh, *wvh, *y1h, *y1l, *h1h;
    __half *wqkvt, *wot, *w1t, *w2t;
    cudaGetSymbolAddress((void**)&ao,   g_ao);
    cudaGetSymbolAddress((void**)&f2,   g_f2);
    cudaGetSymbolAddress((void**)&bqkv, g_bqkv);
    cudaGetSymbolAddress((void**)&xh,   g_xh);
    cudaGetSymbolAddress((void**)&xl,   g_xl);
    cudaGetSymbolAddress((void**)&qh,   g_qh);
    cudaGetSymbolAddress((void**)&ql,   g_ql);
    cudaGetSymbolAddress((void**)&kh,   g_kh);
    cudaGetSymbolAddress((void**)&wvh,  g_wvh);
    cudaGetSymbolAddress((void**)&y1h,  g_y1h);
    cudaGetSymbolAddress((void**)&y1l,  g_y1l);
    cudaGetSymbolAddress((void**)&h1h,  g_h1h);
    cudaGetSymbolAddress((void**)&wqkvt, g_wqkvt);
    cudaGetSymbolAddress((void**)&wot,  g_wot);
    cudaGetSymbolAddress((void**)&w1t,  g_w1t);
    cudaGetSymbolAddress((void**)&w2t,  g_w2t);

    const int SM_AP2 = 2 * 3 * 16384;   // 96 KB
    const int SM_AP1 = 2 * 2 * 16384;   // 64 KB
    cudaFuncSetAttribute((const void*)hgemm<3,2>, cudaFuncAttributeMaxDynamicSharedMemorySize, SM_AP2);
    cudaFuncSetAttribute((const void*)hgemm<0,1>, cudaFuncAttributeMaxDynamicSharedMemorySize, SM_AP1);
    cudaFuncSetAttribute((const void*)hgemm<1,1>, cudaFuncAttributeMaxDynamicSharedMemorySize, SM_AP1);
    cudaFuncSetAttribute((const void*)attn_diag_hmma, cudaFuncAttributeMaxDynamicSharedMemorySize, SMEM_ATTN);

    // mask+split + bias-concat tail (2 extra blocks)
    mask_split_kernel<<<(N4 + 384 + 255) / 256, 256>>>(x, lengths, xh, xl, bq, bk, bv, bqkv);

    // all 6 weight transposes in one launch
    transpose_all_kernel<<<dim3(FFD/32, DD/32, 6), dim3(32, 8)>>>(
        Wq, Wk, Wv, Wo, W1, W2, wqkvt, wot, w1t, w2t);

    dim3 g512(DD / 128, MM / 128);       // (4, 32)
    dim3 gQKV(3 * DD / 128, MM / 128);   // (12, 32)
    dim3 gFF (FFD / 128, MM / 128);      // (16, 32)

    // fused QKV (2-pass): q hi/lo; k,v single plane; padded tiles -> bias
    hgemm<3,2><<<gQKV, 256, SM_AP2>>>(xh, xl, wqkvt, bqkv,
                                      nullptr, qh, ql, kh, wvh,
                                      lengths, 1, MM, 3 * DD, DD, DD);

    // attention diag (2-pass) + in-place v *= diag
    attn_diag_hmma<<<dim3(SS / 64, HH, BB), 128, SMEM_ATTN>>>(qh, ql, kh, wvh, lengths);

    // Wo (1-pass)
    hgemm<0,1><<<g512, 256, SM_AP1>>>(wvh, nullptr, wot, bo,
                                      ao, nullptr, nullptr, nullptr, nullptr,
                                      lengths, 1, MM, DD, DD, DD);

    // ln1: LN(x + ao) -> fp16 hi/lo planes
    ln_kernel<true, false><<<MM, 256>>>(xh, xl, ao, gamma1, beta1, nullptr, y1h, y1l);

    // W1 (1-pass, relu, single-plane out)
    hgemm<1,1><<<gFF, 256, SM_AP1>>>(y1h, nullptr, w1t, b1,
                                     nullptr, h1h, nullptr, nullptr, nullptr,
                                     lengths, 2, MM, FFD, DD, FFD);
    // W2 (1-pass)
    hgemm<0,1><<<g512, 256, SM_AP1>>>(h1h, nullptr, w2t, b2,
                                      f2, nullptr, nullptr, nullptr, nullptr,
                                      lengths, 2, MM, DD, FFD, DD);

    // ln2: LN(y1 + f2) -> fp32 output
    ln_kernel<false, true><<<MM, 256>>>(y1h, y1l, f2, gamma2, beta2,
                                        (float*)d_out, nullptr, nullptr);
}

// round 15
// speedup vs baseline: 6.2471x; 1.0269x over previous
#include <cuda_runtime.h>
#include <cuda_fp16.h>
#include <math.h>
#include <stdint.h>

#define BB 2
#define SS 2048
#define DD 512
#define HH 8
#define DK 64
#define FFD 2048
#define MM (BB*SS)          // 4096 rows
#define L2E 1.4426950408889634f

// ---------------- scratch (static device arrays; no runtime alloc) -------------
__device__ float g_ao[MM*DD];
__device__ float g_f2[MM*DD];
__device__ float g_bqkv[3*DD];
// fp16 planes
__device__ __half g_xh [MM*DD],  g_xl [MM*DD];
__device__ __half g_qh [MM*DD],  g_ql [MM*DD];
__device__ __half g_kh [MM*DD];                 // k single plane
__device__ __half g_wvh[MM*DD];                 // v single plane, scaled in place by attn
__device__ __half g_y1h[MM*DD],  g_y1l[MM*DD];  // hi/lo kept for residual accuracy
__device__ __half g_h1h[MM*FFD];                // single plane
// transposed weights [N, K], single fp16 plane
__device__ __half g_wqkvt[3*DD*DD];
__device__ __half g_wot[DD*DD];
__device__ __half g_w1t[FFD*DD];
__device__ __half g_w2t[DD*FFD];

// ---------------- PTX helpers ---------------------------------------------------
__device__ __forceinline__ uint32_t smem_u32(const void* p) {
    uint32_t a;
    asm("{ .reg .u64 t; cvta.to.shared.u64 t, %1; cvt.u32.u64 %0, t; }" : "=r"(a) : "l"(p));
    return a;
}
__device__ __forceinline__ void mma_fp16(float* c, const uint32_t* a, const uint32_t* b) {
    asm volatile(
        "mma.sync.aligned.m16n8k16.row.col.f32.f16.f16.f32 "
        "{%0,%1,%2,%3},{%4,%5,%6,%7},{%8,%9},{%0,%1,%2,%3};"
        : "+f"(c[0]), "+f"(c[1]), "+f"(c[2]), "+f"(c[3])
        : "r"(a[0]), "r"(a[1]), "r"(a[2]), "r"(a[3]), "r"(b[0]), "r"(b[1]));
}
__device__ __forceinline__ void ldsm4(uint32_t* r, uint32_t addr) {
    asm volatile("ldmatrix.sync.aligned.m8n8.x4.shared.b16 {%0,%1,%2,%3},[%4];"
                 : "=r"(r[0]), "=r"(r[1]), "=r"(r[2]), "=r"(r[3]) : "r"(addr));
}
__device__ __forceinline__ void cpa16(uint32_t dst, const void* src) {
    asm volatile("cp.async.cg.shared.global [%0],[%1],16;" :: "r"(dst), "l"(src));
}
__device__ __forceinline__ void split1(float a, __half& h, __half& l) {
    h = __float2half(a);
    l = __float2half(a - __half2float(h));
}

// ---------------- all weight transposes in ONE launch -----------------------------
__global__ __launch_bounds__(256)
void transpose_all_kernel(const float* __restrict__ Wq, const float* __restrict__ Wk,
                          const float* __restrict__ Wv, const float* __restrict__ Wo,
                          const float* __restrict__ W1, const float* __restrict__ W2,
                          __half* __restrict__ oqkv, __half* __restrict__ oo,
                          __half* __restrict__ o1, __half* __restrict__ o2)
{
    int z = blockIdx.z;
    const float* in;
    __half* oh;
    int R, C, bxi, byi;
    if (z < 4) {
        if (blockIdx.x >= 16) return;
        in = (z == 0) ? Wq : (z == 1) ? Wk : (z == 2) ? Wv : Wo;
        oh = (z < 3) ? (oqkv + (size_t)z * DD * DD) : oo;
        R = DD; C = DD; bxi = blockIdx.x; byi = blockIdx.y;
    } else if (z == 4) {
        in = W1; oh = o1; R = DD; C = FFD;
        bxi = blockIdx.x; byi = blockIdx.y;
    } else {
        in = W2; oh = o2; R = FFD; C = DD;
        bxi = blockIdx.y; byi = blockIdx.x;
    }
    __shared__ float t[32][33];
    int bx = bxi * 32, by = byi * 32;
    int tx = threadIdx.x, ty = threadIdx.y;   // (32, 8)
#pragma unroll
    for (int i = 0; i < 32; i += 8)
        t[ty + i][tx] = in[(size_t)(by + ty + i) * C + bx + tx];
    __syncthreads();
#pragma unroll
    for (int i = 0; i < 32; i += 8)
        oh[(size_t)(bx + ty + i) * R + by + tx] = __float2half(t[tx][ty + i]);
}

// ---------------- pad-mask + split + bias concat (tail blocks) --------------------
#define N4 ((MM*DD)/4)
__global__ void mask_split_kernel(const float* __restrict__ x, const int* __restrict__ lengths,
                                  __half* __restrict__ xh, __half* __restrict__ xl,
                                  const float* __restrict__ bq, const float* __restrict__ bk,
                                  const float* __restrict__ bv, float* __restrict__ bqkv)
{
    int i = blockIdx.x * blockDim.x + threadIdx.x;
    if (i >= N4) {
        int j = i - N4;
        if (j < 384) {
            const float* src = (j < 128) ? bq : (j < 256) ? bk : bv;
            int jj = j & 127;
            ((float4*)bqkv)[j] = ((const float4*)src)[jj];
        }
        return;
    }
    int row = (i * 4) / DD;
    int s = row & (SS - 1);
    int b = row >> 11;
    float4 val = ((const float4*)x)[i];
    if (s >= lengths[b]) val = make_float4(0.f, 0.f, 0.f, 0.f);
    __half h0, l0, h1, l1, h2, l2, h3, l3;
    split1(val.x, h0, l0); split1(val.y, h1, l1);
    split1(val.z, h2, l2); split1(val.w, h3, l3);
    __half2* ph = (__half2*)&xh[i * 4];
    __half2* pl = (__half2*)&xl[i * 4];
    ph[0] = {h0, h1}; ph[1] = {h2, h3};
    pl[0] = {l0, l1}; pl[1] = {l2, l3};
}

// ---------------- HMMA fp16 GEMM (AP = activation passes: 1 or 2) ----------------
template<int MTN, bool RED, int AP>
__device__ __forceinline__ void gemm_tiles(uint32_t base, int arow, int asel,
                                           int brow, int bsel, int rx, int wm, int wn,
                                           float acc[4][4][4])
{
    constexpr uint32_t BO = AP * 16384u;
#pragma unroll
    for (int s = 0; s < 4; s++) {
        uint32_t Ahf[MTN * 4], Alf[MTN * 4], Bhf[8];
#pragma unroll
        for (int mt = 0; mt < MTN; mt++) {
            uint32_t ro = base + ((RED ? 0 : wm * 64 + mt * 16) + arow) * 128;
            uint32_t sw = ((2 * s + asel) ^ rx) << 4;
            ldsm4(&Ahf[mt * 4], ro + sw);
            if (AP == 2) ldsm4(&Alf[mt * 4], ro + 16384 + sw);
        }
#pragma unroll
        for (int nt2 = 0; nt2 < 2; nt2++) {
            uint32_t ro = base + BO + (wn * 32 + nt2 * 16 + brow) * 128;
            ldsm4(&Bhf[nt2 * 4], ro + (((2 * s + bsel) ^ rx) << 4));
        }
#pragma unroll
        for (int mt = 0; mt < MTN; mt++)
#pragma unroll
            for (int nt = 0; nt < 4; nt++)
                mma_fp16(acc[mt][nt], &Ahf[mt * 4], &Bhf[(nt >> 1) * 4 + (nt & 1) * 2]);
        if (AP == 2) {
#pragma unroll
            for (int mt = 0; mt < MTN; mt++)
#pragma unroll
                for (int nt = 0; nt < 4; nt++)
                    mma_fp16(acc[mt][nt], &Alf[mt * 4], &Bhf[(nt >> 1) * 4 + (nt & 1) * 2]);
        }
    }
}

template<int MODE, int AP>
__global__ __launch_bounds__(256, 1)
void hgemm(const __half* __restrict__ Ah, const __half* __restrict__ Al,
           const __half* __restrict__ Bh,
           const float* __restrict__ bias,
           float* __restrict__ C, __half* __restrict__ Ch, __half* __restrict__ Cl,
           __half* __restrict__ Dh, __half* __restrict__ Eh,
           const int* __restrict__ lengths, int skipmode,
           int M, int N, int K, int OD)
{
    constexpr uint32_t BO  = AP * 16384u;
    constexpr uint32_t STG = (AP + 1) * 16384u;
    extern __shared__ char smem[];
    uint32_t sb = smem_u32(smem);
    int tid = threadIdx.x, lane = tid & 31, wid = tid >> 5;
    int bm = blockIdx.y * 128, bn = blockIdx.x * 128;
    int wm = wid & 1, wn = wid >> 1;
    int NK = K >> 6;

    bool padded = false;
    if (skipmode) {
        int b = bm >> 11;
        int s0 = bm & (SS - 1);
        padded = (s0 >= lengths[b]);
    }
    bool skipall = (skipmode == 1) && padded;
    bool reduced = (skipmode == 2) && padded;

    float acc[4][4][4];
#pragma unroll
    for (int i = 0; i < 4; i++)
#pragma unroll
        for (int j = 0; j < 4; j++)
#pragma unroll
            for (int r = 0; r < 4; r++) acc[i][j][r] = 0.f;

    int arow = (lane & 7) + ((lane >> 3) & 1) * 8;
    int asel = lane >> 4;
    int brow = (lane & 7) + (lane >> 4) * 8;
    int bsel = (lane >> 3) & 1;
    int rx = lane & 7;

    if (!skipall) {
        auto issue = [&](int kt) {
            uint32_t base = sb + (kt & 1) * STG;
            int k0 = kt << 6;
            if (reduced) {
                if (tid < 128) {
                    int row = tid >> 3, c = tid & 7;
                    cpa16(base + row * 128 + ((c ^ (row & 7)) << 4),
                          Ah + (size_t)(bm + row) * K + k0 + c * 8);
                } else if (AP == 2 && tid < 256) {
                    int t2 = tid - 128;
                    int row = t2 >> 3, c = t2 & 7;
                    cpa16(base + 16384 + row * 128 + ((c ^ (row & 7)) << 4),
                          Al + (size_t)(bm + row) * K + k0 + c * 8);
                }
            } else {
#pragma unroll
                for (int i = 0; i < 4; i++) {
                    int idx = i * 256 + tid;
                    int row = idx >> 3, c = idx & 7;
                    uint32_t sw = row * 128 + ((c ^ (row & 7)) << 4);
                    cpa16(base + sw, Ah + (size_t)(bm + row) * K + k0 + c * 8);
                    if (AP == 2)
                        cpa16(base + 16384 + sw, Al + (size_t)(bm + row) * K + k0 + c * 8);
                }
            }
#pragma unroll
            for (int i = 0; i < 4; i++) {
                int idx = i * 256 + tid;
                int row = idx >> 3, c = idx & 7;
                cpa16(base + BO + row * 128 + ((c ^ (row & 7)) << 4),
                      Bh + (size_t)(bn + row) * K + k0 + c * 8);
            }
            asm volatile("cp.async.commit_group;");
        };

        issue(0);
        if (NK > 1) issue(1);

        for (int kt = 0; kt < NK; kt++) {
            if (kt == NK - 1) asm volatile("cp.async.wait_group 0;");
            else              asm volatile("cp.async.wait_group 1;");
            __syncthreads();
            uint32_t base = sb + (kt & 1) * STG;
            if (reduced) gemm_tiles<1, true,  AP>(base, arow, asel, brow, bsel, rx, wm, wn, acc);
            else         gemm_tiles<4, false, AP>(base, arow, asel, brow, bsel, rx, wm, wn, acc);
            __syncthreads();
            if (kt + 2 < NK) issue(kt + 2);
        }

        if (reduced) {
#pragma unroll
            for (int mt = 1; mt < 4; mt++)
#pragma unroll
                for (int nt = 0; nt < 4; nt++)
#pragma unroll
                    for (int r = 0; r < 4; r++) acc[mt][nt][r] = acc[0][nt][r];
        }
    }

    // epilogue
    int g = lane >> 2, tig = lane & 3;
    int seg = (MODE == 3) ? (bn >> 9) : 0;
#pragma unroll
    for (int mt = 0; mt < 4; mt++) {
#pragma unroll
        for (int nt = 0; nt < 4; nt++) {
            int colg = bn + wn * 32 + nt * 8 + tig * 2;
            float2 bv = *(const float2*)&bias[colg];
            int r0 = bm + wm * 64 + mt * 16 + g;
            float x0 = acc[mt][nt][0] + bv.x, x1 = acc[mt][nt][1] + bv.y;
            float x2 = acc[mt][nt][2] + bv.x, x3 = acc[mt][nt][3] + bv.y;
            if (MODE == 0) {
                float2 o0 = {x0, x1}, o1 = {x2, x3};
                *(float2*)&C[(size_t)r0 * OD + colg] = o0;
                *(float2*)&C[(size_t)(r0 + 8) * OD + colg] = o1;
            } else if (MODE == 1) {
                x0 = fmaxf(x0, 0.f); x1 = fmaxf(x1, 0.f);
                x2 = fmaxf(x2, 0.f); x3 = fmaxf(x3, 0.f);
                __half2 hh0 = {__float2half(x0), __float2half(x1)};
                __half2 hh1 = {__float2half(x2), __float2half(x3)};
                *(__half2*)&Ch[(size_t)r0 * OD + colg] = hh0;
                *(__half2*)&Ch[(size_t)(r0 + 8) * OD + colg] = hh1;
            } else {  // MODE 3
                int col = colg & 511;
                if (seg == 0) {
                    __half h0, l0, h1, l1, h2, l2, h3, l3;
                    split1(x0, h0, l0); split1(x1, h1, l1);
                    split1(x2, h2, l2); split1(x3, h3, l3);
                    __half2 hh0 = {h0, h1}, ll0 = {l0, l1};
                    __half2 hh1 = {h2, h3}, ll1 = {l2, l3};
                    *(__half2*)&Ch[(size_t)r0 * OD + col] = hh0;
                    *(__half2*)&Cl[(size_t)r0 * OD + col] = ll0;
                    *(__half2*)&Ch[(size_t)(r0 + 8) * OD + col] = hh1;
                    *(__half2*)&Cl[(size_t)(r0 + 8) * OD + col] = ll1;
                } else {
                    __half* oh = (seg == 1) ? Dh : Eh;
                    __half2 hh0 = {__float2half(x0), __float2half(x1)};
                    __half2 hh1 = {__float2half(x2), __float2half(x3)};
                    *(__half2*)&oh[(size_t)r0 * OD + col] = hh0;
                    *(__half2*)&oh[(size_t)(r0 + 8) * OD + col] = hh1;
                }
            }
        }
    }
}

// ---------------- attention diag via HMMA (fp16 2-pass, warp-pair K-split) -------
// 256 threads = 8 warps: warp w -> q-rows (w&3)*16..+15, parity p=w>>2 processes
// tiles t = 2*pt + p. smem: Q hi [0,8K), Q lo [8K,16K), K bufs 4x8K at 16K..48K.
// Combine buffers + sdiag alias the (dead after pt=0) Q region.
#define SMEM_ATTN 49152
__global__ __launch_bounds__(256, 1)
void attn_diag_hmma(const __half* __restrict__ qh, const __half* __restrict__ ql,
                    const __half* __restrict__ kh,
                    __half* vh,
                    const int* __restrict__ lengths)
{
    extern __shared__ char sm[];
    uint32_t sb = smem_u32(sm);
    int bx = (int)gridDim.x - 1 - (int)blockIdx.x;
    int h = blockIdx.y, b = blockIdx.z;
    int tid = threadIdx.x, lane = tid & 31, w = tid >> 5;
    int qg = w & 3, p = w >> 2;
    int i0 = bx * 64;
    int len = lengths[b];
    const size_t vbase = ((size_t)(b * SS + i0)) * DD + h * DK;

    if (i0 >= len) {
        uint4 z = make_uint4(0, 0, 0, 0);
#pragma unroll
        for (int it = 0; it < 2; it++) {
            int idx = it * 256 + tid;
            int row = idx >> 3, c8 = (idx & 7) * 8;
            *(uint4*)&vh[vbase + (size_t)row * DD + c8] = z;
        }
        return;
    }

    auto issueK = [&](int t) {
        if (t > bx) return;
        uint32_t kb = sb + 16384 + (t & 3) * 8192;
        size_t g = ((size_t)(b * SS + t * 64)) * DD + h * DK;
#pragma unroll
        for (int i = 0; i < 2; i++) {
            int idx = i * 256 + tid;
            int row = idx >> 3, c = idx & 7;
            cpa16(kb + row * 128 + ((c ^ (row & 7)) << 4), kh + g + (size_t)row * DD + c * 8);
        }
    };

    int npairs = (bx >> 1) + 1;

    // group 0: Q planes + pair 0
    const size_t qgb = vbase;
#pragma unroll
    for (int i = 0; i < 2; i++) {
        int idx = i * 256 + tid;
        int row = idx >> 3, c = idx & 7;
        uint32_t sw = row * 128 + ((c ^ (row & 7)) << 4);
        cpa16(sb + sw, qh + qgb + (size_t)row * DD + c * 8);
        cpa16(sb + 8192 + sw, ql + qgb + (size_t)row * DD + c * 8);
    }
    issueK(0); issueK(1);
    asm volatile("cp.async.commit_group;");
    if (npairs > 1) {
        issueK(2); issueK(3);
        asm volatile("cp.async.commit_group;");
    }

    int arow = (lane & 7) + ((lane >> 3) & 1) * 8;
    int asel = lane >> 4;
    int brow = (lane & 7) + (lane >> 4) * 8;
    int bsel = (lane >> 3) & 1;
    int g_ = lane >> 2, tig = lane & 3;

    uint32_t Qh[16], Ql[16];
    float m[2] = {-1e30f, -1e30f}, l[2] = {0.f, 0.f}, sd[2] = {-1e30f, -1e30f};

    for (int pt = 0; pt < npairs; pt++) {
        if (pt < npairs - 1) asm volatile("cp.async.wait_group 1;");
        else                 asm volatile("cp.async.wait_group 0;");
        __syncthreads();
        if (pt == 0) {
            int r = qg * 16 + arow;
#pragma unroll
            for (int kc = 0; kc < 4; kc++) {
                ldsm4(&Qh[kc * 4], sb + r * 128 + (((2 * kc + asel) ^ (r & 7)) << 4));
                ldsm4(&Ql[kc * 4], sb + 8192 + r * 128 + (((2 * kc + asel) ^ (r & 7)) << 4));
            }
        }
        int t = 2 * pt + p;
        if (t <= bx) {
            uint32_t kb = sb + 16384 + (t & 3) * 8192;
            float acc[8][4];
#pragma unroll
            for (int nt = 0; nt < 8; nt++)
#pragma unroll
                for (int r = 0; r < 4; r++) acc[nt][r] = 0.f;

#pragma unroll
            for (int kc = 0; kc < 4; kc++) {
                uint32_t Bh[16];
#pragma unroll
                for (int nt2 = 0; nt2 < 4; nt2++) {
                    int rr = nt2 * 16 + brow;
                    ldsm4(&Bh[nt2 * 4], kb + rr * 128 + (((2 * kc + bsel) ^ (rr & 7)) << 4));
                }
#pragma unroll
                for (int nt = 0; nt < 8; nt++)
                    mma_fp16(acc[nt], &Qh[kc * 4], &Bh[(nt >> 1) * 4 + (nt & 1) * 2]);
#pragma unroll
                for (int nt = 0; nt < 8; nt++)
                    mma_fp16(acc[nt], &Ql[kc * 4], &Bh[(nt >> 1) * 4 + (nt & 1) * 2]);
            }

            bool dtile = (t == bx);
#pragma unroll
            for (int r = 0; r < 2; r++) {
                int il = qg * 16 + g_ + r * 8;
                float tm = -1e30f;
                float vals[16];
#pragma unroll
                for (int nt = 0; nt < 8; nt++)
#pragma unroll
                    for (int c = 0; c < 2; c++) {
                        float v = acc[nt][r * 2 + c];
                        if (dtile) {
                            int jl = nt * 8 + tig * 2 + c;
                            if (jl == il) sd[r] = v;
                            if (jl > il) v = -1e30f;
                        }
                        vals[nt * 2 + c] = v;
                        tm = fmaxf(tm, v);
                    }
                float mn = fmaxf(m[r], tm);
                float sc = exp2f((m[r] - mn) * L2E);
                float ls = 0.f;
#pragma unroll
                for (int i = 0; i < 16; i++) ls += exp2f((vals[i] - mn) * L2E);
                l[r] = l[r] * sc + ls;
                m[r] = mn;
            }
        }
        __syncthreads();
        if (pt + 2 < npairs) {
            issueK(2 * pt + 4); issueK(2 * pt + 5);
            asm volatile("cp.async.commit_group;");
        }
    }

    // cross-lane combine within the 4 lanes sharing each row
    float* cmb = (float*)sm;          // m partials [2][64]
    float* clb = cmb + 128;           // l partials
    float* csb = clb + 128;           // sd partials
    float* sdiag = csb + 128;         // final diag [64]
#pragma unroll
    for (int r = 0; r < 2; r++) {
        float mm = m[r], ll = l[r], ss = sd[r];
#pragma unroll
        for (int o = 1; o <= 2; o <<= 1) {
            float mo = __shfl_xor_sync(0xffffffffu, mm, o);
            float lo = __shfl_xor_sync(0xffffffffu, ll, o);
            float so = __shfl_xor_sync(0xffffffffu, ss, o);
            float mn = fmaxf(mm, mo);
            ll = ll * exp2f((mm - mn) * L2E) + lo * exp2f((mo - mn) * L2E);
            mm = mn;
            ss = fmaxf(ss, so);
        }
        if (tig == 0) {
            int rl = qg * 16 + g_ + r * 8;
            cmb[p * 64 + rl] = mm;
            clb[p * 64 + rl] = ll;
            csb[p * 64 + rl] = ss;
        }
    }
    __syncthreads();

    // merge parities (64 threads) -> diag
    if (tid < 64) {
        float m0 = cmb[tid], m1 = cmb[64 + tid];
        float l0 = clb[tid], l1 = clb[64 + tid];
        float s0 = csb[tid], s1 = csb[64 + tid];
        float mn = fmaxf(m0, m1);
        float ll = l0 * exp2f((m0 - mn) * L2E) + l1 * exp2f((m1 - mn) * L2E);
        float ss = fmaxf(s0, s1);
        float dv = (i0 + tid < len) ? exp2f((ss - mn) * L2E) / ll : 0.f;
        sdiag[tid] = dv;
    }
    __syncthreads();

    // fused epilogue: v *= diag, single plane, in place
#pragma unroll
    for (int it = 0; it < 2; it++) {
        int idx = it * 256 + tid;
        int row = idx >> 3, c8 = (idx & 7) * 8;
        size_t off = vbase + (size_t)row * DD + c8;
        uint4 hv = *(uint4*)&vh[off];
        float dv = sdiag[row];
        __half2* hp = (__half2*)&hv;
        uint4 ho;
        __half2* hop = (__half2*)&ho;
#pragma unroll
        for (int j = 0; j < 4; j++) {
            hop[j] = {__float2half(dv * __half2float(hp[j].x)),
                      __float2half(dv * __half2float(hp[j].y))};
        }
        *(uint4*)&vh[off] = ho;
    }
}

// ---------------- LayerNorm(a + r) -----------------------------------------------
template<bool SPLIT, bool OUTF>
__global__ __launch_bounds__(256)
void ln_kernel(const __half* __restrict__ ah, const __half* __restrict__ al,
               const float* __restrict__ r,
               const float* __restrict__ gamma, const float* __restrict__ beta,
               float* __restrict__ out,
               __half* __restrict__ oh, __half* __restrict__ ol)
{
    int row = blockIdx.x;
    int tid = threadIdx.x;
    size_t base = (size_t)row * DD;

    float a0 = __half2float(ah[base + tid]) + __half2float(al[base + tid]);
    float a1 = __half2float(ah[base + tid + 256]) + __half2float(al[base + tid + 256]);
    float v0 = a0 + r[base + tid];
    float v1 = a1 + r[base + tid + 256];

    __shared__ float sred[8];
    __shared__ float smean, srstd;

    float s = v0 + v1;
#pragma unroll
    for (int o = 16; o > 0; o >>= 1) s += __shfl_xor_sync(0xffffffffu, s, o);
    if ((tid & 31) == 0) sred[tid >> 5] = s;
    __syncthreads();
    if (tid == 0) {
        float t = 0.f;
#pragma unroll
        for (int i = 0; i < 8; i++) t += sred[i];
        smean = t * (1.0f / DD);
    }
    __syncthreads();
    float mean = smean;
    float d0 = v0 - mean, d1 = v1 - mean;
    float vs = d0 * d0 + d1 * d1;
#pragma unroll
    for (int o = 16; o > 0; o >>= 1) vs += __shfl_xor_sync(0xffffffffu, vs, o);
    if ((tid & 31) == 0) sred[tid >> 5] = vs;
    __syncthreads();
    if (tid == 0) {
        float t = 0.f;
#pragma unroll
        for (int i = 0; i < 8; i++) t += sred[i];
        srstd = rsqrtf(t * (1.0f / DD) + 1e-3f);
    }
    __syncthreads();
    float rstd = srstd;
    float o0 = gamma[tid]       * (d0 * rstd) + beta[tid];
    float o1 = gamma[tid + 256] * (d1 * rstd) + beta[tid + 256];
    if (OUTF) {
        out[base + tid]       = o0;
        out[base + tid + 256] = o1;
    }
    if (SPLIT) {
        __half h0, l0, h1, l1;
        split1(o0, h0, l0);
        split1(o1, h1, l1);
        oh[base + tid]       = h0;
        ol[base + tid]       = l0;
        oh[base + tid + 256] = h1;
        ol[base + tid + 256] = l1;
    }
}

// ---------------- launch --------------------------------------------------------
extern "C" void kernel_launch(void* const* d_in, const int* in_sizes, int n_in,
                              void* d_out, int out_size)
{
    const float* x       = (const float*)d_in[0];
    const int*   lengths = (const int*)d_in[1];
    const float* Wq = (const float*)d_in[2];
    const float* bq = (const float*)d_in[3];
    const float* Wk = (const float*)d_in[4];
    const float* bk = (const float*)d_in[5];
    const float* Wv = (const float*)d_in[6];
    const float* bv = (const float*)d_in[7];
    const float* Wo = (const float*)d_in[8];
    const float* bo = (const float*)d_in[9];
    const float* W1 = (const float*)d_in[10];
    const float* b1 = (const float*)d_in[11];
    const float* W2 = (const float*)d_in[12];
    const float* b2 = (const float*)d_in[13];
    const float* gamma1 = (const float*)d_in[14];
    const float* beta1  = (const float*)d_in[15];
    const float* gamma2 = (const float*)d_in[16];
    const float* beta2  = (const float*)d_in[17];

    float *ao, *f2, *bqkv;
    __half *xh, *xl, *qh, *ql, *kh, *wvh, *y1h, *y1l, *h1h;
    __half *wqkvt, *wot, *w1t, *w2t;
    cudaGetSymbolAddress((void**)&ao,   g_ao);
    cudaGetSymbolAddress((void**)&f2,   g_f2);
    cudaGetSymbolAddress((void**)&bqkv, g_bqkv);
    cudaGetSymbolAddress((void**)&xh,   g_xh);
    cudaGetSymbolAddress((void**)&xl,   g_xl);
    cudaGetSymbolAddress((void**)&qh,   g_qh);
    cudaGetSymbolAddress((void**)&ql,   g_ql);
    cudaGetSymbolAddress((void**)&kh,   g_kh);
    cudaGetSymbolAddress((void**)&wvh,  g_wvh);
    cudaGetSymbolAddress((void**)&y1h,  g_y1h);
    cudaGetSymbolAddress((void**)&y1l,  g_y1l);
    cudaGetSymbolAddress((void**)&h1h,  g_h1h);
    cudaGetSymbolAddress((void**)&wqkvt, g_wqkvt);
    cudaGetSymbolAddress((void**)&wot,  g_wot);
    cudaGetSymbolAddress((void**)&w1t,  g_w1t);
    cudaGetSymbolAddress((void**)&w2t,  g_w2t);

    const int SM_AP2 = 2 * 3 * 16384;   // 96 KB
    const int SM_AP1 = 2 * 2 * 16384;   // 64 KB
    cudaFuncSetAttribute((const void*)hgemm<3,2>, cudaFuncAttributeMaxDynamicSharedMemorySize, SM_AP2);
    cudaFuncSetAttribute((const void*)hgemm<0,1>, cudaFuncAttributeMaxDynamicSharedMemorySize, SM_AP1);
    cudaFuncSetAttribute((const void*)hgemm<1,1>, cudaFuncAttributeMaxDynamicSharedMemorySize, SM_AP1);
    cudaFuncSetAttribute((const void*)attn_diag_hmma, cudaFuncAttributeMaxDynamicSharedMemorySize, SMEM_ATTN);

    // mask+split + bias-concat tail (2 extra blocks)
    mask_split_kernel<<<(N4 + 384 + 255) / 256, 256>>>(x, lengths, xh, xl, bq, bk, bv, bqkv);

    // all 6 weight transposes in one launch
    transpose_all_kernel<<<dim3(FFD/32, DD/32, 6), dim3(32, 8)>>>(
        Wq, Wk, Wv, Wo, W1, W2, wqkvt, wot, w1t, w2t);

    dim3 g512(DD / 128, MM / 128);       // (4, 32)
    dim3 gQKV(3 * DD / 128, MM / 128);   // (12, 32)
    dim3 gFF (FFD / 128, MM / 128);      // (16, 32)

    // fused QKV (2-pass): q hi/lo; k,v single plane; padded tiles -> bias
    hgemm<3,2><<<gQKV, 256, SM_AP2>>>(xh, xl, wqkvt, bqkv,
                                      nullptr, qh, ql, kh, wvh,
                                      lengths, 1, MM, 3 * DD, DD, DD);

    // attention diag (2-pass, warp-pair K split) + in-place v *= diag
    attn_diag_hmma<<<dim3(SS / 64, HH, BB), 256, SMEM_ATTN>>>(qh, ql, kh, wvh, lengths);

    // Wo (1-pass)
    hgemm<0,1><<<g512, 256, SM_AP1>>>(wvh, nullptr, wot, bo,
                                      ao, nullptr, nullptr, nullptr, nullptr,
                                      lengths, 1, MM, DD, DD, DD);

    // ln1: LN(x + ao) -> fp16 hi/lo planes
    ln_kernel<true, false><<<MM, 256>>>(xh, xl, ao, gamma1, beta1, nullptr, y1h, y1l);

    // W1 (1-pass, relu, single-plane out)
    hgemm<1,1><<<gFF, 256, SM_AP1>>>(y1h, nullptr, w1t, b1,
                                     nullptr, h1h, nullptr, nullptr, nullptr,
                                     lengths, 2, MM, FFD, DD, FFD);
    // W2 (1-pass)
    hgemm<0,1><<<g512, 256, SM_AP1>>>(h1h, nullptr, w2t, b2,
                                      f2, nullptr, nullptr, nullptr, nullptr,
                                      lengths, 2, MM, DD, FFD, DD);

    // ln2: LN(y1 + f2) -> fp32 output
    ln_kernel<false, true><<<MM, 256>>>(y1h, y1l, f2, gamma2, beta2,
                                        (float*)d_out, nullptr, nullptr);
}